// round 1
// baseline (speedup 1.0000x reference)
#include <cuda_runtime.h>
#include <math.h>

// Problem constants
constexpr int kB  = 2;
constexpr int kL  = 2048;
constexpr int kD  = 2048;
constexpr int kH  = 16;
constexpr int kHD = 128;
constexpr int kFF = 8192;
constexpr int kM  = kB * kL;  // 4096 rows

// ---------------------------------------------------------------------------
// Scratch buffers (device globals — no allocation allowed)
// ---------------------------------------------------------------------------
__device__ float g_h[(size_t)kM * kD];        // rmsnorm output (reused for h2)
__device__ float g_qkv[(size_t)kM * 3 * kD];  // qkv projection
__device__ float g_attn[(size_t)kM * kD];     // attention output
__device__ float g_x2[(size_t)kM * kD];       // residual after attention
__device__ float g_gate[(size_t)kM * kFF];    // silu(gate)
__device__ float g_act[(size_t)kM * kFF];     // silu(gate) * up

// ---------------------------------------------------------------------------
// RMSNorm: one block per row, 256 threads, D=2048
// ---------------------------------------------------------------------------
__global__ __launch_bounds__(256) void rmsnorm_kernel(const float* __restrict__ x,
                                                      const float* __restrict__ w,
                                                      float* __restrict__ out) {
    int row = blockIdx.x;
    int t = threadIdx.x;
    const float4* xr = (const float4*)(x + (size_t)row * kD);
    float4 v0 = xr[t];
    float4 v1 = xr[t + 256];
    float s = v0.x * v0.x + v0.y * v0.y + v0.z * v0.z + v0.w * v0.w
            + v1.x * v1.x + v1.y * v1.y + v1.z * v1.z + v1.w * v1.w;
#pragma unroll
    for (int o = 16; o > 0; o >>= 1) s += __shfl_xor_sync(0xffffffffu, s, o);

    __shared__ float red[8];
    __shared__ float rtot;
    int wid = t >> 5, lane = t & 31;
    if (lane == 0) red[wid] = s;
    __syncthreads();
    if (t == 0) {
        float tot = 0.f;
#pragma unroll
        for (int i = 0; i < 8; i++) tot += red[i];
        rtot = rsqrtf(tot * (1.0f / kD) + 1e-6f);
    }
    __syncthreads();
    float r = rtot;

    const float4* wv = (const float4*)w;
    float4 w0 = wv[t], w1 = wv[t + 256];
    float4 r0, r1;
    r0.x = v0.x * r * w0.x; r0.y = v0.y * r * w0.y;
    r0.z = v0.z * r * w0.z; r0.w = v0.w * r * w0.w;
    r1.x = v1.x * r * w1.x; r1.y = v1.y * r * w1.y;
    r1.z = v1.z * r * w1.z; r1.w = v1.w * r * w1.w;
    float4* ov = (float4*)(out + (size_t)row * kD);
    ov[t] = r0;
    ov[t + 256] = r1;
}

// ---------------------------------------------------------------------------
// NT GEMM: C[M,N] = A[M,K] @ B[N,K]^T   (both operands K-contiguous)
// 128x128 tile, BK=16, 256 threads, 8x8 register micro-tile.
// EPI: 0 = none, 1 = +Aux (residual), 2 = silu, 3 = *Aux (elementwise mul)
// All dims assumed divisible by 128 (they are: M=4096, N in {2048,6144,8192},
// K in {2048,8192}).
// ---------------------------------------------------------------------------
template <int EPI>
__global__ __launch_bounds__(256) void gemm_nt(const float* __restrict__ A,
                                               const float* __restrict__ Bm,
                                               float* __restrict__ C,
                                               const float* __restrict__ Aux,
                                               int Mdim, int Ndim, int Kdim) {
    __shared__ float As[16][128];
    __shared__ float Bs[16][128];
    int m0 = blockIdx.y * 128;
    int n0 = blockIdx.x * 128;
    int t = threadIdx.x;
    int ty = t >> 4, tx = t & 15;

    float acc[8][8];
#pragma unroll
    for (int i = 0; i < 8; i++)
#pragma unroll
        for (int j = 0; j < 8; j++) acc[i][j] = 0.f;

    for (int k0 = 0; k0 < Kdim; k0 += 16) {
#pragma unroll
        for (int i = 0; i < 2; i++) {
            int f = t * 2 + i;
            int row = f >> 2;
            int c4 = (f & 3) * 4;
            float4 va = *(const float4*)(A + (size_t)(m0 + row) * Kdim + k0 + c4);
            As[c4 + 0][row] = va.x;
            As[c4 + 1][row] = va.y;
            As[c4 + 2][row] = va.z;
            As[c4 + 3][row] = va.w;
            float4 vb = *(const float4*)(Bm + (size_t)(n0 + row) * Kdim + k0 + c4);
            Bs[c4 + 0][row] = vb.x;
            Bs[c4 + 1][row] = vb.y;
            Bs[c4 + 2][row] = vb.z;
            Bs[c4 + 3][row] = vb.w;
        }
        __syncthreads();
#pragma unroll
        for (int k = 0; k < 16; k++) {
            float a[8], bb[8];
#pragma unroll
            for (int i = 0; i < 8; i++) a[i] = As[k][ty * 8 + i];
#pragma unroll
            for (int j = 0; j < 8; j++) bb[j] = Bs[k][tx * 8 + j];
#pragma unroll
            for (int i = 0; i < 8; i++)
#pragma unroll
                for (int j = 0; j < 8; j++) acc[i][j] += a[i] * bb[j];
        }
        __syncthreads();
    }

#pragma unroll
    for (int i = 0; i < 8; i++) {
        size_t m = (size_t)(m0 + ty * 8 + i);
        float* cp = C + m * Ndim + n0 + tx * 8;
        const float* ap = (EPI == 1 || EPI == 3) ? (Aux + m * Ndim + n0 + tx * 8) : nullptr;
#pragma unroll
        for (int j = 0; j < 8; j++) {
            float v = acc[i][j];
            if (EPI == 1) v += ap[j];
            if (EPI == 2) v = v / (1.f + expf(-v));
            if (EPI == 3) v *= ap[j];
            cp[j] = v;
        }
    }
}

// ---------------------------------------------------------------------------
// Flash attention (fp32, causal). One block per (q-tile of 64, head, batch).
// 256 threads. Online softmax. HD=128, BKV=64.
// qkv layout per row (l): [3][H][HD]  -> q at h*128, k at D + h*128, v at 2D + h*128.
// Output written as [b, l, h*HD] = [M, D].
// ---------------------------------------------------------------------------
constexpr int QS_STRIDE = 129;
constexpr int PS_STRIDE = 65;
constexpr int ATTN_SMEM_FLOATS = 64 * QS_STRIDE * 2   // Qs, Ks
                               + 64 * 128              // Vs
                               + 64 * PS_STRIDE        // Ps
                               + 3 * 64;               // m, l, corr
constexpr int ATTN_SMEM = ATTN_SMEM_FLOATS * 4;

__global__ __launch_bounds__(256) void attn_kernel(const float* __restrict__ qkv,
                                                   float* __restrict__ o_out) {
    extern __shared__ float sm[];
    float* Qs = sm;
    float* Ks = Qs + 64 * QS_STRIDE;
    float* Vs = Ks + 64 * QS_STRIDE;
    float* Ps = Vs + 64 * 128;
    float* mrow = Ps + 64 * PS_STRIDE;
    float* lrow = mrow + 64;
    float* crow = lrow + 64;

    int q0 = blockIdx.x * 64;
    int h = blockIdx.y;
    int b = blockIdx.z;
    int t = threadIdx.x;
    const float scale = 0.08838834764831845f;  // 1/sqrt(128)

    const float* qbase = qkv + ((size_t)b * kL) * (3 * kD) + h * kHD;

    // Load + pre-scale Q tile [64][128]
    for (int idx = t; idx < 64 * 32; idx += 256) {
        int r = idx >> 5, c = (idx & 31) * 4;
        float4 v = *(const float4*)(qbase + (size_t)(q0 + r) * (3 * kD) + c);
        float* dst = Qs + r * QS_STRIDE + c;
        dst[0] = v.x * scale; dst[1] = v.y * scale;
        dst[2] = v.z * scale; dst[3] = v.w * scale;
    }
    if (t < 64) { mrow[t] = -1e30f; lrow[t] = 0.f; }

    float o[4][8];
#pragma unroll
    for (int i = 0; i < 4; i++)
#pragma unroll
        for (int j = 0; j < 8; j++) o[i][j] = 0.f;

    int tq = t >> 4, tk = t & 15;
    int nkb = blockIdx.x + 1;  // causal: only KV tiles up to and including diagonal

    for (int kb = 0; kb < nkb; kb++) {
        int k0 = kb * 64;
        __syncthreads();  // protects Ks/Vs/Ps from the previous iteration's readers
        for (int idx = t; idx < 64 * 32; idx += 256) {
            int r = idx >> 5, c = (idx & 31) * 4;
            const float* src = qbase + (size_t)(k0 + r) * (3 * kD) + c;
            float4 kv = *(const float4*)(src + kD);
            float* kd = Ks + r * QS_STRIDE + c;
            kd[0] = kv.x; kd[1] = kv.y; kd[2] = kv.z; kd[3] = kv.w;
            float4 vv = *(const float4*)(src + 2 * kD);
            *(float4*)(Vs + r * 128 + c) = vv;
        }
        __syncthreads();

        // Scores: each thread computes a 4x4 block of S[64][64]
        float s[4][4];
#pragma unroll
        for (int i = 0; i < 4; i++)
#pragma unroll
            for (int j = 0; j < 4; j++) s[i][j] = 0.f;

#pragma unroll 4
        for (int d = 0; d < kHD; d++) {
            float qa[4], kv[4];
#pragma unroll
            for (int i = 0; i < 4; i++) qa[i] = Qs[(tq * 4 + i) * QS_STRIDE + d];
#pragma unroll
            for (int j = 0; j < 4; j++) kv[j] = Ks[(tk * 4 + j) * QS_STRIDE + d];
#pragma unroll
            for (int i = 0; i < 4; i++)
#pragma unroll
                for (int j = 0; j < 4; j++) s[i][j] += qa[i] * kv[j];
        }

        bool diag = (kb == nkb - 1);
#pragma unroll
        for (int i = 0; i < 4; i++) {
            int qi = tq * 4 + i;
#pragma unroll
            for (int j = 0; j < 4; j++) {
                int kj = tk * 4 + j;
                float v = s[i][j];
                if (diag && kj > qi) v = -1e30f;
                Ps[qi * PS_STRIDE + kj] = v;
            }
        }
        __syncthreads();

        // Online softmax: thread q (< 64) owns row q
        if (t < 64) {
            float mo = mrow[t];
            float mx = mo;
            float* pr = Ps + t * PS_STRIDE;
            for (int j = 0; j < 64; j++) mx = fmaxf(mx, pr[j]);
            float corr = expf(mo - mx);
            float sum = 0.f;
            for (int j = 0; j < 64; j++) {
                float p = expf(pr[j] - mx);
                pr[j] = p;
                sum += p;
            }
            lrow[t] = lrow[t] * corr + sum;
            mrow[t] = mx;
            crow[t] = corr;
        }
        __syncthreads();

        // P @ V: thread owns queries tq*4..tq*4+3, dims tk*8..tk*8+7
        float c4v[4];
#pragma unroll
        for (int i = 0; i < 4; i++) c4v[i] = crow[tq * 4 + i];
#pragma unroll
        for (int i = 0; i < 4; i++)
#pragma unroll
            for (int dj = 0; dj < 8; dj++) o[i][dj] *= c4v[i];

        for (int j = 0; j < 64; j++) {
            float p[4];
#pragma unroll
            for (int i = 0; i < 4; i++) p[i] = Ps[(tq * 4 + i) * PS_STRIDE + j];
            float v[8];
#pragma unroll
            for (int dj = 0; dj < 8; dj++) v[dj] = Vs[j * 128 + tk * 8 + dj];
#pragma unroll
            for (int i = 0; i < 4; i++)
#pragma unroll
                for (int dj = 0; dj < 8; dj++) o[i][dj] += p[i] * v[dj];
        }
    }

    __syncthreads();
#pragma unroll
    for (int i = 0; i < 4; i++) {
        int qi = tq * 4 + i;
        float inv = 1.f / lrow[qi];
        float* dst = o_out + ((size_t)b * kL + q0 + qi) * kD + h * kHD + tk * 8;
#pragma unroll
        for (int dj = 0; dj < 8; dj++) dst[dj] = o[i][dj] * inv;
    }
}

// ---------------------------------------------------------------------------
// Launch: rmsnorm -> qkv GEMM -> attention -> out GEMM(+res) -> rmsnorm ->
//         gate GEMM(silu) -> up GEMM(*gate) -> down GEMM(+res) -> d_out
// Inputs (metadata order): x, mask, norm1_w, qkv_w, out_w, norm2_w, gate_w,
//                          up_w, down_w.  mask is exactly causal -> unused.
// ---------------------------------------------------------------------------
extern "C" void kernel_launch(void* const* d_in, const int* in_sizes, int n_in,
                              void* d_out, int out_size) {
    (void)in_sizes; (void)n_in; (void)out_size;
    const float* x       = (const float*)d_in[0];
    const float* norm1_w = (const float*)d_in[2];
    const float* qkv_w   = (const float*)d_in[3];
    const float* out_w   = (const float*)d_in[4];
    const float* norm2_w = (const float*)d_in[5];
    const float* gate_w  = (const float*)d_in[6];
    const float* up_w    = (const float*)d_in[7];
    const float* down_w  = (const float*)d_in[8];
    float* out = (float*)d_out;

    float *h, *qkvb, *attnb, *x2, *gate, *act;
    cudaGetSymbolAddress((void**)&h, g_h);
    cudaGetSymbolAddress((void**)&qkvb, g_qkv);
    cudaGetSymbolAddress((void**)&attnb, g_attn);
    cudaGetSymbolAddress((void**)&x2, g_x2);
    cudaGetSymbolAddress((void**)&gate, g_gate);
    cudaGetSymbolAddress((void**)&act, g_act);

    cudaFuncSetAttribute((const void*)attn_kernel,
                         cudaFuncAttributeMaxDynamicSharedMemorySize, ATTN_SMEM);

    // 1) h = rmsnorm(x, norm1_w)
    rmsnorm_kernel<<<kM, 256>>>(x, norm1_w, h);
    // 2) qkv = h @ qkv_w^T
    gemm_nt<0><<<dim3(3 * kD / 128, kM / 128), 256>>>(h, qkv_w, qkvb, nullptr, kM, 3 * kD, kD);
    // 3) attention
    attn_kernel<<<dim3(kL / 64, kH, kB), 256, ATTN_SMEM>>>(qkvb, attnb);
    // 4) x2 = attn @ out_w^T + x
    gemm_nt<1><<<dim3(kD / 128, kM / 128), 256>>>(attnb, out_w, x2, x, kM, kD, kD);
    // 5) h = rmsnorm(x2, norm2_w)
    rmsnorm_kernel<<<kM, 256>>>(x2, norm2_w, h);
    // 6) gate = silu(h @ gate_w^T)
    gemm_nt<2><<<dim3(kFF / 128, kM / 128), 256>>>(h, gate_w, gate, nullptr, kM, kFF, kD);
    // 7) act = (h @ up_w^T) * gate
    gemm_nt<3><<<dim3(kFF / 128, kM / 128), 256>>>(h, up_w, act, gate, kM, kFF, kD);
    // 8) out = act @ down_w^T + x2
    gemm_nt<1><<<dim3(kD / 128, kM / 128), 256>>>(act, down_w, out, x2, kM, kD, kFF);
}

// round 2
// speedup vs baseline: 2.6856x; 2.6856x over previous
#include <cuda_runtime.h>
#include <math.h>
#include <stdint.h>

// Problem constants
constexpr int kB  = 2;
constexpr int kL  = 2048;
constexpr int kD  = 2048;
constexpr int kH  = 16;
constexpr int kHD = 128;
constexpr int kFF = 8192;
constexpr int kM  = kB * kL;  // 4096 rows

// ---------------------------------------------------------------------------
// Scratch buffers (device globals — no allocation allowed)
// ---------------------------------------------------------------------------
__device__ float g_h[(size_t)kM * kD];
__device__ float g_qkv[(size_t)kM * 3 * kD];
__device__ float g_attn[(size_t)kM * kD];
__device__ float g_x2[(size_t)kM * kD];
__device__ float g_gate[(size_t)kM * kFF];
__device__ float g_act[(size_t)kM * kFF];

// ---------------------------------------------------------------------------
// PTX helpers
// ---------------------------------------------------------------------------
__device__ __forceinline__ void cp_async16(float* smem, const float* gmem) {
    uint32_t s = (uint32_t)__cvta_generic_to_shared(smem);
    asm volatile("cp.async.cg.shared.global [%0], [%1], 16;\n" :: "r"(s), "l"(gmem));
}
__device__ __forceinline__ void cp_commit() {
    asm volatile("cp.async.commit_group;\n");
}
__device__ __forceinline__ void cp_wait_all() {
    asm volatile("cp.async.wait_group 0;\n");
}
__device__ __forceinline__ uint32_t f2tf32(float x) {
    uint32_t r;
    asm("cvt.rna.tf32.f32 %0, %1;" : "=r"(r) : "f"(x));
    return r;
}
__device__ __forceinline__ void mma_tf32(float* c, const uint32_t* a, const uint32_t* b) {
    asm volatile(
        "mma.sync.aligned.m16n8k8.row.col.f32.tf32.tf32.f32 "
        "{%0,%1,%2,%3}, {%4,%5,%6,%7}, {%8,%9}, {%0,%1,%2,%3};"
        : "+f"(c[0]), "+f"(c[1]), "+f"(c[2]), "+f"(c[3])
        : "r"(a[0]), "r"(a[1]), "r"(a[2]), "r"(a[3]), "r"(b[0]), "r"(b[1]));
}

// ---------------------------------------------------------------------------
// RMSNorm: one block per row, 256 threads, D=2048
// ---------------------------------------------------------------------------
__global__ __launch_bounds__(256) void rmsnorm_kernel(const float* __restrict__ x,
                                                      const float* __restrict__ w,
                                                      float* __restrict__ out) {
    int row = blockIdx.x;
    int t = threadIdx.x;
    const float4* xr = (const float4*)(x + (size_t)row * kD);
    float4 v0 = xr[t];
    float4 v1 = xr[t + 256];
    float s = v0.x * v0.x + v0.y * v0.y + v0.z * v0.z + v0.w * v0.w
            + v1.x * v1.x + v1.y * v1.y + v1.z * v1.z + v1.w * v1.w;
#pragma unroll
    for (int o = 16; o > 0; o >>= 1) s += __shfl_xor_sync(0xffffffffu, s, o);

    __shared__ float red[8];
    __shared__ float rtot;
    int wid = t >> 5, lane = t & 31;
    if (lane == 0) red[wid] = s;
    __syncthreads();
    if (t == 0) {
        float tot = 0.f;
#pragma unroll
        for (int i = 0; i < 8; i++) tot += red[i];
        rtot = rsqrtf(tot * (1.0f / kD) + 1e-6f);
    }
    __syncthreads();
    float r = rtot;

    const float4* wv = (const float4*)w;
    float4 w0 = wv[t], w1 = wv[t + 256];
    float4 r0, r1;
    r0.x = v0.x * r * w0.x; r0.y = v0.y * r * w0.y;
    r0.z = v0.z * r * w0.z; r0.w = v0.w * r * w0.w;
    r1.x = v1.x * r * w1.x; r1.y = v1.y * r * w1.y;
    r1.z = v1.z * r * w1.z; r1.w = v1.w * r * w1.w;
    float4* ov = (float4*)(out + (size_t)row * kD);
    ov[t] = r0;
    ov[t + 256] = r1;
}

// ---------------------------------------------------------------------------
// TF32 tensor-core NT GEMM: C[M,N] = A[M,K] @ B[N,K]^T
// 128x128 block tile, BK=32, 8 warps (64x32 each), double-buffered cp.async.
// SMEM rows padded to 36 floats. EPI: 0 none, 1 +Aux, 2 silu, 3 *Aux.
// Dims divisible by 128 (K by 32).
// ---------------------------------------------------------------------------
constexpr int GS_PAD = 36;                       // floats per smem row
constexpr int GS_TILE = 128 * GS_PAD;            // one buffer of one operand
constexpr int GEMM_SMEM = 4 * GS_TILE * 4;       // 2 operands x 2 buffers, bytes

__device__ __forceinline__ void cp_tile(float* smem, const float* g, int ldg,
                                        int k0, int t) {
#pragma unroll
    for (int i = 0; i < 4; i++) {
        int idx = t + 256 * i;
        int row = idx >> 3;
        int c4 = (idx & 7) * 4;
        cp_async16(smem + row * GS_PAD + c4, g + (size_t)row * ldg + k0 + c4);
    }
}

template <int EPI>
__global__ __launch_bounds__(256) void gemm_tf32(const float* __restrict__ A,
                                                 const float* __restrict__ Bm,
                                                 float* __restrict__ C,
                                                 const float* __restrict__ Aux,
                                                 int Ndim, int Kdim) {
    extern __shared__ float sm[];
    float* As = sm;                 // [2][128][36]
    float* Bs = sm + 2 * GS_TILE;   // [2][128][36]

    const int t = threadIdx.x;
    const int wid = t >> 5, lane = t & 31;
    const int m0 = blockIdx.y * 128;
    const int n0 = blockIdx.x * 128;
    const int wm = (wid >> 2) * 64;   // warp m offset within tile
    const int wn = (wid & 3) * 32;    // warp n offset within tile
    const int r = lane >> 2;          // 0..7
    const int c = lane & 3;           // 0..3

    const float* Ab = A + (size_t)m0 * Kdim;
    const float* Bb = Bm + (size_t)n0 * Kdim;

    float acc[4][4][4];
#pragma unroll
    for (int mi = 0; mi < 4; mi++)
#pragma unroll
        for (int ni = 0; ni < 4; ni++)
#pragma unroll
            for (int q = 0; q < 4; q++) acc[mi][ni][q] = 0.f;

    const int KT = Kdim / 32;

    // Prefetch first tiles
    cp_tile(As, Ab, Kdim, 0, t);
    cp_tile(Bs, Bb, Kdim, 0, t);
    cp_commit();

    for (int kt = 0; kt < KT; kt++) {
        int buf = kt & 1;
        cp_wait_all();
        __syncthreads();
        if (kt + 1 < KT) {
            int nb = (kt + 1) & 1;
            cp_tile(As + nb * GS_TILE, Ab, Kdim, (kt + 1) * 32, t);
            cp_tile(Bs + nb * GS_TILE, Bb, Kdim, (kt + 1) * 32, t);
            cp_commit();
        }
        const float* as = As + buf * GS_TILE;
        const float* bs = Bs + buf * GS_TILE;

#pragma unroll
        for (int ks = 0; ks < 4; ks++) {
            const int k = ks * 8;
            uint32_t af[4][4], bf[4][2];
#pragma unroll
            for (int mi = 0; mi < 4; mi++) {
                int base = (wm + mi * 16 + r) * GS_PAD + k + c;
                af[mi][0] = f2tf32(as[base]);
                af[mi][1] = f2tf32(as[base + 8 * GS_PAD]);
                af[mi][2] = f2tf32(as[base + 4]);
                af[mi][3] = f2tf32(as[base + 8 * GS_PAD + 4]);
            }
#pragma unroll
            for (int ni = 0; ni < 4; ni++) {
                int base = (wn + ni * 8 + r) * GS_PAD + k + c;
                bf[ni][0] = f2tf32(bs[base]);
                bf[ni][1] = f2tf32(bs[base + 4]);
            }
#pragma unroll
            for (int mi = 0; mi < 4; mi++)
#pragma unroll
                for (int ni = 0; ni < 4; ni++)
                    mma_tf32(acc[mi][ni], af[mi], bf[ni]);
        }
        __syncthreads();
    }

    // Epilogue: c0,c1 at (row, col..col+1), c2,c3 at (row+8, col..col+1)
#pragma unroll
    for (int mi = 0; mi < 4; mi++) {
#pragma unroll
        for (int ni = 0; ni < 4; ni++) {
            int row = m0 + wm + mi * 16 + (lane >> 2);
            int col = n0 + wn + ni * 8 + (lane & 3) * 2;
#pragma unroll
            for (int half = 0; half < 2; half++) {
                size_t off = (size_t)(row + half * 8) * Ndim + col;
                float v0 = acc[mi][ni][half * 2 + 0];
                float v1 = acc[mi][ni][half * 2 + 1];
                if (EPI == 1) { v0 += Aux[off]; v1 += Aux[off + 1]; }
                if (EPI == 2) { v0 = v0 / (1.f + expf(-v0)); v1 = v1 / (1.f + expf(-v1)); }
                if (EPI == 3) { v0 *= Aux[off]; v1 *= Aux[off + 1]; }
                *(float2*)(C + off) = make_float2(v0, v1);
            }
        }
    }
}

// ---------------------------------------------------------------------------
// Flash attention (fp32, causal) — unchanged from round 1.
// ---------------------------------------------------------------------------
constexpr int QS_STRIDE = 129;
constexpr int PS_STRIDE = 65;
constexpr int ATTN_SMEM_FLOATS = 64 * QS_STRIDE * 2
                               + 64 * 128
                               + 64 * PS_STRIDE
                               + 3 * 64;
constexpr int ATTN_SMEM = ATTN_SMEM_FLOATS * 4;

__global__ __launch_bounds__(256) void attn_kernel(const float* __restrict__ qkv,
                                                   float* __restrict__ o_out) {
    extern __shared__ float sm[];
    float* Qs = sm;
    float* Ks = Qs + 64 * QS_STRIDE;
    float* Vs = Ks + 64 * QS_STRIDE;
    float* Ps = Vs + 64 * 128;
    float* mrow = Ps + 64 * PS_STRIDE;
    float* lrow = mrow + 64;
    float* crow = lrow + 64;

    int q0 = blockIdx.x * 64;
    int h = blockIdx.y;
    int b = blockIdx.z;
    int t = threadIdx.x;
    const float scale = 0.08838834764831845f;

    const float* qbase = qkv + ((size_t)b * kL) * (3 * kD) + h * kHD;

    for (int idx = t; idx < 64 * 32; idx += 256) {
        int r = idx >> 5, c = (idx & 31) * 4;
        float4 v = *(const float4*)(qbase + (size_t)(q0 + r) * (3 * kD) + c);
        float* dst = Qs + r * QS_STRIDE + c;
        dst[0] = v.x * scale; dst[1] = v.y * scale;
        dst[2] = v.z * scale; dst[3] = v.w * scale;
    }
    if (t < 64) { mrow[t] = -1e30f; lrow[t] = 0.f; }

    float o[4][8];
#pragma unroll
    for (int i = 0; i < 4; i++)
#pragma unroll
        for (int j = 0; j < 8; j++) o[i][j] = 0.f;

    int tq = t >> 4, tk = t & 15;
    int nkb = blockIdx.x + 1;

    for (int kb = 0; kb < nkb; kb++) {
        int k0 = kb * 64;
        __syncthreads();
        for (int idx = t; idx < 64 * 32; idx += 256) {
            int r = idx >> 5, c = (idx & 31) * 4;
            const float* src = qbase + (size_t)(k0 + r) * (3 * kD) + c;
            float4 kv = *(const float4*)(src + kD);
            float* kd = Ks + r * QS_STRIDE + c;
            kd[0] = kv.x; kd[1] = kv.y; kd[2] = kv.z; kd[3] = kv.w;
            float4 vv = *(const float4*)(src + 2 * kD);
            *(float4*)(Vs + r * 128 + c) = vv;
        }
        __syncthreads();

        float s[4][4];
#pragma unroll
        for (int i = 0; i < 4; i++)
#pragma unroll
            for (int j = 0; j < 4; j++) s[i][j] = 0.f;

#pragma unroll 4
        for (int d = 0; d < kHD; d++) {
            float qa[4], kv[4];
#pragma unroll
            for (int i = 0; i < 4; i++) qa[i] = Qs[(tq * 4 + i) * QS_STRIDE + d];
#pragma unroll
            for (int j = 0; j < 4; j++) kv[j] = Ks[(tk * 4 + j) * QS_STRIDE + d];
#pragma unroll
            for (int i = 0; i < 4; i++)
#pragma unroll
                for (int j = 0; j < 4; j++) s[i][j] += qa[i] * kv[j];
        }

        bool diag = (kb == nkb - 1);
#pragma unroll
        for (int i = 0; i < 4; i++) {
            int qi = tq * 4 + i;
#pragma unroll
            for (int j = 0; j < 4; j++) {
                int kj = tk * 4 + j;
                float v = s[i][j];
                if (diag && kj > qi) v = -1e30f;
                Ps[qi * PS_STRIDE + kj] = v;
            }
        }
        __syncthreads();

        if (t < 64) {
            float mo = mrow[t];
            float mx = mo;
            float* pr = Ps + t * PS_STRIDE;
            for (int j = 0; j < 64; j++) mx = fmaxf(mx, pr[j]);
            float corr = expf(mo - mx);
            float sum = 0.f;
            for (int j = 0; j < 64; j++) {
                float p = expf(pr[j] - mx);
                pr[j] = p;
                sum += p;
            }
            lrow[t] = lrow[t] * corr + sum;
            mrow[t] = mx;
            crow[t] = corr;
        }
        __syncthreads();

        float c4v[4];
#pragma unroll
        for (int i = 0; i < 4; i++) c4v[i] = crow[tq * 4 + i];
#pragma unroll
        for (int i = 0; i < 4; i++)
#pragma unroll
            for (int dj = 0; dj < 8; dj++) o[i][dj] *= c4v[i];

        for (int j = 0; j < 64; j++) {
            float p[4];
#pragma unroll
            for (int i = 0; i < 4; i++) p[i] = Ps[(tq * 4 + i) * PS_STRIDE + j];
            float v[8];
#pragma unroll
            for (int dj = 0; dj < 8; dj++) v[dj] = Vs[j * 128 + tk * 8 + dj];
#pragma unroll
            for (int i = 0; i < 4; i++)
#pragma unroll
                for (int dj = 0; dj < 8; dj++) o[i][dj] += p[i] * v[dj];
        }
    }

    __syncthreads();
#pragma unroll
    for (int i = 0; i < 4; i++) {
        int qi = tq * 4 + i;
        float inv = 1.f / lrow[qi];
        float* dst = o_out + ((size_t)b * kL + q0 + qi) * kD + h * kHD + tk * 8;
#pragma unroll
        for (int dj = 0; dj < 8; dj++) dst[dj] = o[i][dj] * inv;
    }
}

// ---------------------------------------------------------------------------
// Launch
// ---------------------------------------------------------------------------
extern "C" void kernel_launch(void* const* d_in, const int* in_sizes, int n_in,
                              void* d_out, int out_size) {
    (void)in_sizes; (void)n_in; (void)out_size;
    const float* x       = (const float*)d_in[0];
    const float* norm1_w = (const float*)d_in[2];
    const float* qkv_w   = (const float*)d_in[3];
    const float* out_w   = (const float*)d_in[4];
    const float* norm2_w = (const float*)d_in[5];
    const float* gate_w  = (const float*)d_in[6];
    const float* up_w    = (const float*)d_in[7];
    const float* down_w  = (const float*)d_in[8];
    float* out = (float*)d_out;

    float *h, *qkvb, *attnb, *x2, *gate, *act;
    cudaGetSymbolAddress((void**)&h, g_h);
    cudaGetSymbolAddress((void**)&qkvb, g_qkv);
    cudaGetSymbolAddress((void**)&attnb, g_attn);
    cudaGetSymbolAddress((void**)&x2, g_x2);
    cudaGetSymbolAddress((void**)&gate, g_gate);
    cudaGetSymbolAddress((void**)&act, g_act);

    cudaFuncSetAttribute((const void*)attn_kernel,
                         cudaFuncAttributeMaxDynamicSharedMemorySize, ATTN_SMEM);
    cudaFuncSetAttribute((const void*)gemm_tf32<0>,
                         cudaFuncAttributeMaxDynamicSharedMemorySize, GEMM_SMEM);
    cudaFuncSetAttribute((const void*)gemm_tf32<1>,
                         cudaFuncAttributeMaxDynamicSharedMemorySize, GEMM_SMEM);
    cudaFuncSetAttribute((const void*)gemm_tf32<2>,
                         cudaFuncAttributeMaxDynamicSharedMemorySize, GEMM_SMEM);
    cudaFuncSetAttribute((const void*)gemm_tf32<3>,
                         cudaFuncAttributeMaxDynamicSharedMemorySize, GEMM_SMEM);

    // 1) h = rmsnorm(x, norm1_w)
    rmsnorm_kernel<<<kM, 256>>>(x, norm1_w, h);
    // 2) qkv = h @ qkv_w^T
    gemm_tf32<0><<<dim3(3 * kD / 128, kM / 128), 256, GEMM_SMEM>>>(h, qkv_w, qkvb, nullptr, 3 * kD, kD);
    // 3) attention
    attn_kernel<<<dim3(kL / 64, kH, kB), 256, ATTN_SMEM>>>(qkvb, attnb);
    // 4) x2 = attn @ out_w^T + x
    gemm_tf32<1><<<dim3(kD / 128, kM / 128), 256, GEMM_SMEM>>>(attnb, out_w, x2, x, kD, kD);
    // 5) h = rmsnorm(x2, norm2_w)
    rmsnorm_kernel<<<kM, 256>>>(x2, norm2_w, h);
    // 6) gate = silu(h @ gate_w^T)
    gemm_tf32<2><<<dim3(kFF / 128, kM / 128), 256, GEMM_SMEM>>>(h, gate_w, gate, nullptr, kFF, kD);
    // 7) act = (h @ up_w^T) * gate
    gemm_tf32<3><<<dim3(kFF / 128, kM / 128), 256, GEMM_SMEM>>>(h, up_w, act, gate, kFF, kD);
    // 8) out = act @ down_w^T + x2
    gemm_tf32<1><<<dim3(kD / 128, kM / 128), 256, GEMM_SMEM>>>(act, down_w, out, x2, kD, kFF);
}

// round 5
// speedup vs baseline: 2.7737x; 1.0328x over previous
#include <cuda_runtime.h>
#include <math.h>
#include <stdint.h>

// Problem constants
constexpr int kB  = 2;
constexpr int kL  = 2048;
constexpr int kD  = 2048;
constexpr int kH  = 16;
constexpr int kHD = 128;
constexpr int kFF = 8192;
constexpr int kM  = kB * kL;  // 4096 rows

// ---------------------------------------------------------------------------
// Scratch buffers (device globals — no allocation allowed)
// ---------------------------------------------------------------------------
__device__ float g_h[(size_t)kM * kD];
__device__ float g_qkv[(size_t)kM * 3 * kD];
__device__ float g_attn[(size_t)kM * kD];
__device__ float g_x2[(size_t)kM * kD];
__device__ float g_gate[(size_t)kM * kFF];
__device__ float g_act[(size_t)kM * kFF];

// Single extern shared symbol for all kernels
extern __shared__ char dynsmem[];

// ---------------------------------------------------------------------------
// PTX helpers
// ---------------------------------------------------------------------------
__device__ __forceinline__ uint32_t f2tf32(float x) {
    uint32_t r;
    asm("cvt.rna.tf32.f32 %0, %1;" : "=r"(r) : "f"(x));
    return r;
}
__device__ __forceinline__ void mma_tf32(float* c, const uint32_t* a, const uint32_t* b) {
    asm volatile(
        "mma.sync.aligned.m16n8k8.row.col.f32.tf32.tf32.f32 "
        "{%0,%1,%2,%3}, {%4,%5,%6,%7}, {%8,%9}, {%0,%1,%2,%3};"
        : "+f"(c[0]), "+f"(c[1]), "+f"(c[2]), "+f"(c[3])
        : "r"(a[0]), "r"(a[1]), "r"(a[2]), "r"(a[3]), "r"(b[0]), "r"(b[1]));
}

// ---------------------------------------------------------------------------
// TF32 mma.sync GEMM: C[M,N] = A[M,K] @ B[N,K]^T (both K-major fp32).
// Block tile 128x256, BK=32, 8 warps each 64x64, tf32 pre-converted in SMEM,
// register double-buffered global loads, SMEM double buffer.
// EPI: 0 none, 1 +Aux, 2 silu, 3 *Aux. M%128==0, N%256==0, K%32==0.
// ---------------------------------------------------------------------------
constexpr int BM = 128, BN = 256, BK = 32;
constexpr int LDS_STRIDE = 36;  // floats per smem row (conflict-free)
constexpr int A_FLOATS = BM * LDS_STRIDE;  // 4608
constexpr int B_FLOATS = BN * LDS_STRIDE;  // 9216
constexpr int GEMM_SMEM = 2 * (A_FLOATS + B_FLOATS) * 4;  // 110592 bytes

template <int EPI>
__global__ __launch_bounds__(256, 1) void gemm_mma(const float* __restrict__ A,
                                                   const float* __restrict__ Bm,
                                                   float* __restrict__ C,
                                                   const float* __restrict__ Aux,
                                                   int Ndim, int Kdim) {
    uint32_t* smw = (uint32_t*)dynsmem;
    uint32_t* As = smw;                  // [2][128*36]
    uint32_t* Bs = smw + 2 * A_FLOATS;   // [2][256*36]

    const int tid = threadIdx.x;
    const int wid = tid >> 5, lane = tid & 31;
    const int r = lane >> 2, c = lane & 3;
    const int m0 = blockIdx.y * BM;
    const int n0 = blockIdx.x * BN;
    const int wm = (wid >> 2) * 64;
    const int wn = (wid & 3) * 64;

    const float* Ab = A + (size_t)m0 * Kdim;
    const float* Bb = Bm + (size_t)n0 * Kdim;

    float acc[4][8][4];
#pragma unroll
    for (int mb = 0; mb < 4; mb++)
#pragma unroll
        for (int nb = 0; nb < 8; nb++)
#pragma unroll
            for (int q = 0; q < 4; q++) acc[mb][nb][q] = 0.f;

    float4 pa[4], pb[8];

    const int KT = Kdim / BK;

    // Prefetch stage 0 into registers
    {
#pragma unroll
        for (int i = 0; i < 4; i++) {
            int idx = tid + 256 * i;
            pa[i] = *(const float4*)(Ab + (size_t)(idx >> 3) * Kdim + (idx & 7) * 4);
        }
#pragma unroll
        for (int i = 0; i < 8; i++) {
            int idx = tid + 256 * i;
            pb[i] = *(const float4*)(Bb + (size_t)(idx >> 3) * Kdim + (idx & 7) * 4);
        }
    }

    for (int kt = 0; kt < KT; kt++) {
        const int buf = kt & 1;
        uint32_t* as_w = As + buf * A_FLOATS;
        uint32_t* bs_w = Bs + buf * B_FLOATS;

        // Store prefetched registers (converted to tf32) into SMEM
#pragma unroll
        for (int i = 0; i < 4; i++) {
            int idx = tid + 256 * i;
            uint32_t off = (idx >> 3) * LDS_STRIDE + (idx & 7) * 4;
            *(uint4*)(as_w + off) = make_uint4(f2tf32(pa[i].x), f2tf32(pa[i].y),
                                               f2tf32(pa[i].z), f2tf32(pa[i].w));
        }
#pragma unroll
        for (int i = 0; i < 8; i++) {
            int idx = tid + 256 * i;
            uint32_t off = (idx >> 3) * LDS_STRIDE + (idx & 7) * 4;
            *(uint4*)(bs_w + off) = make_uint4(f2tf32(pb[i].x), f2tf32(pb[i].y),
                                               f2tf32(pb[i].z), f2tf32(pb[i].w));
        }
        __syncthreads();

        // Prefetch next stage (global latency hides under the MMA phase)
        if (kt + 1 < KT) {
            const size_t ko = (size_t)(kt + 1) * BK;
#pragma unroll
            for (int i = 0; i < 4; i++) {
                int idx = tid + 256 * i;
                pa[i] = *(const float4*)(Ab + (size_t)(idx >> 3) * Kdim + ko + (idx & 7) * 4);
            }
#pragma unroll
            for (int i = 0; i < 8; i++) {
                int idx = tid + 256 * i;
                pb[i] = *(const float4*)(Bb + (size_t)(idx >> 3) * Kdim + ko + (idx & 7) * 4);
            }
        }

        // MMA phase: 4 k8-steps, 32 MMAs each
        const uint32_t* as_r = As + buf * A_FLOATS;
        const uint32_t* bs_r = Bs + buf * B_FLOATS;
#pragma unroll
        for (int ks = 0; ks < 4; ks++) {
            uint32_t af[4][4], bf[8][2];
            const uint32_t* ap = as_r + ks * 8 + c;
#pragma unroll
            for (int mb = 0; mb < 4; mb++) {
                int base = (wm + mb * 16 + r) * LDS_STRIDE;
                af[mb][0] = ap[base];
                af[mb][1] = ap[base + 8 * LDS_STRIDE];
                af[mb][2] = ap[base + 4];
                af[mb][3] = ap[base + 8 * LDS_STRIDE + 4];
            }
            const uint32_t* bp = bs_r + ks * 8 + c;
#pragma unroll
            for (int nb = 0; nb < 8; nb++) {
                int base = (wn + nb * 8 + r) * LDS_STRIDE;
                bf[nb][0] = bp[base];
                bf[nb][1] = bp[base + 4];
            }
#pragma unroll
            for (int mb = 0; mb < 4; mb++)
#pragma unroll
                for (int nb = 0; nb < 8; nb++)
                    mma_tf32(acc[mb][nb], af[mb], bf[nb]);
        }
        __syncthreads();
    }

    // Epilogue
#pragma unroll
    for (int mb = 0; mb < 4; mb++) {
#pragma unroll
        for (int nb = 0; nb < 8; nb++) {
            int row0 = m0 + wm + mb * 16 + r;
            int col = n0 + wn + nb * 8 + c * 2;
#pragma unroll
            for (int half = 0; half < 2; half++) {
                size_t off = (size_t)(row0 + half * 8) * Ndim + col;
                float v0 = acc[mb][nb][half * 2 + 0];
                float v1 = acc[mb][nb][half * 2 + 1];
                if (EPI == 1 || EPI == 3) {
                    float2 a2 = *(const float2*)(Aux + off);
                    if (EPI == 1) { v0 += a2.x; v1 += a2.y; }
                    else          { v0 *= a2.x; v1 *= a2.y; }
                }
                if (EPI == 2) {
                    v0 = v0 / (1.f + expf(-v0));
                    v1 = v1 / (1.f + expf(-v1));
                }
                *(float2*)(C + off) = make_float2(v0, v1);
            }
        }
    }
}

// ---------------------------------------------------------------------------
// RMSNorm: one block per row, 256 threads, D=2048
// ---------------------------------------------------------------------------
__global__ __launch_bounds__(256) void rmsnorm_kernel(const float* __restrict__ x,
                                                      const float* __restrict__ w,
                                                      float* __restrict__ out) {
    int row = blockIdx.x;
    int t = threadIdx.x;
    const float4* xr = (const float4*)(x + (size_t)row * kD);
    float4 v0 = xr[t];
    float4 v1 = xr[t + 256];
    float s = v0.x * v0.x + v0.y * v0.y + v0.z * v0.z + v0.w * v0.w
            + v1.x * v1.x + v1.y * v1.y + v1.z * v1.z + v1.w * v1.w;
#pragma unroll
    for (int o = 16; o > 0; o >>= 1) s += __shfl_xor_sync(0xffffffffu, s, o);

    __shared__ float red[8];
    __shared__ float rtot;
    int wid = t >> 5, lane = t & 31;
    if (lane == 0) red[wid] = s;
    __syncthreads();
    if (t == 0) {
        float tot = 0.f;
#pragma unroll
        for (int i = 0; i < 8; i++) tot += red[i];
        rtot = rsqrtf(tot * (1.0f / kD) + 1e-6f);
    }
    __syncthreads();
    float r = rtot;

    const float4* wv = (const float4*)w;
    float4 w0 = wv[t], w1 = wv[t + 256];
    float4 r0, r1;
    r0.x = v0.x * r * w0.x; r0.y = v0.y * r * w0.y;
    r0.z = v0.z * r * w0.z; r0.w = v0.w * r * w0.w;
    r1.x = v1.x * r * w1.x; r1.y = v1.y * r * w1.y;
    r1.z = v1.z * r * w1.z; r1.w = v1.w * r * w1.w;
    float4* ov = (float4*)(out + (size_t)row * kD);
    ov[t] = r0;
    ov[t + 256] = r1;
}

// ---------------------------------------------------------------------------
// Flash attention (fp32, causal).
// ---------------------------------------------------------------------------
constexpr int QS_STRIDE = 129;
constexpr int PS_STRIDE = 65;
constexpr int ATTN_SMEM_FLOATS = 64 * QS_STRIDE * 2
                               + 64 * 128
                               + 64 * PS_STRIDE
                               + 3 * 64;
constexpr int ATTN_SMEM = ATTN_SMEM_FLOATS * 4;

__global__ __launch_bounds__(256) void attn_kernel(const float* __restrict__ qkv,
                                                   float* __restrict__ o_out) {
    float* smf = (float*)dynsmem;
    float* Qs = smf;
    float* Ks = Qs + 64 * QS_STRIDE;
    float* Vs = Ks + 64 * QS_STRIDE;
    float* Ps = Vs + 64 * 128;
    float* mrow = Ps + 64 * PS_STRIDE;
    float* lrow = mrow + 64;
    float* crow = lrow + 64;

    int q0 = blockIdx.x * 64;
    int h = blockIdx.y;
    int b = blockIdx.z;
    int t = threadIdx.x;
    const float scale = 0.08838834764831845f;

    const float* qbase = qkv + ((size_t)b * kL) * (3 * kD) + h * kHD;

    for (int idx = t; idx < 64 * 32; idx += 256) {
        int r = idx >> 5, c = (idx & 31) * 4;
        float4 v = *(const float4*)(qbase + (size_t)(q0 + r) * (3 * kD) + c);
        float* dst = Qs + r * QS_STRIDE + c;
        dst[0] = v.x * scale; dst[1] = v.y * scale;
        dst[2] = v.z * scale; dst[3] = v.w * scale;
    }
    if (t < 64) { mrow[t] = -1e30f; lrow[t] = 0.f; }

    float o[4][8];
#pragma unroll
    for (int i = 0; i < 4; i++)
#pragma unroll
        for (int j = 0; j < 8; j++) o[i][j] = 0.f;

    int tq = t >> 4, tk = t & 15;
    int nkb = blockIdx.x + 1;

    for (int kb = 0; kb < nkb; kb++) {
        int k0 = kb * 64;
        __syncthreads();
        for (int idx = t; idx < 64 * 32; idx += 256) {
            int r = idx >> 5, c = (idx & 31) * 4;
            const float* src = qbase + (size_t)(k0 + r) * (3 * kD) + c;
            float4 kv = *(const float4*)(src + kD);
            float* kd = Ks + r * QS_STRIDE + c;
            kd[0] = kv.x; kd[1] = kv.y; kd[2] = kv.z; kd[3] = kv.w;
            float4 vv = *(const float4*)(src + 2 * kD);
            *(float4*)(Vs + r * 128 + c) = vv;
        }
        __syncthreads();

        float s[4][4];
#pragma unroll
        for (int i = 0; i < 4; i++)
#pragma unroll
            for (int j = 0; j < 4; j++) s[i][j] = 0.f;

#pragma unroll 4
        for (int d = 0; d < kHD; d++) {
            float qa[4], kv[4];
#pragma unroll
            for (int i = 0; i < 4; i++) qa[i] = Qs[(tq * 4 + i) * QS_STRIDE + d];
#pragma unroll
            for (int j = 0; j < 4; j++) kv[j] = Ks[(tk * 4 + j) * QS_STRIDE + d];
#pragma unroll
            for (int i = 0; i < 4; i++)
#pragma unroll
                for (int j = 0; j < 4; j++) s[i][j] += qa[i] * kv[j];
        }

        bool diag = (kb == nkb - 1);
#pragma unroll
        for (int i = 0; i < 4; i++) {
            int qi = tq * 4 + i;
#pragma unroll
            for (int j = 0; j < 4; j++) {
                int kj = tk * 4 + j;
                float v = s[i][j];
                if (diag && kj > qi) v = -1e30f;
                Ps[qi * PS_STRIDE + kj] = v;
            }
        }
        __syncthreads();

        if (t < 64) {
            float mo = mrow[t];
            float mx = mo;
            float* pr = Ps + t * PS_STRIDE;
            for (int j = 0; j < 64; j++) mx = fmaxf(mx, pr[j]);
            float corr = expf(mo - mx);
            float sum = 0.f;
            for (int j = 0; j < 64; j++) {
                float p = expf(pr[j] - mx);
                pr[j] = p;
                sum += p;
            }
            lrow[t] = lrow[t] * corr + sum;
            mrow[t] = mx;
            crow[t] = corr;
        }
        __syncthreads();

        float c4v[4];
#pragma unroll
        for (int i = 0; i < 4; i++) c4v[i] = crow[tq * 4 + i];
#pragma unroll
        for (int i = 0; i < 4; i++)
#pragma unroll
            for (int dj = 0; dj < 8; dj++) o[i][dj] *= c4v[i];

        for (int j = 0; j < 64; j++) {
            float p[4];
#pragma unroll
            for (int i = 0; i < 4; i++) p[i] = Ps[(tq * 4 + i) * PS_STRIDE + j];
            float v[8];
#pragma unroll
            for (int dj = 0; dj < 8; dj++) v[dj] = Vs[j * 128 + tk * 8 + dj];
#pragma unroll
            for (int i = 0; i < 4; i++)
#pragma unroll
                for (int dj = 0; dj < 8; dj++) o[i][dj] += p[i] * v[dj];
        }
    }

    __syncthreads();
#pragma unroll
    for (int i = 0; i < 4; i++) {
        int qi = tq * 4 + i;
        float inv = 1.f / lrow[qi];
        float* dst = o_out + ((size_t)b * kL + q0 + qi) * kD + h * kHD + tk * 8;
#pragma unroll
        for (int dj = 0; dj < 8; dj++) dst[dj] = o[i][dj] * inv;
    }
}

// ---------------------------------------------------------------------------
// Launch
// ---------------------------------------------------------------------------
extern "C" void kernel_launch(void* const* d_in, const int* in_sizes, int n_in,
                              void* d_out, int out_size) {
    (void)in_sizes; (void)n_in; (void)out_size;
    const float* x       = (const float*)d_in[0];
    const float* norm1_w = (const float*)d_in[2];
    const float* qkv_w   = (const float*)d_in[3];
    const float* out_w   = (const float*)d_in[4];
    const float* norm2_w = (const float*)d_in[5];
    const float* gate_w  = (const float*)d_in[6];
    const float* up_w    = (const float*)d_in[7];
    const float* down_w  = (const float*)d_in[8];
    float* out = (float*)d_out;

    float *h, *qkvb, *attnb, *x2, *gate, *act;
    cudaGetSymbolAddress((void**)&h, g_h);
    cudaGetSymbolAddress((void**)&qkvb, g_qkv);
    cudaGetSymbolAddress((void**)&attnb, g_attn);
    cudaGetSymbolAddress((void**)&x2, g_x2);
    cudaGetSymbolAddress((void**)&gate, g_gate);
    cudaGetSymbolAddress((void**)&act, g_act);

    cudaFuncSetAttribute((const void*)attn_kernel,
                         cudaFuncAttributeMaxDynamicSharedMemorySize, ATTN_SMEM);
    cudaFuncSetAttribute((const void*)gemm_mma<0>,
                         cudaFuncAttributeMaxDynamicSharedMemorySize, GEMM_SMEM);
    cudaFuncSetAttribute((const void*)gemm_mma<1>,
                         cudaFuncAttributeMaxDynamicSharedMemorySize, GEMM_SMEM);
    cudaFuncSetAttribute((const void*)gemm_mma<2>,
                         cudaFuncAttributeMaxDynamicSharedMemorySize, GEMM_SMEM);
    cudaFuncSetAttribute((const void*)gemm_mma<3>,
                         cudaFuncAttributeMaxDynamicSharedMemorySize, GEMM_SMEM);

    // 1) h = rmsnorm(x, norm1_w)
    rmsnorm_kernel<<<kM, 256>>>(x, norm1_w, h);
    // 2) qkv = h @ qkv_w^T
    gemm_mma<0><<<dim3(3 * kD / BN, kM / BM), 256, GEMM_SMEM>>>(h, qkv_w, qkvb, nullptr, 3 * kD, kD);
    // 3) attention
    attn_kernel<<<dim3(kL / 64, kH, kB), 256, ATTN_SMEM>>>(qkvb, attnb);
    // 4) x2 = attn @ out_w^T + x
    gemm_mma<1><<<dim3(kD / BN, kM / BM), 256, GEMM_SMEM>>>(attnb, out_w, x2, x, kD, kD);
    // 5) h = rmsnorm(x2, norm2_w)
    rmsnorm_kernel<<<kM, 256>>>(x2, norm2_w, h);
    // 6) gate = silu(h @ gate_w^T)
    gemm_mma<2><<<dim3(kFF / BN, kM / BM), 256, GEMM_SMEM>>>(h, gate_w, gate, nullptr, kFF, kD);
    // 7) act = (h @ up_w^T) * gate
    gemm_mma<3><<<dim3(kFF / BN, kM / BM), 256, GEMM_SMEM>>>(h, up_w, act, gate, kFF, kD);
    // 8) out = act @ down_w^T + x2
    gemm_mma<1><<<dim3(kD / BN, kM / BM), 256, GEMM_SMEM>>>(act, down_w, out, x2, kD, kFF);
}

// round 6
// speedup vs baseline: 2.8594x; 1.0309x over previous
#include <cuda_runtime.h>
#include <math.h>
#include <stdint.h>

// Problem constants
constexpr int kB  = 2;
constexpr int kL  = 2048;
constexpr int kD  = 2048;
constexpr int kH  = 16;
constexpr int kHD = 128;
constexpr int kFF = 8192;
constexpr int kM  = kB * kL;  // 4096 rows

// ---------------------------------------------------------------------------
// Scratch buffers (device globals — no allocation allowed)
// ---------------------------------------------------------------------------
__device__ float g_h[(size_t)kM * kD];
__device__ float g_qkv[(size_t)kM * 3 * kD];
__device__ float g_attn[(size_t)kM * kD];
__device__ float g_x2[(size_t)kM * kD];
__device__ float g_gate[(size_t)kM * kFF];
__device__ float g_act[(size_t)kM * kFF];
// tf32-rounded weights: [qkv 3D*D][out D*D][gate FF*D][up FF*D][down D*FF]
constexpr size_t W_QKV  = 0;
constexpr size_t W_OUT  = (size_t)3 * kD * kD;            // 12582912
constexpr size_t W_GATE = W_OUT + (size_t)kD * kD;        // 16777216
constexpr size_t W_UP   = W_GATE + (size_t)kFF * kD;      // 33554432
constexpr size_t W_DOWN = W_UP + (size_t)kFF * kD;        // 50331648
constexpr size_t W_TOTAL = W_DOWN + (size_t)kD * kFF;     // 67108864
__device__ float g_wc[W_TOTAL];

// Single extern shared symbol for all kernels
extern __shared__ char dynsmem[];

// ---------------------------------------------------------------------------
// PTX helpers
// ---------------------------------------------------------------------------
__device__ __forceinline__ uint32_t f2tf32(float x) {
    uint32_t r;
    asm("cvt.rna.tf32.f32 %0, %1;" : "=r"(r) : "f"(x));
    return r;
}
__device__ __forceinline__ float rnd_tf32(float x) {
    return __uint_as_float(f2tf32(x));
}
__device__ __forceinline__ void mma_tf32(float* c, const uint32_t* a, const uint32_t* b) {
    asm volatile(
        "mma.sync.aligned.m16n8k8.row.col.f32.tf32.tf32.f32 "
        "{%0,%1,%2,%3}, {%4,%5,%6,%7}, {%8,%9}, {%0,%1,%2,%3};"
        : "+f"(c[0]), "+f"(c[1]), "+f"(c[2]), "+f"(c[3])
        : "r"(a[0]), "r"(a[1]), "r"(a[2]), "r"(a[3]), "r"(b[0]), "r"(b[1]));
}
__device__ __forceinline__ void cp_async16(uint32_t smem_addr, const float* gmem) {
    asm volatile("cp.async.cg.shared.global [%0], [%1], 16;\n"
                 :: "r"(smem_addr), "l"(gmem));
}
__device__ __forceinline__ void cp_commit() {
    asm volatile("cp.async.commit_group;\n" ::: "memory");
}
__device__ __forceinline__ void cp_wait2() {
    asm volatile("cp.async.wait_group 2;\n" ::: "memory");
}
__device__ __forceinline__ uint32_t smem_u32(const void* p) {
    uint32_t a;
    asm("{ .reg .u64 t; cvta.to.shared.u64 t, %1; cvt.u32.u64 %0, t; }"
        : "=r"(a) : "l"(p));
    return a;
}

// ---------------------------------------------------------------------------
// Weight pre-round: out[i] = tf32_rna(in[i]), float4 elements
// ---------------------------------------------------------------------------
__global__ __launch_bounds__(256) void cvt_tf32_kernel(const float4* __restrict__ in,
                                                       float4* __restrict__ out, int n4) {
    int i = blockIdx.x * 256 + threadIdx.x;
    if (i < n4) {
        float4 v = in[i];
        out[i] = make_float4(rnd_tf32(v.x), rnd_tf32(v.y), rnd_tf32(v.z), rnd_tf32(v.w));
    }
}

// ---------------------------------------------------------------------------
// TF32 mma.sync GEMM: C[M,N] = A[M,K] @ B[N,K]^T.
// A and B hold tf32-rounded fp32 (HW truncation = exact). Block 128x256,
// BK=32, 8 warps each 64x64, 4-stage cp.async pipeline, padded-36 SMEM.
// EPI: 0 none, 1 +Aux, 2 silu, 3 *Aux.  RND: round outputs to tf32.
// ---------------------------------------------------------------------------
constexpr int BM = 128, BN = 256, BK = 32;
constexpr int LDSS = 36;                       // floats per smem row
constexpr int A_FLOATS = BM * LDSS;            // 4608
constexpr int B_FLOATS = BN * LDSS;            // 9216
constexpr int STAGE_FLOATS = A_FLOATS + B_FLOATS;  // 13824
constexpr int NSTAGE = 4;
constexpr int GEMM_SMEM = NSTAGE * STAGE_FLOATS * 4;  // 221184 bytes

__device__ __forceinline__ void issue_stage(uint32_t sA, uint32_t sB,
                                            const float* __restrict__ Ab,
                                            const float* __restrict__ Bb,
                                            int kt, int Kdim, int tid) {
    const size_t ko = (size_t)kt * BK;
#pragma unroll
    for (int i = 0; i < 4; i++) {
        int idx = tid + 256 * i;
        int row = idx >> 3, c = idx & 7;
        cp_async16(sA + (row * LDSS + c * 4) * 4, Ab + (size_t)row * Kdim + ko + c * 4);
    }
#pragma unroll
    for (int i = 0; i < 8; i++) {
        int idx = tid + 256 * i;
        int row = idx >> 3, c = idx & 7;
        cp_async16(sB + (row * LDSS + c * 4) * 4, Bb + (size_t)row * Kdim + ko + c * 4);
    }
}

template <int EPI, bool RND>
__global__ __launch_bounds__(256, 1) void gemm_mma(const float* __restrict__ A,
                                                   const float* __restrict__ Bm,
                                                   float* __restrict__ C,
                                                   const float* __restrict__ Aux,
                                                   int Ndim, int Kdim) {
    uint32_t* smw = (uint32_t*)dynsmem;
    const uint32_t sbase = smem_u32(smw);

    const int tid = threadIdx.x;
    const int wid = tid >> 5, lane = tid & 31;
    const int r = lane >> 2, c = lane & 3;
    const int m0 = blockIdx.y * BM;
    const int n0 = blockIdx.x * BN;
    const int wm = (wid >> 2) * 64;
    const int wn = (wid & 3) * 64;

    const float* Ab = A + (size_t)m0 * Kdim;
    const float* Bb = Bm + (size_t)n0 * Kdim;
    const int KT = Kdim / BK;

    float acc[4][8][4];
#pragma unroll
    for (int mb = 0; mb < 4; mb++)
#pragma unroll
        for (int nb = 0; nb < 8; nb++)
#pragma unroll
            for (int q = 0; q < 4; q++) acc[mb][nb][q] = 0.f;

    // Prologue: fill stages 0..2
#pragma unroll
    for (int s = 0; s < 3; s++) {
        uint32_t sA = sbase + s * STAGE_FLOATS * 4;
        issue_stage(sA, sA + A_FLOATS * 4, Ab, Bb, s, Kdim, tid);
        cp_commit();
    }

    for (int kt = 0; kt < KT; kt++) {
        cp_wait2();
        __syncthreads();
        // Refill stage (kt+3): slot last read at iter kt-1, all warps past it.
        if (kt + 3 < KT) {
            int fs = (kt + 3) & 3;
            uint32_t sA = sbase + fs * STAGE_FLOATS * 4;
            issue_stage(sA, sA + A_FLOATS * 4, Ab, Bb, kt + 3, Kdim, tid);
        }
        cp_commit();  // empty group at tail keeps wait_group bookkeeping exact

        const uint32_t* as_r = smw + (kt & 3) * STAGE_FLOATS;
        const uint32_t* bs_r = as_r + A_FLOATS;
#pragma unroll
        for (int ks = 0; ks < 4; ks++) {
            uint32_t af[4][4], bf[8][2];
            const uint32_t* ap = as_r + ks * 8 + c;
#pragma unroll
            for (int mb = 0; mb < 4; mb++) {
                int base = (wm + mb * 16 + r) * LDSS;
                af[mb][0] = ap[base];
                af[mb][1] = ap[base + 8 * LDSS];
                af[mb][2] = ap[base + 4];
                af[mb][3] = ap[base + 8 * LDSS + 4];
            }
            const uint32_t* bp = bs_r + ks * 8 + c;
#pragma unroll
            for (int nb = 0; nb < 8; nb++) {
                int base = (wn + nb * 8 + r) * LDSS;
                bf[nb][0] = bp[base];
                bf[nb][1] = bp[base + 4];
            }
#pragma unroll
            for (int mb = 0; mb < 4; mb++)
#pragma unroll
                for (int nb = 0; nb < 8; nb++)
                    mma_tf32(acc[mb][nb], af[mb], bf[nb]);
        }
        __syncthreads();
    }

    // Epilogue
#pragma unroll
    for (int mb = 0; mb < 4; mb++) {
#pragma unroll
        for (int nb = 0; nb < 8; nb++) {
            int row0 = m0 + wm + mb * 16 + r;
            int col = n0 + wn + nb * 8 + c * 2;
#pragma unroll
            for (int half = 0; half < 2; half++) {
                size_t off = (size_t)(row0 + half * 8) * Ndim + col;
                float v0 = acc[mb][nb][half * 2 + 0];
                float v1 = acc[mb][nb][half * 2 + 1];
                if (EPI == 1 || EPI == 3) {
                    float2 a2 = *(const float2*)(Aux + off);
                    if (EPI == 1) { v0 += a2.x; v1 += a2.y; }
                    else          { v0 *= a2.x; v1 *= a2.y; }
                }
                if (EPI == 2) {
                    v0 = v0 / (1.f + expf(-v0));
                    v1 = v1 / (1.f + expf(-v1));
                }
                if (RND) { v0 = rnd_tf32(v0); v1 = rnd_tf32(v1); }
                *(float2*)(C + off) = make_float2(v0, v1);
            }
        }
    }
}

// ---------------------------------------------------------------------------
// RMSNorm: one block per row, 256 threads, D=2048. Output tf32-rounded
// (it feeds MMA A-operands only).
// ---------------------------------------------------------------------------
__global__ __launch_bounds__(256) void rmsnorm_kernel(const float* __restrict__ x,
                                                      const float* __restrict__ w,
                                                      float* __restrict__ out) {
    int row = blockIdx.x;
    int t = threadIdx.x;
    const float4* xr = (const float4*)(x + (size_t)row * kD);
    float4 v0 = xr[t];
    float4 v1 = xr[t + 256];
    float s = v0.x * v0.x + v0.y * v0.y + v0.z * v0.z + v0.w * v0.w
            + v1.x * v1.x + v1.y * v1.y + v1.z * v1.z + v1.w * v1.w;
#pragma unroll
    for (int o = 16; o > 0; o >>= 1) s += __shfl_xor_sync(0xffffffffu, s, o);

    __shared__ float red[8];
    __shared__ float rtot;
    int wid = t >> 5, lane = t & 31;
    if (lane == 0) red[wid] = s;
    __syncthreads();
    if (t == 0) {
        float tot = 0.f;
#pragma unroll
        for (int i = 0; i < 8; i++) tot += red[i];
        rtot = rsqrtf(tot * (1.0f / kD) + 1e-6f);
    }
    __syncthreads();
    float r = rtot;

    const float4* wv = (const float4*)w;
    float4 w0 = wv[t], w1 = wv[t + 256];
    float4 r0, r1;
    r0.x = rnd_tf32(v0.x * r * w0.x); r0.y = rnd_tf32(v0.y * r * w0.y);
    r0.z = rnd_tf32(v0.z * r * w0.z); r0.w = rnd_tf32(v0.w * r * w0.w);
    r1.x = rnd_tf32(v1.x * r * w1.x); r1.y = rnd_tf32(v1.y * r * w1.y);
    r1.z = rnd_tf32(v1.z * r * w1.z); r1.w = rnd_tf32(v1.w * r * w1.w);
    float4* ov = (float4*)(out + (size_t)row * kD);
    ov[t] = r0;
    ov[t + 256] = r1;
}

// ---------------------------------------------------------------------------
// Flash attention (fp32, causal). Output tf32-rounded (feeds out-proj MMA).
// ---------------------------------------------------------------------------
constexpr int QS_STRIDE = 129;
constexpr int PS_STRIDE = 65;
constexpr int ATTN_SMEM_FLOATS = 64 * QS_STRIDE * 2
                               + 64 * 128
                               + 64 * PS_STRIDE
                               + 3 * 64;
constexpr int ATTN_SMEM = ATTN_SMEM_FLOATS * 4;

__global__ __launch_bounds__(256) void attn_kernel(const float* __restrict__ qkv,
                                                   float* __restrict__ o_out) {
    float* smf = (float*)dynsmem;
    float* Qs = smf;
    float* Ks = Qs + 64 * QS_STRIDE;
    float* Vs = Ks + 64 * QS_STRIDE;
    float* Ps = Vs + 64 * 128;
    float* mrow = Ps + 64 * PS_STRIDE;
    float* lrow = mrow + 64;
    float* crow = lrow + 64;

    int q0 = blockIdx.x * 64;
    int h = blockIdx.y;
    int b = blockIdx.z;
    int t = threadIdx.x;
    const float scale = 0.08838834764831845f;

    const float* qbase = qkv + ((size_t)b * kL) * (3 * kD) + h * kHD;

    for (int idx = t; idx < 64 * 32; idx += 256) {
        int r = idx >> 5, c = (idx & 31) * 4;
        float4 v = *(const float4*)(qbase + (size_t)(q0 + r) * (3 * kD) + c);
        float* dst = Qs + r * QS_STRIDE + c;
        dst[0] = v.x * scale; dst[1] = v.y * scale;
        dst[2] = v.z * scale; dst[3] = v.w * scale;
    }
    if (t < 64) { mrow[t] = -1e30f; lrow[t] = 0.f; }

    float o[4][8];
#pragma unroll
    for (int i = 0; i < 4; i++)
#pragma unroll
        for (int j = 0; j < 8; j++) o[i][j] = 0.f;

    int tq = t >> 4, tk = t & 15;
    int nkb = blockIdx.x + 1;

    for (int kb = 0; kb < nkb; kb++) {
        int k0 = kb * 64;
        __syncthreads();
        for (int idx = t; idx < 64 * 32; idx += 256) {
            int r = idx >> 5, c = (idx & 31) * 4;
            const float* src = qbase + (size_t)(k0 + r) * (3 * kD) + c;
            float4 kv = *(const float4*)(src + kD);
            float* kd = Ks + r * QS_STRIDE + c;
            kd[0] = kv.x; kd[1] = kv.y; kd[2] = kv.z; kd[3] = kv.w;
            float4 vv = *(const float4*)(src + 2 * kD);
            *(float4*)(Vs + r * 128 + c) = vv;
        }
        __syncthreads();

        float s[4][4];
#pragma unroll
        for (int i = 0; i < 4; i++)
#pragma unroll
            for (int j = 0; j < 4; j++) s[i][j] = 0.f;

#pragma unroll 4
        for (int d = 0; d < kHD; d++) {
            float qa[4], kv[4];
#pragma unroll
            for (int i = 0; i < 4; i++) qa[i] = Qs[(tq * 4 + i) * QS_STRIDE + d];
#pragma unroll
            for (int j = 0; j < 4; j++) kv[j] = Ks[(tk * 4 + j) * QS_STRIDE + d];
#pragma unroll
            for (int i = 0; i < 4; i++)
#pragma unroll
                for (int j = 0; j < 4; j++) s[i][j] += qa[i] * kv[j];
        }

        bool diag = (kb == nkb - 1);
#pragma unroll
        for (int i = 0; i < 4; i++) {
            int qi = tq * 4 + i;
#pragma unroll
            for (int j = 0; j < 4; j++) {
                int kj = tk * 4 + j;
                float v = s[i][j];
                if (diag && kj > qi) v = -1e30f;
                Ps[qi * PS_STRIDE + kj] = v;
            }
        }
        __syncthreads();

        if (t < 64) {
            float mo = mrow[t];
            float mx = mo;
            float* pr = Ps + t * PS_STRIDE;
            for (int j = 0; j < 64; j++) mx = fmaxf(mx, pr[j]);
            float corr = expf(mo - mx);
            float sum = 0.f;
            for (int j = 0; j < 64; j++) {
                float p = expf(pr[j] - mx);
                pr[j] = p;
                sum += p;
            }
            lrow[t] = lrow[t] * corr + sum;
            mrow[t] = mx;
            crow[t] = corr;
        }
        __syncthreads();

        float c4v[4];
#pragma unroll
        for (int i = 0; i < 4; i++) c4v[i] = crow[tq * 4 + i];
#pragma unroll
        for (int i = 0; i < 4; i++)
#pragma unroll
            for (int dj = 0; dj < 8; dj++) o[i][dj] *= c4v[i];

        for (int j = 0; j < 64; j++) {
            float p[4];
#pragma unroll
            for (int i = 0; i < 4; i++) p[i] = Ps[(tq * 4 + i) * PS_STRIDE + j];
            float v[8];
#pragma unroll
            for (int dj = 0; dj < 8; dj++) v[dj] = Vs[j * 128 + tk * 8 + dj];
#pragma unroll
            for (int i = 0; i < 4; i++)
#pragma unroll
                for (int dj = 0; dj < 8; dj++) o[i][dj] += p[i] * v[dj];
        }
    }

    __syncthreads();
#pragma unroll
    for (int i = 0; i < 4; i++) {
        int qi = tq * 4 + i;
        float inv = 1.f / lrow[qi];
        float* dst = o_out + ((size_t)b * kL + q0 + qi) * kD + h * kHD + tk * 8;
#pragma unroll
        for (int dj = 0; dj < 8; dj++) dst[dj] = rnd_tf32(o[i][dj] * inv);
    }
}

// ---------------------------------------------------------------------------
// Launch
// ---------------------------------------------------------------------------
extern "C" void kernel_launch(void* const* d_in, const int* in_sizes, int n_in,
                              void* d_out, int out_size) {
    (void)in_sizes; (void)n_in; (void)out_size;
    const float* x       = (const float*)d_in[0];
    const float* norm1_w = (const float*)d_in[2];
    const float* qkv_w   = (const float*)d_in[3];
    const float* out_w   = (const float*)d_in[4];
    const float* norm2_w = (const float*)d_in[5];
    const float* gate_w  = (const float*)d_in[6];
    const float* up_w    = (const float*)d_in[7];
    const float* down_w  = (const float*)d_in[8];
    float* out = (float*)d_out;

    float *h, *qkvb, *attnb, *x2, *gate, *act, *wc;
    cudaGetSymbolAddress((void**)&h, g_h);
    cudaGetSymbolAddress((void**)&qkvb, g_qkv);
    cudaGetSymbolAddress((void**)&attnb, g_attn);
    cudaGetSymbolAddress((void**)&x2, g_x2);
    cudaGetSymbolAddress((void**)&gate, g_gate);
    cudaGetSymbolAddress((void**)&act, g_act);
    cudaGetSymbolAddress((void**)&wc, g_wc);

    cudaFuncSetAttribute((const void*)attn_kernel,
                         cudaFuncAttributeMaxDynamicSharedMemorySize, ATTN_SMEM);
    cudaFuncSetAttribute((const void*)gemm_mma<0, false>,
                         cudaFuncAttributeMaxDynamicSharedMemorySize, GEMM_SMEM);
    cudaFuncSetAttribute((const void*)gemm_mma<1, false>,
                         cudaFuncAttributeMaxDynamicSharedMemorySize, GEMM_SMEM);
    cudaFuncSetAttribute((const void*)gemm_mma<2, false>,
                         cudaFuncAttributeMaxDynamicSharedMemorySize, GEMM_SMEM);
    cudaFuncSetAttribute((const void*)gemm_mma<3, true>,
                         cudaFuncAttributeMaxDynamicSharedMemorySize, GEMM_SMEM);

    // 0) Pre-round weights to tf32
    cvt_tf32_kernel<<<(int)((W_OUT - W_QKV) / 4 + 255) / 256, 256>>>(
        (const float4*)qkv_w, (float4*)(wc + W_QKV), (int)((W_OUT - W_QKV) / 4));
    cvt_tf32_kernel<<<(int)((W_GATE - W_OUT) / 4 + 255) / 256, 256>>>(
        (const float4*)out_w, (float4*)(wc + W_OUT), (int)((W_GATE - W_OUT) / 4));
    cvt_tf32_kernel<<<(int)((W_UP - W_GATE) / 4 + 255) / 256, 256>>>(
        (const float4*)gate_w, (float4*)(wc + W_GATE), (int)((W_UP - W_GATE) / 4));
    cvt_tf32_kernel<<<(int)((W_DOWN - W_UP) / 4 + 255) / 256, 256>>>(
        (const float4*)up_w, (float4*)(wc + W_UP), (int)((W_DOWN - W_UP) / 4));
    cvt_tf32_kernel<<<(int)((W_TOTAL - W_DOWN) / 4 + 255) / 256, 256>>>(
        (const float4*)down_w, (float4*)(wc + W_DOWN), (int)((W_TOTAL - W_DOWN) / 4));

    // 1) h = rmsnorm(x, norm1_w)  [tf32-rounded]
    rmsnorm_kernel<<<kM, 256>>>(x, norm1_w, h);
    // 2) qkv = h @ qkv_w^T
    gemm_mma<0, false><<<dim3(3 * kD / BN, kM / BM), 256, GEMM_SMEM>>>(
        h, wc + W_QKV, qkvb, nullptr, 3 * kD, kD);
    // 3) attention  [output tf32-rounded]
    attn_kernel<<<dim3(kL / 64, kH, kB), 256, ATTN_SMEM>>>(qkvb, attnb);
    // 4) x2 = attn @ out_w^T + x
    gemm_mma<1, false><<<dim3(kD / BN, kM / BM), 256, GEMM_SMEM>>>(
        attnb, wc + W_OUT, x2, x, kD, kD);
    // 5) h = rmsnorm(x2, norm2_w)  [tf32-rounded]
    rmsnorm_kernel<<<kM, 256>>>(x2, norm2_w, h);
    // 6) gate = silu(h @ gate_w^T)  [fp32, elementwise aux]
    gemm_mma<2, false><<<dim3(kFF / BN, kM / BM), 256, GEMM_SMEM>>>(
        h, wc + W_GATE, gate, nullptr, kFF, kD);
    // 7) act = (h @ up_w^T) * gate  [tf32-rounded, feeds down-proj MMA]
    gemm_mma<3, true><<<dim3(kFF / BN, kM / BM), 256, GEMM_SMEM>>>(
        h, wc + W_UP, act, gate, kFF, kD);
    // 8) out = act @ down_w^T + x2
    gemm_mma<1, false><<<dim3(kD / BN, kM / BM), 256, GEMM_SMEM>>>(
        act, wc + W_DOWN, out, x2, kD, kFF);
}

// round 7
// speedup vs baseline: 4.2862x; 1.4990x over previous
#include <cuda_runtime.h>
#include <cuda_fp16.h>
#include <math.h>
#include <stdint.h>

// Problem constants
constexpr int kB  = 2;
constexpr int kL  = 2048;
constexpr int kD  = 2048;
constexpr int kH  = 16;
constexpr int kHD = 128;
constexpr int kFF = 8192;
constexpr int kM  = kB * kL;  // 4096 rows

// ---------------------------------------------------------------------------
// Scratch buffers (device globals — no allocation allowed)
// ---------------------------------------------------------------------------
__device__ float g_qkv[(size_t)kM * 3 * kD];   // qkv projection (fp32, attention input)
__device__ float g_x2[(size_t)kM * kD];        // residual after attention
__device__ float g_gate[(size_t)kM * kFF];     // silu(gate) fp32
__device__ __half g_h16[(size_t)kM * kD];      // rmsnorm output (fp16 GEMM A)
__device__ __half g_attn16[(size_t)kM * kD];   // attention output (fp16 GEMM A)
__device__ __half g_act16[(size_t)kM * kFF];   // silu(gate)*up (fp16 GEMM A)
// fp16 weights: [qkv 3D*D][out D*D][gate FF*D][up FF*D][down D*FF]
constexpr size_t W_QKV  = 0;
constexpr size_t W_OUT  = (size_t)3 * kD * kD;
constexpr size_t W_GATE = W_OUT + (size_t)kD * kD;
constexpr size_t W_UP   = W_GATE + (size_t)kFF * kD;
constexpr size_t W_DOWN = W_UP + (size_t)kFF * kD;
constexpr size_t W_TOTAL = W_DOWN + (size_t)kD * kFF;
__device__ __half g_w16[W_TOTAL];

// Single extern shared symbol for all kernels
extern __shared__ char dynsmem[];

// ---------------------------------------------------------------------------
// PTX helpers
// ---------------------------------------------------------------------------
__device__ __forceinline__ void mma_f16(float* c, const uint32_t* a, const uint32_t* b) {
    asm volatile(
        "mma.sync.aligned.m16n8k16.row.col.f32.f16.f16.f32 "
        "{%0,%1,%2,%3}, {%4,%5,%6,%7}, {%8,%9}, {%0,%1,%2,%3};"
        : "+f"(c[0]), "+f"(c[1]), "+f"(c[2]), "+f"(c[3])
        : "r"(a[0]), "r"(a[1]), "r"(a[2]), "r"(a[3]), "r"(b[0]), "r"(b[1]));
}
__device__ __forceinline__ void cp_async16(uint32_t smem_addr, const void* gmem) {
    asm volatile("cp.async.cg.shared.global [%0], [%1], 16;\n"
                 :: "r"(smem_addr), "l"(gmem));
}
__device__ __forceinline__ void cp_commit() {
    asm volatile("cp.async.commit_group;\n" ::: "memory");
}
__device__ __forceinline__ void cp_wait2() {
    asm volatile("cp.async.wait_group 2;\n" ::: "memory");
}
__device__ __forceinline__ uint32_t smem_u32(const void* p) {
    uint32_t a;
    asm("{ .reg .u64 t; cvta.to.shared.u64 t, %1; cvt.u32.u64 %0, t; }"
        : "=r"(a) : "l"(p));
    return a;
}

// ---------------------------------------------------------------------------
// Weight convert: fp32 -> fp16, 4 elements per thread
// ---------------------------------------------------------------------------
__global__ __launch_bounds__(256) void cvt_f16_kernel(const float4* __restrict__ in,
                                                      uint2* __restrict__ out, int n4) {
    int i = blockIdx.x * 256 + threadIdx.x;
    if (i < n4) {
        float4 v = in[i];
        __half2 h0 = __floats2half2_rn(v.x, v.y);
        __half2 h1 = __floats2half2_rn(v.z, v.w);
        out[i] = make_uint2(*(uint32_t*)&h0, *(uint32_t*)&h1);
    }
}

// ---------------------------------------------------------------------------
// FP16 mma.sync GEMM: C[M,N] = A[M,K] @ B[N,K]^T (both K-major fp16).
// Block 128x256, BK=64, 8 warps each 64x64, 4-stage cp.async pipeline.
// SMEM rows: 64 halves (128B) + 16B pad = 144B = 36 words (conflict-free).
// EPI: 0 none, 1 +Aux, 2 silu, 3 *Aux.  OUT16: write __half else float.
// M%128==0, N%256==0, K%64==0.
// ---------------------------------------------------------------------------
constexpr int BM = 128, BN = 256, BK = 64;
constexpr int ROW_W = 36;                         // 32-bit words per smem row
constexpr int A_WORDS = BM * ROW_W;               // 4608
constexpr int B_WORDS = BN * ROW_W;               // 9216
constexpr int STAGE_WORDS = A_WORDS + B_WORDS;    // 13824
constexpr int NSTAGE = 4;
constexpr int GEMM_SMEM = NSTAGE * STAGE_WORDS * 4;  // 221184 bytes

__device__ __forceinline__ void issue_stage(uint32_t sA, uint32_t sB,
                                            const __half* __restrict__ Ab,
                                            const __half* __restrict__ Bb,
                                            int kt, int Kdim, int tid) {
    const size_t ko = (size_t)kt * BK;
    // A: 128 rows x 8 chunks(16B); 1024 chunks, 4 per thread
#pragma unroll
    for (int i = 0; i < 4; i++) {
        int idx = tid + 256 * i;
        int row = idx >> 3, ch = idx & 7;
        cp_async16(sA + row * 144 + ch * 16, Ab + (size_t)row * Kdim + ko + ch * 8);
    }
    // B: 256 rows x 8 chunks; 2048 chunks, 8 per thread
#pragma unroll
    for (int i = 0; i < 8; i++) {
        int idx = tid + 256 * i;
        int row = idx >> 3, ch = idx & 7;
        cp_async16(sB + row * 144 + ch * 16, Bb + (size_t)row * Kdim + ko + ch * 8);
    }
}

template <int EPI, bool OUT16>
__global__ __launch_bounds__(256, 1) void gemm_h(const __half* __restrict__ A,
                                                 const __half* __restrict__ Bm,
                                                 void* __restrict__ Cv,
                                                 const float* __restrict__ Aux,
                                                 int Ndim, int Kdim) {
    uint32_t* smw = (uint32_t*)dynsmem;
    const uint32_t sbase = smem_u32(smw);

    const int tid = threadIdx.x;
    const int wid = tid >> 5, lane = tid & 31;
    const int r = lane >> 2, c = lane & 3;
    const int m0 = blockIdx.y * BM;
    const int n0 = blockIdx.x * BN;
    const int wm = (wid >> 2) * 64;
    const int wn = (wid & 3) * 64;

    const __half* Ab = A + (size_t)m0 * Kdim;
    const __half* Bb = Bm + (size_t)n0 * Kdim;
    const int KT = Kdim / BK;

    float acc[4][8][4];
#pragma unroll
    for (int mb = 0; mb < 4; mb++)
#pragma unroll
        for (int nb = 0; nb < 8; nb++)
#pragma unroll
            for (int q = 0; q < 4; q++) acc[mb][nb][q] = 0.f;

    // Prologue: fill stages 0..2
#pragma unroll
    for (int s = 0; s < 3; s++) {
        uint32_t sA = sbase + s * STAGE_WORDS * 4;
        issue_stage(sA, sA + A_WORDS * 4, Ab, Bb, s, Kdim, tid);
        cp_commit();
    }

    for (int kt = 0; kt < KT; kt++) {
        cp_wait2();
        __syncthreads();
        if (kt + 3 < KT) {
            int fs = (kt + 3) & 3;
            uint32_t sA = sbase + fs * STAGE_WORDS * 4;
            issue_stage(sA, sA + A_WORDS * 4, Ab, Bb, kt + 3, Kdim, tid);
        }
        cp_commit();  // empty group at tail keeps wait_group bookkeeping exact

        const uint32_t* as_r = smw + (kt & 3) * STAGE_WORDS;
        const uint32_t* bs_r = as_r + A_WORDS;
        // 4 k16-steps per stage
#pragma unroll
        for (int ks = 0; ks < 4; ks++) {
            uint32_t af[4][4], bf[8][2];
            const uint32_t* ap = as_r + ks * 8 + c;
#pragma unroll
            for (int mb = 0; mb < 4; mb++) {
                int base = (wm + mb * 16 + r) * ROW_W;
                af[mb][0] = ap[base];
                af[mb][1] = ap[base + 8 * ROW_W];
                af[mb][2] = ap[base + 4];
                af[mb][3] = ap[base + 8 * ROW_W + 4];
            }
            const uint32_t* bp = bs_r + ks * 8 + c;
#pragma unroll
            for (int nb = 0; nb < 8; nb++) {
                int base = (wn + nb * 8 + r) * ROW_W;
                bf[nb][0] = bp[base];
                bf[nb][1] = bp[base + 4];
            }
#pragma unroll
            for (int mb = 0; mb < 4; mb++)
#pragma unroll
                for (int nb = 0; nb < 8; nb++)
                    mma_f16(acc[mb][nb], af[mb], bf[nb]);
        }
        __syncthreads();
    }

    // Epilogue: c0,c1 at (row, col..col+1), c2,c3 at (row+8, ...)
#pragma unroll
    for (int mb = 0; mb < 4; mb++) {
#pragma unroll
        for (int nb = 0; nb < 8; nb++) {
            int row0 = m0 + wm + mb * 16 + r;
            int col = n0 + wn + nb * 8 + c * 2;
#pragma unroll
            for (int half = 0; half < 2; half++) {
                size_t off = (size_t)(row0 + half * 8) * Ndim + col;
                float v0 = acc[mb][nb][half * 2 + 0];
                float v1 = acc[mb][nb][half * 2 + 1];
                if (EPI == 1 || EPI == 3) {
                    float2 a2 = *(const float2*)(Aux + off);
                    if (EPI == 1) { v0 += a2.x; v1 += a2.y; }
                    else          { v0 *= a2.x; v1 *= a2.y; }
                }
                if (EPI == 2) {
                    v0 = v0 / (1.f + expf(-v0));
                    v1 = v1 / (1.f + expf(-v1));
                }
                if (OUT16) {
                    __half2 hv = __floats2half2_rn(v0, v1);
                    *(uint32_t*)((__half*)Cv + off) = *(uint32_t*)&hv;
                } else {
                    *(float2*)((float*)Cv + off) = make_float2(v0, v1);
                }
            }
        }
    }
}

// ---------------------------------------------------------------------------
// RMSNorm: one block per row, 256 threads, D=2048. fp16 output.
// ---------------------------------------------------------------------------
__global__ __launch_bounds__(256) void rmsnorm_kernel(const float* __restrict__ x,
                                                      const float* __restrict__ w,
                                                      __half* __restrict__ out) {
    int row = blockIdx.x;
    int t = threadIdx.x;
    const float4* xr = (const float4*)(x + (size_t)row * kD);
    float4 v0 = xr[t];
    float4 v1 = xr[t + 256];
    float s = v0.x * v0.x + v0.y * v0.y + v0.z * v0.z + v0.w * v0.w
            + v1.x * v1.x + v1.y * v1.y + v1.z * v1.z + v1.w * v1.w;
#pragma unroll
    for (int o = 16; o > 0; o >>= 1) s += __shfl_xor_sync(0xffffffffu, s, o);

    __shared__ float red[8];
    __shared__ float rtot;
    int wid = t >> 5, lane = t & 31;
    if (lane == 0) red[wid] = s;
    __syncthreads();
    if (t == 0) {
        float tot = 0.f;
#pragma unroll
        for (int i = 0; i < 8; i++) tot += red[i];
        rtot = rsqrtf(tot * (1.0f / kD) + 1e-6f);
    }
    __syncthreads();
    float r = rtot;

    const float4* wv = (const float4*)w;
    float4 w0 = wv[t], w1 = wv[t + 256];
    __half2 h0 = __floats2half2_rn(v0.x * r * w0.x, v0.y * r * w0.y);
    __half2 h1 = __floats2half2_rn(v0.z * r * w0.z, v0.w * r * w0.w);
    __half2 h2 = __floats2half2_rn(v1.x * r * w1.x, v1.y * r * w1.y);
    __half2 h3 = __floats2half2_rn(v1.z * r * w1.z, v1.w * r * w1.w);
    uint2* ov = (uint2*)(out + (size_t)row * kD);
    ov[t] = make_uint2(*(uint32_t*)&h0, *(uint32_t*)&h1);
    ov[t + 256] = make_uint2(*(uint32_t*)&h2, *(uint32_t*)&h3);
}

// ---------------------------------------------------------------------------
// Flash attention (fp32 compute, causal). fp16 output (feeds out-proj MMA).
// ---------------------------------------------------------------------------
constexpr int QS_STRIDE = 129;
constexpr int PS_STRIDE = 65;
constexpr int ATTN_SMEM_FLOATS = 64 * QS_STRIDE * 2
                               + 64 * 128
                               + 64 * PS_STRIDE
                               + 3 * 64;
constexpr int ATTN_SMEM = ATTN_SMEM_FLOATS * 4;

__global__ __launch_bounds__(256) void attn_kernel(const float* __restrict__ qkv,
                                                   __half* __restrict__ o_out) {
    float* smf = (float*)dynsmem;
    float* Qs = smf;
    float* Ks = Qs + 64 * QS_STRIDE;
    float* Vs = Ks + 64 * QS_STRIDE;
    float* Ps = Vs + 64 * 128;
    float* mrow = Ps + 64 * PS_STRIDE;
    float* lrow = mrow + 64;
    float* crow = lrow + 64;

    int q0 = blockIdx.x * 64;
    int h = blockIdx.y;
    int b = blockIdx.z;
    int t = threadIdx.x;
    const float scale = 0.08838834764831845f;

    const float* qbase = qkv + ((size_t)b * kL) * (3 * kD) + h * kHD;

    for (int idx = t; idx < 64 * 32; idx += 256) {
        int r = idx >> 5, c = (idx & 31) * 4;
        float4 v = *(const float4*)(qbase + (size_t)(q0 + r) * (3 * kD) + c);
        float* dst = Qs + r * QS_STRIDE + c;
        dst[0] = v.x * scale; dst[1] = v.y * scale;
        dst[2] = v.z * scale; dst[3] = v.w * scale;
    }
    if (t < 64) { mrow[t] = -1e30f; lrow[t] = 0.f; }

    float o[4][8];
#pragma unroll
    for (int i = 0; i < 4; i++)
#pragma unroll
        for (int j = 0; j < 8; j++) o[i][j] = 0.f;

    int tq = t >> 4, tk = t & 15;
    int nkb = blockIdx.x + 1;

    for (int kb = 0; kb < nkb; kb++) {
        int k0 = kb * 64;
        __syncthreads();
        for (int idx = t; idx < 64 * 32; idx += 256) {
            int r = idx >> 5, c = (idx & 31) * 4;
            const float* src = qbase + (size_t)(k0 + r) * (3 * kD) + c;
            float4 kv = *(const float4*)(src + kD);
            float* kd = Ks + r * QS_STRIDE + c;
            kd[0] = kv.x; kd[1] = kv.y; kd[2] = kv.z; kd[3] = kv.w;
            float4 vv = *(const float4*)(src + 2 * kD);
            *(float4*)(Vs + r * 128 + c) = vv;
        }
        __syncthreads();

        float s[4][4];
#pragma unroll
        for (int i = 0; i < 4; i++)
#pragma unroll
            for (int j = 0; j < 4; j++) s[i][j] = 0.f;

#pragma unroll 4
        for (int d = 0; d < kHD; d++) {
            float qa[4], kv[4];
#pragma unroll
            for (int i = 0; i < 4; i++) qa[i] = Qs[(tq * 4 + i) * QS_STRIDE + d];
#pragma unroll
            for (int j = 0; j < 4; j++) kv[j] = Ks[(tk * 4 + j) * QS_STRIDE + d];
#pragma unroll
            for (int i = 0; i < 4; i++)
#pragma unroll
                for (int j = 0; j < 4; j++) s[i][j] += qa[i] * kv[j];
        }

        bool diag = (kb == nkb - 1);
#pragma unroll
        for (int i = 0; i < 4; i++) {
            int qi = tq * 4 + i;
#pragma unroll
            for (int j = 0; j < 4; j++) {
                int kj = tk * 4 + j;
                float v = s[i][j];
                if (diag && kj > qi) v = -1e30f;
                Ps[qi * PS_STRIDE + kj] = v;
            }
        }
        __syncthreads();

        if (t < 64) {
            float mo = mrow[t];
            float mx = mo;
            float* pr = Ps + t * PS_STRIDE;
            for (int j = 0; j < 64; j++) mx = fmaxf(mx, pr[j]);
            float corr = expf(mo - mx);
            float sum = 0.f;
            for (int j = 0; j < 64; j++) {
                float p = expf(pr[j] - mx);
                pr[j] = p;
                sum += p;
            }
            lrow[t] = lrow[t] * corr + sum;
            mrow[t] = mx;
            crow[t] = corr;
        }
        __syncthreads();

        float c4v[4];
#pragma unroll
        for (int i = 0; i < 4; i++) c4v[i] = crow[tq * 4 + i];
#pragma unroll
        for (int i = 0; i < 4; i++)
#pragma unroll
            for (int dj = 0; dj < 8; dj++) o[i][dj] *= c4v[i];

        for (int j = 0; j < 64; j++) {
            float p[4];
#pragma unroll
            for (int i = 0; i < 4; i++) p[i] = Ps[(tq * 4 + i) * PS_STRIDE + j];
            float v[8];
#pragma unroll
            for (int dj = 0; dj < 8; dj++) v[dj] = Vs[j * 128 + tk * 8 + dj];
#pragma unroll
            for (int i = 0; i < 4; i++)
#pragma unroll
                for (int dj = 0; dj < 8; dj++) o[i][dj] += p[i] * v[dj];
        }
    }

    __syncthreads();
#pragma unroll
    for (int i = 0; i < 4; i++) {
        int qi = tq * 4 + i;
        float inv = 1.f / lrow[qi];
        __half* dst = o_out + ((size_t)b * kL + q0 + qi) * kD + h * kHD + tk * 8;
#pragma unroll
        for (int dj = 0; dj < 4; dj++) {
            __half2 hv = __floats2half2_rn(o[i][dj * 2] * inv, o[i][dj * 2 + 1] * inv);
            *(uint32_t*)(dst + dj * 2) = *(uint32_t*)&hv;
        }
    }
}

// ---------------------------------------------------------------------------
// Launch
// ---------------------------------------------------------------------------
extern "C" void kernel_launch(void* const* d_in, const int* in_sizes, int n_in,
                              void* d_out, int out_size) {
    (void)in_sizes; (void)n_in; (void)out_size;
    const float* x       = (const float*)d_in[0];
    const float* norm1_w = (const float*)d_in[2];
    const float* qkv_w   = (const float*)d_in[3];
    const float* out_w   = (const float*)d_in[4];
    const float* norm2_w = (const float*)d_in[5];
    const float* gate_w  = (const float*)d_in[6];
    const float* up_w    = (const float*)d_in[7];
    const float* down_w  = (const float*)d_in[8];
    float* out = (float*)d_out;

    float *qkvb, *x2, *gate;
    __half *h16, *attn16, *act16, *w16;
    cudaGetSymbolAddress((void**)&qkvb, g_qkv);
    cudaGetSymbolAddress((void**)&x2, g_x2);
    cudaGetSymbolAddress((void**)&gate, g_gate);
    cudaGetSymbolAddress((void**)&h16, g_h16);
    cudaGetSymbolAddress((void**)&attn16, g_attn16);
    cudaGetSymbolAddress((void**)&act16, g_act16);
    cudaGetSymbolAddress((void**)&w16, g_w16);

    cudaFuncSetAttribute((const void*)attn_kernel,
                         cudaFuncAttributeMaxDynamicSharedMemorySize, ATTN_SMEM);
    cudaFuncSetAttribute((const void*)gemm_h<0, false>,
                         cudaFuncAttributeMaxDynamicSharedMemorySize, GEMM_SMEM);
    cudaFuncSetAttribute((const void*)gemm_h<1, false>,
                         cudaFuncAttributeMaxDynamicSharedMemorySize, GEMM_SMEM);
    cudaFuncSetAttribute((const void*)gemm_h<2, false>,
                         cudaFuncAttributeMaxDynamicSharedMemorySize, GEMM_SMEM);
    cudaFuncSetAttribute((const void*)gemm_h<3, true>,
                         cudaFuncAttributeMaxDynamicSharedMemorySize, GEMM_SMEM);

    // 0) Convert weights to fp16
    cvt_f16_kernel<<<(int)((W_OUT - W_QKV) / 4 + 255) / 256, 256>>>(
        (const float4*)qkv_w, (uint2*)(w16 + W_QKV), (int)((W_OUT - W_QKV) / 4));
    cvt_f16_kernel<<<(int)((W_GATE - W_OUT) / 4 + 255) / 256, 256>>>(
        (const float4*)out_w, (uint2*)(w16 + W_OUT), (int)((W_GATE - W_OUT) / 4));
    cvt_f16_kernel<<<(int)((W_UP - W_GATE) / 4 + 255) / 256, 256>>>(
        (const float4*)gate_w, (uint2*)(w16 + W_GATE), (int)((W_UP - W_GATE) / 4));
    cvt_f16_kernel<<<(int)((W_DOWN - W_UP) / 4 + 255) / 256, 256>>>(
        (const float4*)up_w, (uint2*)(w16 + W_UP), (int)((W_DOWN - W_UP) / 4));
    cvt_f16_kernel<<<(int)((W_TOTAL - W_DOWN) / 4 + 255) / 256, 256>>>(
        (const float4*)down_w, (uint2*)(w16 + W_DOWN), (int)((W_TOTAL - W_DOWN) / 4));

    // 1) h16 = rmsnorm(x, norm1_w)
    rmsnorm_kernel<<<kM, 256>>>(x, norm1_w, h16);
    // 2) qkv = h16 @ qkv_w16^T  (fp32 out for attention)
    gemm_h<0, false><<<dim3(3 * kD / BN, kM / BM), 256, GEMM_SMEM>>>(
        h16, w16 + W_QKV, qkvb, nullptr, 3 * kD, kD);
    // 3) attention (fp16 out)
    attn_kernel<<<dim3(kL / 64, kH, kB), 256, ATTN_SMEM>>>(qkvb, attn16);
    // 4) x2 = attn16 @ out_w16^T + x
    gemm_h<1, false><<<dim3(kD / BN, kM / BM), 256, GEMM_SMEM>>>(
        attn16, w16 + W_OUT, x2, x, kD, kD);
    // 5) h16 = rmsnorm(x2, norm2_w)
    rmsnorm_kernel<<<kM, 256>>>(x2, norm2_w, h16);
    // 6) gate = silu(h16 @ gate_w16^T)  (fp32)
    gemm_h<2, false><<<dim3(kFF / BN, kM / BM), 256, GEMM_SMEM>>>(
        h16, w16 + W_GATE, gate, nullptr, kFF, kD);
    // 7) act16 = (h16 @ up_w16^T) * gate  (fp16 out)
    gemm_h<3, true><<<dim3(kFF / BN, kM / BM), 256, GEMM_SMEM>>>(
        h16, w16 + W_UP, act16, gate, kFF, kD);
    // 8) out = act16 @ down_w16^T + x2
    gemm_h<1, false><<<dim3(kD / BN, kM / BM), 256, GEMM_SMEM>>>(
        act16, w16 + W_DOWN, out, x2, kD, kFF);
}

// round 8
// speedup vs baseline: 6.6304x; 1.5469x over previous
#include <cuda_runtime.h>
#include <cuda_fp16.h>
#include <math.h>
#include <stdint.h>

// Problem constants
constexpr int kB  = 2;
constexpr int kL  = 2048;
constexpr int kD  = 2048;
constexpr int kH  = 16;
constexpr int kHD = 128;
constexpr int kFF = 8192;
constexpr int kM  = kB * kL;  // 4096 rows

// ---------------------------------------------------------------------------
// Scratch buffers (device globals — no allocation allowed)
// ---------------------------------------------------------------------------
__device__ float  g_x2[(size_t)kM * kD];        // residual after attention
__device__ float  g_gate[(size_t)kM * kFF];     // silu(gate) fp32
__device__ __half g_qkv16[(size_t)kM * 3 * kD]; // qkv projection (fp16)
__device__ __half g_h16[(size_t)kM * kD];       // rmsnorm output
__device__ __half g_attn16[(size_t)kM * kD];    // attention output
__device__ __half g_act16[(size_t)kM * kFF];    // silu(gate)*up
// fp16 weights
constexpr size_t W_QKV  = 0;
constexpr size_t W_OUT  = (size_t)3 * kD * kD;
constexpr size_t W_GATE = W_OUT + (size_t)kD * kD;
constexpr size_t W_UP   = W_GATE + (size_t)kFF * kD;
constexpr size_t W_DOWN = W_UP + (size_t)kFF * kD;
constexpr size_t W_TOTAL = W_DOWN + (size_t)kD * kFF;
__device__ __half g_w16[W_TOTAL];

extern __shared__ char dynsmem[];

// ---------------------------------------------------------------------------
// PTX helpers
// ---------------------------------------------------------------------------
__device__ __forceinline__ void mma_f16(float* c, const uint32_t* a, const uint32_t* b) {
    asm volatile(
        "mma.sync.aligned.m16n8k16.row.col.f32.f16.f16.f32 "
        "{%0,%1,%2,%3}, {%4,%5,%6,%7}, {%8,%9}, {%0,%1,%2,%3};"
        : "+f"(c[0]), "+f"(c[1]), "+f"(c[2]), "+f"(c[3])
        : "r"(a[0]), "r"(a[1]), "r"(a[2]), "r"(a[3]), "r"(b[0]), "r"(b[1]));
}
__device__ __forceinline__ void ldsm_x4(uint32_t& r0, uint32_t& r1, uint32_t& r2,
                                        uint32_t& r3, uint32_t addr) {
    asm volatile("ldmatrix.sync.aligned.m8n8.x4.shared.b16 {%0,%1,%2,%3}, [%4];"
                 : "=r"(r0), "=r"(r1), "=r"(r2), "=r"(r3) : "r"(addr));
}
__device__ __forceinline__ void ldsm_x4_t(uint32_t& r0, uint32_t& r1, uint32_t& r2,
                                          uint32_t& r3, uint32_t addr) {
    asm volatile("ldmatrix.sync.aligned.m8n8.x4.trans.shared.b16 {%0,%1,%2,%3}, [%4];"
                 : "=r"(r0), "=r"(r1), "=r"(r2), "=r"(r3) : "r"(addr));
}
__device__ __forceinline__ void cp_async16(uint32_t smem_addr, const void* gmem) {
    asm volatile("cp.async.cg.shared.global [%0], [%1], 16;\n"
                 :: "r"(smem_addr), "l"(gmem));
}
__device__ __forceinline__ void cp_commit() {
    asm volatile("cp.async.commit_group;\n" ::: "memory");
}
__device__ __forceinline__ void cp_wait2() {
    asm volatile("cp.async.wait_group 2;\n" ::: "memory");
}
__device__ __forceinline__ uint32_t smem_u32(const void* p) {
    uint32_t a;
    asm("{ .reg .u64 t; cvta.to.shared.u64 t, %1; cvt.u32.u64 %0, t; }"
        : "=r"(a) : "l"(p));
    return a;
}

// ---------------------------------------------------------------------------
// Weight convert: fp32 -> fp16
// ---------------------------------------------------------------------------
__global__ __launch_bounds__(256) void cvt_f16_kernel(const float4* __restrict__ in,
                                                      uint2* __restrict__ out, int n4) {
    int i = blockIdx.x * 256 + threadIdx.x;
    if (i < n4) {
        float4 v = in[i];
        __half2 h0 = __floats2half2_rn(v.x, v.y);
        __half2 h1 = __floats2half2_rn(v.z, v.w);
        out[i] = make_uint2(*(uint32_t*)&h0, *(uint32_t*)&h1);
    }
}

// ---------------------------------------------------------------------------
// FP16 mma.sync GEMM (ldmatrix fragments): C[M,N] = A[M,K] @ B[N,K]^T.
// Block 128x256, BK=64, 8 warps each 64x64, 4-stage cp.async pipeline.
// ---------------------------------------------------------------------------
constexpr int BM = 128, BN = 256, BK = 64;
constexpr int ROW_W = 36;                         // 32-bit words per smem row (144B)
constexpr int A_WORDS = BM * ROW_W;
constexpr int B_WORDS = BN * ROW_W;
constexpr int STAGE_WORDS = A_WORDS + B_WORDS;
constexpr int GEMM_SMEM = 4 * STAGE_WORDS * 4;    // 221184 bytes

__device__ __forceinline__ void issue_stage(uint32_t sA, uint32_t sB,
                                            const __half* __restrict__ Ab,
                                            const __half* __restrict__ Bb,
                                            int kt, int Kdim, int tid) {
    const size_t ko = (size_t)kt * BK;
#pragma unroll
    for (int i = 0; i < 4; i++) {
        int idx = tid + 256 * i;
        int row = idx >> 3, ch = idx & 7;
        cp_async16(sA + row * 144 + ch * 16, Ab + (size_t)row * Kdim + ko + ch * 8);
    }
#pragma unroll
    for (int i = 0; i < 8; i++) {
        int idx = tid + 256 * i;
        int row = idx >> 3, ch = idx & 7;
        cp_async16(sB + row * 144 + ch * 16, Bb + (size_t)row * Kdim + ko + ch * 8);
    }
}

template <int EPI, bool OUT16>
__global__ __launch_bounds__(256, 1) void gemm_h(const __half* __restrict__ A,
                                                 const __half* __restrict__ Bm,
                                                 void* __restrict__ Cv,
                                                 const float* __restrict__ Aux,
                                                 int Ndim, int Kdim) {
    const uint32_t sbase = smem_u32(dynsmem);
    const int tid = threadIdx.x;
    const int wid = tid >> 5, lane = tid & 31;
    const int r = lane >> 2, c = lane & 3;
    const int m0 = blockIdx.y * BM;
    const int n0 = blockIdx.x * BN;
    const int wm = (wid >> 2) * 64;
    const int wn = (wid & 3) * 64;

    const __half* Ab = A + (size_t)m0 * Kdim;
    const __half* Bb = Bm + (size_t)n0 * Kdim;
    const int KT = Kdim / BK;

    // ldmatrix lane-dependent base offsets (bytes, relative to stage base)
    const uint32_t a_off = ((wm + (lane & 15)) * ROW_W + (lane >> 4) * 4) * 4;
    const uint32_t b_off = ((wn + ((lane & 16) >> 1) + (lane & 7)) * ROW_W
                            + ((lane >> 3) & 1) * 4) * 4;

    float acc[4][8][4];
#pragma unroll
    for (int mb = 0; mb < 4; mb++)
#pragma unroll
        for (int nb = 0; nb < 8; nb++)
#pragma unroll
            for (int q = 0; q < 4; q++) acc[mb][nb][q] = 0.f;

#pragma unroll
    for (int s = 0; s < 3; s++) {
        uint32_t sA = sbase + s * STAGE_WORDS * 4;
        issue_stage(sA, sA + A_WORDS * 4, Ab, Bb, s, Kdim, tid);
        cp_commit();
    }

    for (int kt = 0; kt < KT; kt++) {
        cp_wait2();
        __syncthreads();
        if (kt + 3 < KT) {
            int fs = (kt + 3) & 3;
            uint32_t sA = sbase + fs * STAGE_WORDS * 4;
            issue_stage(sA, sA + A_WORDS * 4, Ab, Bb, kt + 3, Kdim, tid);
        }
        cp_commit();

        const uint32_t sA = sbase + (kt & 3) * STAGE_WORDS * 4;
        const uint32_t sB = sA + A_WORDS * 4;
#pragma unroll
        for (int ks = 0; ks < 4; ks++) {
            uint32_t af[4][4], bf[8][2];
#pragma unroll
            for (int mb = 0; mb < 4; mb++)
                ldsm_x4(af[mb][0], af[mb][1], af[mb][2], af[mb][3],
                        sA + a_off + mb * (16 * ROW_W * 4) + ks * 32);
#pragma unroll
            for (int nb2 = 0; nb2 < 4; nb2++)
                ldsm_x4(bf[2 * nb2][0], bf[2 * nb2][1], bf[2 * nb2 + 1][0], bf[2 * nb2 + 1][1],
                        sB + b_off + nb2 * (16 * ROW_W * 4) + ks * 32);
#pragma unroll
            for (int mb = 0; mb < 4; mb++)
#pragma unroll
                for (int nb = 0; nb < 8; nb++)
                    mma_f16(acc[mb][nb], af[mb], bf[nb]);
        }
        __syncthreads();
    }

    // Epilogue
#pragma unroll
    for (int mb = 0; mb < 4; mb++) {
#pragma unroll
        for (int nb = 0; nb < 8; nb++) {
            int row0 = m0 + wm + mb * 16 + r;
            int col = n0 + wn + nb * 8 + c * 2;
#pragma unroll
            for (int half = 0; half < 2; half++) {
                size_t off = (size_t)(row0 + half * 8) * Ndim + col;
                float v0 = acc[mb][nb][half * 2 + 0];
                float v1 = acc[mb][nb][half * 2 + 1];
                if (EPI == 1 || EPI == 3) {
                    float2 a2 = *(const float2*)(Aux + off);
                    if (EPI == 1) { v0 += a2.x; v1 += a2.y; }
                    else          { v0 *= a2.x; v1 *= a2.y; }
                }
                if (EPI == 2) {
                    v0 = v0 / (1.f + expf(-v0));
                    v1 = v1 / (1.f + expf(-v1));
                }
                if (OUT16) {
                    __half2 hv = __floats2half2_rn(v0, v1);
                    *(uint32_t*)((__half*)Cv + off) = *(uint32_t*)&hv;
                } else {
                    *(float2*)((float*)Cv + off) = make_float2(v0, v1);
                }
            }
        }
    }
}

// ---------------------------------------------------------------------------
// RMSNorm: one block per row, fp16 output
// ---------------------------------------------------------------------------
__global__ __launch_bounds__(256) void rmsnorm_kernel(const float* __restrict__ x,
                                                      const float* __restrict__ w,
                                                      __half* __restrict__ out) {
    int row = blockIdx.x;
    int t = threadIdx.x;
    const float4* xr = (const float4*)(x + (size_t)row * kD);
    float4 v0 = xr[t];
    float4 v1 = xr[t + 256];
    float s = v0.x * v0.x + v0.y * v0.y + v0.z * v0.z + v0.w * v0.w
            + v1.x * v1.x + v1.y * v1.y + v1.z * v1.z + v1.w * v1.w;
#pragma unroll
    for (int o = 16; o > 0; o >>= 1) s += __shfl_xor_sync(0xffffffffu, s, o);

    __shared__ float red[8];
    __shared__ float rtot;
    int wid = t >> 5, lane = t & 31;
    if (lane == 0) red[wid] = s;
    __syncthreads();
    if (t == 0) {
        float tot = 0.f;
#pragma unroll
        for (int i = 0; i < 8; i++) tot += red[i];
        rtot = rsqrtf(tot * (1.0f / kD) + 1e-6f);
    }
    __syncthreads();
    float r = rtot;

    const float4* wv = (const float4*)w;
    float4 w0 = wv[t], w1 = wv[t + 256];
    __half2 h0 = __floats2half2_rn(v0.x * r * w0.x, v0.y * r * w0.y);
    __half2 h1 = __floats2half2_rn(v0.z * r * w0.z, v0.w * r * w0.w);
    __half2 h2 = __floats2half2_rn(v1.x * r * w1.x, v1.y * r * w1.y);
    __half2 h3 = __floats2half2_rn(v1.z * r * w1.z, v1.w * r * w1.w);
    uint2* ov = (uint2*)(out + (size_t)row * kD);
    ov[t] = make_uint2(*(uint32_t*)&h0, *(uint32_t*)&h1);
    ov[t + 256] = make_uint2(*(uint32_t*)&h2, *(uint32_t*)&h3);
}

// ---------------------------------------------------------------------------
// Tensor-core flash attention (fp16 MMA, fp32 softmax/accum, causal).
// Block = (q-tile 64, head, batch), 256 threads / 8 warps.
// S warp: rows (w&3)*16, cols (w>>2)*32. O warp: rows (w&3)*16, cols (w>>2)*64.
// ---------------------------------------------------------------------------
constexpr int AQ_W = 68;                 // words per Q/K/V smem row (272B)
constexpr int PS_W = 65;                 // fp32 S row stride (floats)
constexpr int PH_W = 36;                 // fp16 P row stride (words)
constexpr int OFF_Q  = 0;
constexpr int OFF_K  = OFF_Q + 64 * AQ_W;
constexpr int OFF_V  = OFF_K + 64 * AQ_W;
constexpr int OFF_PS = OFF_V + 64 * AQ_W;
constexpr int OFF_PH = OFF_PS + 64 * PS_W;
constexpr int OFF_M  = OFF_PH + 64 * PH_W;
constexpr int OFF_L  = OFF_M + 64;
constexpr int OFF_C  = OFF_L + 64;
constexpr int ATTN_SMEM = (OFF_C + 64) * 4;   // 78848 bytes

__global__ __launch_bounds__(256, 2) void attn_kernel(const __half* __restrict__ qkv,
                                                      __half* __restrict__ o_out) {
    uint32_t* smw = (uint32_t*)dynsmem;
    const uint32_t sb = smem_u32(smw);
    float* ps = (float*)smw + OFF_PS;
    float* mrow = (float*)smw + OFF_M;
    float* lrow = (float*)smw + OFF_L;
    float* crow = (float*)smw + OFF_C;

    const int t = threadIdx.x, wid = t >> 5, lane = t & 31;
    const int q0 = blockIdx.x * 64, h = blockIdx.y, b = blockIdx.z;
    const float scale = 0.08838834764831845f;

    const __half* base = qkv + ((size_t)b * kL) * (3 * kD) + h * kHD;

    // Load Q tile [64][128] fp16
#pragma unroll
    for (int i = 0; i < 4; i++) {
        int idx = t + 256 * i;
        int row = idx >> 4, ch = idx & 15;
        *(uint4*)(smw + OFF_Q + row * AQ_W + ch * 4) =
            *(const uint4*)(base + (size_t)(q0 + row) * (3 * kD) + ch * 8);
    }
    if (t < 64) { mrow[t] = -1e30f; lrow[t] = 0.f; }

    const int wr  = (wid & 3) * 16;   // rows for S and O
    const int wcs = (wid >> 2) * 32;  // S cols
    const int wco = (wid >> 2) * 64;  // O cols
    const int l15 = lane & 15, l7 = lane & 7;

    // ldmatrix base addresses (bytes)
    const uint32_t qa = sb + (OFF_Q + (wr + l15) * AQ_W + (lane >> 4) * 4) * 4;
    const uint32_t ka = sb + (OFF_K + (wcs + ((lane & 16) >> 1) + l7) * AQ_W
                              + ((lane >> 3) & 1) * 4) * 4;
    const uint32_t pa = sb + (OFF_PH + (wr + l15) * PH_W + (lane >> 4) * 4) * 4;
    // V (trans): row = ks*16 + (lane&8) + l7 ; col_half extra = ((lane&16)>>1)
    const uint32_t va = sb + (OFF_V + ((lane & 8) + l7) * AQ_W) * 4
                        + (wco + ((lane & 16) >> 1)) * 2;

    float oacc[8][4];
#pragma unroll
    for (int nb = 0; nb < 8; nb++)
#pragma unroll
        for (int q = 0; q < 4; q++) oacc[nb][q] = 0.f;

    const int rS = wr + (lane >> 2);       // S/O fragment row (first of pair)
    const int cS = wcs + (lane & 3) * 2;   // S fragment col
    const int nkb = blockIdx.x + 1;

    for (int kb = 0; kb < nkb; kb++) {
        const int k0 = kb * 64;
        __syncthreads();  // K/V (and Q on first iter) safe to (re)fill / first use
        // Load K and V tiles [64][128] fp16
#pragma unroll
        for (int i = 0; i < 4; i++) {
            int idx = t + 256 * i;
            int row = idx >> 4, ch = idx & 15;
            const __half* kr = base + (size_t)(k0 + row) * (3 * kD) + kD + ch * 8;
            *(uint4*)(smw + OFF_K + row * AQ_W + ch * 4) = *(const uint4*)(kr);
            *(uint4*)(smw + OFF_V + row * AQ_W + ch * 4) = *(const uint4*)(kr + kD);
        }
        __syncthreads();

        // S = Q @ K^T  (8 k16-steps over HD=128)
        float sacc[4][4];
#pragma unroll
        for (int nb = 0; nb < 4; nb++)
#pragma unroll
            for (int q = 0; q < 4; q++) sacc[nb][q] = 0.f;
#pragma unroll
        for (int ks = 0; ks < 8; ks++) {
            uint32_t af[4], bf[4][2];
            ldsm_x4(af[0], af[1], af[2], af[3], qa + ks * 32);
            ldsm_x4(bf[0][0], bf[0][1], bf[1][0], bf[1][1], ka + ks * 32);
            ldsm_x4(bf[2][0], bf[2][1], bf[3][0], bf[3][1],
                    ka + 16 * AQ_W * 4 + ks * 32);
#pragma unroll
            for (int nb = 0; nb < 4; nb++) mma_f16(sacc[nb], af, bf[nb]);
        }

        // Store S (scaled + masked) to Ps
        const bool diag = (kb == nkb - 1);
#pragma unroll
        for (int nb = 0; nb < 4; nb++) {
            int col = cS + nb * 8;
            float v0 = sacc[nb][0] * scale, v1 = sacc[nb][1] * scale;
            float v2 = sacc[nb][2] * scale, v3 = sacc[nb][3] * scale;
            if (diag) {
                if (k0 + col > q0 + rS) v0 = -1e30f;
                if (k0 + col + 1 > q0 + rS) v1 = -1e30f;
                if (k0 + col > q0 + rS + 8) v2 = -1e30f;
                if (k0 + col + 1 > q0 + rS + 8) v3 = -1e30f;
            }
            ps[rS * PS_W + col] = v0; ps[rS * PS_W + col + 1] = v1;
            ps[(rS + 8) * PS_W + col] = v2; ps[(rS + 8) * PS_W + col + 1] = v3;
        }
        __syncthreads();

        // Online softmax: thread q < 64 owns row q; writes fp16 P
        if (t < 64) {
            float mo = mrow[t], mx = mo;
            const float* pr = ps + t * PS_W;
            for (int j = 0; j < 64; j++) mx = fmaxf(mx, pr[j]);
            float corr = expf(mo - mx), sum = 0.f;
            uint32_t* phr = smw + OFF_PH + t * PH_W;
            for (int j = 0; j < 64; j += 2) {
                float p0 = expf(pr[j] - mx);
                float p1 = expf(pr[j + 1] - mx);
                sum += p0 + p1;
                __half2 hp = __floats2half2_rn(p0, p1);
                phr[j >> 1] = *(uint32_t*)&hp;
            }
            lrow[t] = lrow[t] * corr + sum;
            mrow[t] = mx;
            crow[t] = corr;
        }
        __syncthreads();

        // Rescale O accumulators
        float corr0 = crow[rS], corr1 = crow[rS + 8];
#pragma unroll
        for (int nb = 0; nb < 8; nb++) {
            oacc[nb][0] *= corr0; oacc[nb][1] *= corr0;
            oacc[nb][2] *= corr1; oacc[nb][3] *= corr1;
        }

        // O += P @ V  (4 k16-steps over kv=64)
#pragma unroll
        for (int ks = 0; ks < 4; ks++) {
            uint32_t af[4], bv[8][2];
            ldsm_x4(af[0], af[1], af[2], af[3], pa + ks * 32);
#pragma unroll
            for (int nb2 = 0; nb2 < 4; nb2++)
                ldsm_x4_t(bv[2 * nb2][0], bv[2 * nb2][1],
                          bv[2 * nb2 + 1][0], bv[2 * nb2 + 1][1],
                          va + ks * (16 * AQ_W * 4) + nb2 * 32);
#pragma unroll
            for (int nb = 0; nb < 8; nb++) mma_f16(oacc[nb], af, bv[nb]);
        }
    }

    // Epilogue: normalize and write fp16
    float inv0 = 1.f / lrow[rS];
    float inv1 = 1.f / lrow[rS + 8];
#pragma unroll
    for (int nb = 0; nb < 8; nb++) {
        int col = wco + nb * 8 + (lane & 3) * 2;
        __half* d0 = o_out + ((size_t)(b * kL + q0 + rS)) * kD + h * kHD + col;
        __half* d1 = d0 + (size_t)8 * kD;
        __half2 h01 = __floats2half2_rn(oacc[nb][0] * inv0, oacc[nb][1] * inv0);
        __half2 h23 = __floats2half2_rn(oacc[nb][2] * inv1, oacc[nb][3] * inv1);
        *(uint32_t*)d0 = *(uint32_t*)&h01;
        *(uint32_t*)d1 = *(uint32_t*)&h23;
    }
}

// ---------------------------------------------------------------------------
// Launch
// ---------------------------------------------------------------------------
extern "C" void kernel_launch(void* const* d_in, const int* in_sizes, int n_in,
                              void* d_out, int out_size) {
    (void)in_sizes; (void)n_in; (void)out_size;
    const float* x       = (const float*)d_in[0];
    const float* norm1_w = (const float*)d_in[2];
    const float* qkv_w   = (const float*)d_in[3];
    const float* out_w   = (const float*)d_in[4];
    const float* norm2_w = (const float*)d_in[5];
    const float* gate_w  = (const float*)d_in[6];
    const float* up_w    = (const float*)d_in[7];
    const float* down_w  = (const float*)d_in[8];
    float* out = (float*)d_out;

    float *x2, *gate;
    __half *qkv16, *h16, *attn16, *act16, *w16;
    cudaGetSymbolAddress((void**)&x2, g_x2);
    cudaGetSymbolAddress((void**)&gate, g_gate);
    cudaGetSymbolAddress((void**)&qkv16, g_qkv16);
    cudaGetSymbolAddress((void**)&h16, g_h16);
    cudaGetSymbolAddress((void**)&attn16, g_attn16);
    cudaGetSymbolAddress((void**)&act16, g_act16);
    cudaGetSymbolAddress((void**)&w16, g_w16);

    cudaFuncSetAttribute((const void*)attn_kernel,
                         cudaFuncAttributeMaxDynamicSharedMemorySize, ATTN_SMEM);
    cudaFuncSetAttribute((const void*)gemm_h<0, true>,
                         cudaFuncAttributeMaxDynamicSharedMemorySize, GEMM_SMEM);
    cudaFuncSetAttribute((const void*)gemm_h<1, false>,
                         cudaFuncAttributeMaxDynamicSharedMemorySize, GEMM_SMEM);
    cudaFuncSetAttribute((const void*)gemm_h<2, false>,
                         cudaFuncAttributeMaxDynamicSharedMemorySize, GEMM_SMEM);
    cudaFuncSetAttribute((const void*)gemm_h<3, true>,
                         cudaFuncAttributeMaxDynamicSharedMemorySize, GEMM_SMEM);

    // 0) Convert weights to fp16
    cvt_f16_kernel<<<(int)((W_OUT - W_QKV) / 4 + 255) / 256, 256>>>(
        (const float4*)qkv_w, (uint2*)(w16 + W_QKV), (int)((W_OUT - W_QKV) / 4));
    cvt_f16_kernel<<<(int)((W_GATE - W_OUT) / 4 + 255) / 256, 256>>>(
        (const float4*)out_w, (uint2*)(w16 + W_OUT), (int)((W_GATE - W_OUT) / 4));
    cvt_f16_kernel<<<(int)((W_UP - W_GATE) / 4 + 255) / 256, 256>>>(
        (const float4*)gate_w, (uint2*)(w16 + W_GATE), (int)((W_UP - W_GATE) / 4));
    cvt_f16_kernel<<<(int)((W_DOWN - W_UP) / 4 + 255) / 256, 256>>>(
        (const float4*)up_w, (uint2*)(w16 + W_UP), (int)((W_DOWN - W_UP) / 4));
    cvt_f16_kernel<<<(int)((W_TOTAL - W_DOWN) / 4 + 255) / 256, 256>>>(
        (const float4*)down_w, (uint2*)(w16 + W_DOWN), (int)((W_TOTAL - W_DOWN) / 4));

    // 1) h16 = rmsnorm(x, norm1_w)
    rmsnorm_kernel<<<kM, 256>>>(x, norm1_w, h16);
    // 2) qkv16 = h16 @ qkv_w16^T  (fp16 out)
    gemm_h<0, true><<<dim3(3 * kD / BN, kM / BM), 256, GEMM_SMEM>>>(
        h16, w16 + W_QKV, qkv16, nullptr, 3 * kD, kD);
    // 3) tensor-core attention (fp16 out)
    attn_kernel<<<dim3(kL / 64, kH, kB), 256, ATTN_SMEM>>>(qkv16, attn16);
    // 4) x2 = attn16 @ out_w16^T + x
    gemm_h<1, false><<<dim3(kD / BN, kM / BM), 256, GEMM_SMEM>>>(
        attn16, w16 + W_OUT, x2, x, kD, kD);
    // 5) h16 = rmsnorm(x2, norm2_w)
    rmsnorm_kernel<<<kM, 256>>>(x2, norm2_w, h16);
    // 6) gate = silu(h16 @ gate_w16^T)  (fp32)
    gemm_h<2, false><<<dim3(kFF / BN, kM / BM), 256, GEMM_SMEM>>>(
        h16, w16 + W_GATE, gate, nullptr, kFF, kD);
    // 7) act16 = (h16 @ up_w16^T) * gate  (fp16 out)
    gemm_h<3, true><<<dim3(kFF / BN, kM / BM), 256, GEMM_SMEM>>>(
        h16, w16 + W_UP, act16, gate, kFF, kD);
    // 8) out = act16 @ down_w16^T + x2
    gemm_h<1, false><<<dim3(kD / BN, kM / BM), 256, GEMM_SMEM>>>(
        act16, w16 + W_DOWN, out, x2, kD, kFF);
}

// round 9
// speedup vs baseline: 7.4208x; 1.1192x over previous
#include <cuda_runtime.h>
#include <cuda_fp16.h>
#include <math.h>
#include <stdint.h>

// Problem constants
constexpr int kB  = 2;
constexpr int kL  = 2048;
constexpr int kD  = 2048;
constexpr int kH  = 16;
constexpr int kHD = 128;
constexpr int kFF = 8192;
constexpr int kM  = kB * kL;  // 4096 rows

// ---------------------------------------------------------------------------
// Scratch buffers (device globals — no allocation allowed)
// ---------------------------------------------------------------------------
__device__ float  g_x2[(size_t)kM * kD];
__device__ float  g_gate[(size_t)kM * kFF];
__device__ __half g_qkv16[(size_t)kM * 3 * kD];
__device__ __half g_h16[(size_t)kM * kD];
__device__ __half g_attn16[(size_t)kM * kD];
__device__ __half g_act16[(size_t)kM * kFF];
constexpr size_t W_QKV  = 0;
constexpr size_t W_OUT  = (size_t)3 * kD * kD;
constexpr size_t W_GATE = W_OUT + (size_t)kD * kD;
constexpr size_t W_UP   = W_GATE + (size_t)kFF * kD;
constexpr size_t W_DOWN = W_UP + (size_t)kFF * kD;
constexpr size_t W_TOTAL = W_DOWN + (size_t)kD * kFF;
__device__ __half g_w16[W_TOTAL];

extern __shared__ char dynsmem[];

// ---------------------------------------------------------------------------
// PTX helpers
// ---------------------------------------------------------------------------
__device__ __forceinline__ void mma_f16(float* c, const uint32_t* a, const uint32_t* b) {
    asm volatile(
        "mma.sync.aligned.m16n8k16.row.col.f32.f16.f16.f32 "
        "{%0,%1,%2,%3}, {%4,%5,%6,%7}, {%8,%9}, {%0,%1,%2,%3};"
        : "+f"(c[0]), "+f"(c[1]), "+f"(c[2]), "+f"(c[3])
        : "r"(a[0]), "r"(a[1]), "r"(a[2]), "r"(a[3]), "r"(b[0]), "r"(b[1]));
}
__device__ __forceinline__ void ldsm_x4(uint32_t& r0, uint32_t& r1, uint32_t& r2,
                                        uint32_t& r3, uint32_t addr) {
    asm volatile("ldmatrix.sync.aligned.m8n8.x4.shared.b16 {%0,%1,%2,%3}, [%4];"
                 : "=r"(r0), "=r"(r1), "=r"(r2), "=r"(r3) : "r"(addr));
}
__device__ __forceinline__ void ldsm_x4_t(uint32_t& r0, uint32_t& r1, uint32_t& r2,
                                          uint32_t& r3, uint32_t addr) {
    asm volatile("ldmatrix.sync.aligned.m8n8.x4.trans.shared.b16 {%0,%1,%2,%3}, [%4];"
                 : "=r"(r0), "=r"(r1), "=r"(r2), "=r"(r3) : "r"(addr));
}
__device__ __forceinline__ void cp_async16(uint32_t smem_addr, const void* gmem) {
    asm volatile("cp.async.cg.shared.global [%0], [%1], 16;\n"
                 :: "r"(smem_addr), "l"(gmem));
}
__device__ __forceinline__ void cp_commit() {
    asm volatile("cp.async.commit_group;\n" ::: "memory");
}
__device__ __forceinline__ void cp_wait1() {
    asm volatile("cp.async.wait_group 1;\n" ::: "memory");
}
__device__ __forceinline__ uint32_t smem_u32(const void* p) {
    uint32_t a;
    asm("{ .reg .u64 t; cvta.to.shared.u64 t, %1; cvt.u32.u64 %0, t; }"
        : "=r"(a) : "l"(p));
    return a;
}

// ---------------------------------------------------------------------------
// Weight convert: fp32 -> fp16
// ---------------------------------------------------------------------------
__global__ __launch_bounds__(256) void cvt_f16_kernel(const float4* __restrict__ in,
                                                      uint2* __restrict__ out, int n4) {
    int i = blockIdx.x * 256 + threadIdx.x;
    if (i < n4) {
        float4 v = in[i];
        __half2 h0 = __floats2half2_rn(v.x, v.y);
        __half2 h1 = __floats2half2_rn(v.z, v.w);
        out[i] = make_uint2(*(uint32_t*)&h0, *(uint32_t*)&h1);
    }
}

// ---------------------------------------------------------------------------
// FP16 mma.sync GEMM, 2 CTAs/SM: C[M,N] = A[M,K] @ B[N,K]^T.
// Block 128x128, BK=64, 8 warps each 64x32, 3-stage cp.async pipeline,
// one __syncthreads per k-iter. SMEM rows 144B (36 words), conflict-free.
// EPI: 0 none, 1 +Aux, 2 silu, 3 *Aux.  OUT16: __half out else float.
// ---------------------------------------------------------------------------
constexpr int BM = 128, BN = 128, BK = 64;
constexpr int ROW_W = 36;                          // words per smem row (144B)
constexpr int A_WORDS = BM * ROW_W;                // 4608
constexpr int B_WORDS = BN * ROW_W;                // 4608
constexpr int STAGE_WORDS = A_WORDS + B_WORDS;     // 9216 (36864 B)
constexpr int GEMM_SMEM = 3 * STAGE_WORDS * 4;     // 110592 bytes -> 2 CTAs/SM

__device__ __forceinline__ void issue_stage(uint32_t sA, uint32_t sB,
                                            const __half* __restrict__ Ab,
                                            const __half* __restrict__ Bb,
                                            int kt, int Kdim, int tid) {
    const size_t ko = (size_t)kt * BK;
#pragma unroll
    for (int i = 0; i < 4; i++) {
        int idx = tid + 256 * i;
        int row = idx >> 3, ch = idx & 7;
        cp_async16(sA + row * 144 + ch * 16, Ab + (size_t)row * Kdim + ko + ch * 8);
    }
#pragma unroll
    for (int i = 0; i < 4; i++) {
        int idx = tid + 256 * i;
        int row = idx >> 3, ch = idx & 7;
        cp_async16(sB + row * 144 + ch * 16, Bb + (size_t)row * Kdim + ko + ch * 8);
    }
}

template <int EPI, bool OUT16>
__global__ __launch_bounds__(256, 2) void gemm_h(const __half* __restrict__ A,
                                                 const __half* __restrict__ Bm,
                                                 void* __restrict__ Cv,
                                                 const float* __restrict__ Aux,
                                                 int Ndim, int Kdim) {
    const uint32_t sbase = smem_u32(dynsmem);
    const int tid = threadIdx.x;
    const int wid = tid >> 5, lane = tid & 31;
    const int r = lane >> 2, c = lane & 3;
    const int m0 = blockIdx.y * BM;
    const int n0 = blockIdx.x * BN;
    const int wm = (wid & 1) * 64;
    const int wn = (wid >> 1) * 32;

    const __half* Ab = A + (size_t)m0 * Kdim;
    const __half* Bb = Bm + (size_t)n0 * Kdim;
    const int KT = Kdim / BK;

    const uint32_t a_off = ((wm + (lane & 15)) * ROW_W + (lane >> 4) * 4) * 4;
    const uint32_t b_off = ((wn + ((lane & 16) >> 1) + (lane & 7)) * ROW_W
                            + ((lane >> 3) & 1) * 4) * 4;

    float acc[4][4][4];
#pragma unroll
    for (int mb = 0; mb < 4; mb++)
#pragma unroll
        for (int nb = 0; nb < 4; nb++)
#pragma unroll
            for (int q = 0; q < 4; q++) acc[mb][nb][q] = 0.f;

    // Prologue: fill stages 0,1
#pragma unroll
    for (int s = 0; s < 2; s++) {
        uint32_t sA = sbase + s * STAGE_WORDS * 4;
        issue_stage(sA, sA + A_WORDS * 4, Ab, Bb, s, Kdim, tid);
        cp_commit();
    }

    int stage = 0;
    for (int kt = 0; kt < KT; kt++) {
        cp_wait1();
        __syncthreads();
        // Refill stage (kt+2)%3: its last readers (iter kt-1) are past this barrier.
        if (kt + 2 < KT) {
            int fs = stage + 2; if (fs >= 3) fs -= 3;
            uint32_t sA = sbase + fs * STAGE_WORDS * 4;
            issue_stage(sA, sA + A_WORDS * 4, Ab, Bb, kt + 2, Kdim, tid);
        }
        cp_commit();

        const uint32_t sA = sbase + stage * STAGE_WORDS * 4;
        const uint32_t sB = sA + A_WORDS * 4;
#pragma unroll
        for (int ks = 0; ks < 4; ks++) {
            uint32_t af[4][4], bf[4][2];
#pragma unroll
            for (int mb = 0; mb < 4; mb++)
                ldsm_x4(af[mb][0], af[mb][1], af[mb][2], af[mb][3],
                        sA + a_off + mb * (16 * ROW_W * 4) + ks * 32);
#pragma unroll
            for (int nb2 = 0; nb2 < 2; nb2++)
                ldsm_x4(bf[2 * nb2][0], bf[2 * nb2][1], bf[2 * nb2 + 1][0], bf[2 * nb2 + 1][1],
                        sB + b_off + nb2 * (16 * ROW_W * 4) + ks * 32);
#pragma unroll
            for (int mb = 0; mb < 4; mb++)
#pragma unroll
                for (int nb = 0; nb < 4; nb++)
                    mma_f16(acc[mb][nb], af[mb], bf[nb]);
        }
        if (++stage == 3) stage = 0;
    }

    // Epilogue
#pragma unroll
    for (int mb = 0; mb < 4; mb++) {
#pragma unroll
        for (int nb = 0; nb < 4; nb++) {
            int row0 = m0 + wm + mb * 16 + r;
            int col = n0 + wn + nb * 8 + c * 2;
#pragma unroll
            for (int half = 0; half < 2; half++) {
                size_t off = (size_t)(row0 + half * 8) * Ndim + col;
                float v0 = acc[mb][nb][half * 2 + 0];
                float v1 = acc[mb][nb][half * 2 + 1];
                if (EPI == 1 || EPI == 3) {
                    float2 a2 = *(const float2*)(Aux + off);
                    if (EPI == 1) { v0 += a2.x; v1 += a2.y; }
                    else          { v0 *= a2.x; v1 *= a2.y; }
                }
                if (EPI == 2) {
                    v0 = v0 / (1.f + expf(-v0));
                    v1 = v1 / (1.f + expf(-v1));
                }
                if (OUT16) {
                    __half2 hv = __floats2half2_rn(v0, v1);
                    *(uint32_t*)((__half*)Cv + off) = *(uint32_t*)&hv;
                } else {
                    *(float2*)((float*)Cv + off) = make_float2(v0, v1);
                }
            }
        }
    }
}

// ---------------------------------------------------------------------------
// RMSNorm: one block per row, fp16 output
// ---------------------------------------------------------------------------
__global__ __launch_bounds__(256) void rmsnorm_kernel(const float* __restrict__ x,
                                                      const float* __restrict__ w,
                                                      __half* __restrict__ out) {
    int row = blockIdx.x;
    int t = threadIdx.x;
    const float4* xr = (const float4*)(x + (size_t)row * kD);
    float4 v0 = xr[t];
    float4 v1 = xr[t + 256];
    float s = v0.x * v0.x + v0.y * v0.y + v0.z * v0.z + v0.w * v0.w
            + v1.x * v1.x + v1.y * v1.y + v1.z * v1.z + v1.w * v1.w;
#pragma unroll
    for (int o = 16; o > 0; o >>= 1) s += __shfl_xor_sync(0xffffffffu, s, o);

    __shared__ float red[8];
    __shared__ float rtot;
    int wid = t >> 5, lane = t & 31;
    if (lane == 0) red[wid] = s;
    __syncthreads();
    if (t == 0) {
        float tot = 0.f;
#pragma unroll
        for (int i = 0; i < 8; i++) tot += red[i];
        rtot = rsqrtf(tot * (1.0f / kD) + 1e-6f);
    }
    __syncthreads();
    float r = rtot;

    const float4* wv = (const float4*)w;
    float4 w0 = wv[t], w1 = wv[t + 256];
    __half2 h0 = __floats2half2_rn(v0.x * r * w0.x, v0.y * r * w0.y);
    __half2 h1 = __floats2half2_rn(v0.z * r * w0.z, v0.w * r * w0.w);
    __half2 h2 = __floats2half2_rn(v1.x * r * w1.x, v1.y * r * w1.y);
    __half2 h3 = __floats2half2_rn(v1.z * r * w1.z, v1.w * r * w1.w);
    uint2* ov = (uint2*)(out + (size_t)row * kD);
    ov[t] = make_uint2(*(uint32_t*)&h0, *(uint32_t*)&h1);
    ov[t + 256] = make_uint2(*(uint32_t*)&h2, *(uint32_t*)&h3);
}

// ---------------------------------------------------------------------------
// Tensor-core flash attention (fp16 MMA, fp32 softmax/accum, causal).
// ---------------------------------------------------------------------------
constexpr int AQ_W = 68;
constexpr int PS_W = 65;
constexpr int PH_W = 36;
constexpr int OFF_Q  = 0;
constexpr int OFF_K  = OFF_Q + 64 * AQ_W;
constexpr int OFF_V  = OFF_K + 64 * AQ_W;
constexpr int OFF_PS = OFF_V + 64 * AQ_W;
constexpr int OFF_PH = OFF_PS + 64 * PS_W;
constexpr int OFF_M  = OFF_PH + 64 * PH_W;
constexpr int OFF_L  = OFF_M + 64;
constexpr int OFF_C  = OFF_L + 64;
constexpr int ATTN_SMEM = (OFF_C + 64) * 4;

__global__ __launch_bounds__(256, 2) void attn_kernel(const __half* __restrict__ qkv,
                                                      __half* __restrict__ o_out) {
    uint32_t* smw = (uint32_t*)dynsmem;
    const uint32_t sb = smem_u32(smw);
    float* ps = (float*)smw + OFF_PS;
    float* mrow = (float*)smw + OFF_M;
    float* lrow = (float*)smw + OFF_L;
    float* crow = (float*)smw + OFF_C;

    const int t = threadIdx.x, wid = t >> 5, lane = t & 31;
    const int q0 = blockIdx.x * 64, h = blockIdx.y, b = blockIdx.z;
    const float scale = 0.08838834764831845f;

    const __half* base = qkv + ((size_t)b * kL) * (3 * kD) + h * kHD;

#pragma unroll
    for (int i = 0; i < 4; i++) {
        int idx = t + 256 * i;
        int row = idx >> 4, ch = idx & 15;
        *(uint4*)(smw + OFF_Q + row * AQ_W + ch * 4) =
            *(const uint4*)(base + (size_t)(q0 + row) * (3 * kD) + ch * 8);
    }
    if (t < 64) { mrow[t] = -1e30f; lrow[t] = 0.f; }

    const int wr  = (wid & 3) * 16;
    const int wcs = (wid >> 2) * 32;
    const int wco = (wid >> 2) * 64;
    const int l15 = lane & 15, l7 = lane & 7;

    const uint32_t qa = sb + (OFF_Q + (wr + l15) * AQ_W + (lane >> 4) * 4) * 4;
    const uint32_t ka = sb + (OFF_K + (wcs + ((lane & 16) >> 1) + l7) * AQ_W
                              + ((lane >> 3) & 1) * 4) * 4;
    const uint32_t pa = sb + (OFF_PH + (wr + l15) * PH_W + (lane >> 4) * 4) * 4;
    const uint32_t va = sb + (OFF_V + ((lane & 8) + l7) * AQ_W) * 4
                        + (wco + ((lane & 16) >> 1)) * 2;

    float oacc[8][4];
#pragma unroll
    for (int nb = 0; nb < 8; nb++)
#pragma unroll
        for (int q = 0; q < 4; q++) oacc[nb][q] = 0.f;

    const int rS = wr + (lane >> 2);
    const int cS = wcs + (lane & 3) * 2;
    const int nkb = blockIdx.x + 1;

    for (int kb = 0; kb < nkb; kb++) {
        const int k0 = kb * 64;
        __syncthreads();
#pragma unroll
        for (int i = 0; i < 4; i++) {
            int idx = t + 256 * i;
            int row = idx >> 4, ch = idx & 15;
            const __half* kr = base + (size_t)(k0 + row) * (3 * kD) + kD + ch * 8;
            *(uint4*)(smw + OFF_K + row * AQ_W + ch * 4) = *(const uint4*)(kr);
            *(uint4*)(smw + OFF_V + row * AQ_W + ch * 4) = *(const uint4*)(kr + kD);
        }
        __syncthreads();

        float sacc[4][4];
#pragma unroll
        for (int nb = 0; nb < 4; nb++)
#pragma unroll
            for (int q = 0; q < 4; q++) sacc[nb][q] = 0.f;
#pragma unroll
        for (int ks = 0; ks < 8; ks++) {
            uint32_t af[4], bf[4][2];
            ldsm_x4(af[0], af[1], af[2], af[3], qa + ks * 32);
            ldsm_x4(bf[0][0], bf[0][1], bf[1][0], bf[1][1], ka + ks * 32);
            ldsm_x4(bf[2][0], bf[2][1], bf[3][0], bf[3][1],
                    ka + 16 * AQ_W * 4 + ks * 32);
#pragma unroll
            for (int nb = 0; nb < 4; nb++) mma_f16(sacc[nb], af, bf[nb]);
        }

        const bool diag = (kb == nkb - 1);
#pragma unroll
        for (int nb = 0; nb < 4; nb++) {
            int col = cS + nb * 8;
            float v0 = sacc[nb][0] * scale, v1 = sacc[nb][1] * scale;
            float v2 = sacc[nb][2] * scale, v3 = sacc[nb][3] * scale;
            if (diag) {
                if (k0 + col > q0 + rS) v0 = -1e30f;
                if (k0 + col + 1 > q0 + rS) v1 = -1e30f;
                if (k0 + col > q0 + rS + 8) v2 = -1e30f;
                if (k0 + col + 1 > q0 + rS + 8) v3 = -1e30f;
            }
            ps[rS * PS_W + col] = v0; ps[rS * PS_W + col + 1] = v1;
            ps[(rS + 8) * PS_W + col] = v2; ps[(rS + 8) * PS_W + col + 1] = v3;
        }
        __syncthreads();

        if (t < 64) {
            float mo = mrow[t], mx = mo;
            const float* pr = ps + t * PS_W;
            for (int j = 0; j < 64; j++) mx = fmaxf(mx, pr[j]);
            float corr = expf(mo - mx), sum = 0.f;
            uint32_t* phr = smw + OFF_PH + t * PH_W;
            for (int j = 0; j < 64; j += 2) {
                float p0 = expf(pr[j] - mx);
                float p1 = expf(pr[j + 1] - mx);
                sum += p0 + p1;
                __half2 hp = __floats2half2_rn(p0, p1);
                phr[j >> 1] = *(uint32_t*)&hp;
            }
            lrow[t] = lrow[t] * corr + sum;
            mrow[t] = mx;
            crow[t] = corr;
        }
        __syncthreads();

        float corr0 = crow[rS], corr1 = crow[rS + 8];
#pragma unroll
        for (int nb = 0; nb < 8; nb++) {
            oacc[nb][0] *= corr0; oacc[nb][1] *= corr0;
            oacc[nb][2] *= corr1; oacc[nb][3] *= corr1;
        }

#pragma unroll
        for (int ks = 0; ks < 4; ks++) {
            uint32_t af[4], bv[8][2];
            ldsm_x4(af[0], af[1], af[2], af[3], pa + ks * 32);
#pragma unroll
            for (int nb2 = 0; nb2 < 4; nb2++)
                ldsm_x4_t(bv[2 * nb2][0], bv[2 * nb2][1],
                          bv[2 * nb2 + 1][0], bv[2 * nb2 + 1][1],
                          va + ks * (16 * AQ_W * 4) + nb2 * 32);
#pragma unroll
            for (int nb = 0; nb < 8; nb++) mma_f16(oacc[nb], af, bv[nb]);
        }
    }

    float inv0 = 1.f / lrow[rS];
    float inv1 = 1.f / lrow[rS + 8];
#pragma unroll
    for (int nb = 0; nb < 8; nb++) {
        int col = wco + nb * 8 + (lane & 3) * 2;
        __half* d0 = o_out + ((size_t)(b * kL + q0 + rS)) * kD + h * kHD + col;
        __half* d1 = d0 + (size_t)8 * kD;
        __half2 h01 = __floats2half2_rn(oacc[nb][0] * inv0, oacc[nb][1] * inv0);
        __half2 h23 = __floats2half2_rn(oacc[nb][2] * inv1, oacc[nb][3] * inv1);
        *(uint32_t*)d0 = *(uint32_t*)&h01;
        *(uint32_t*)d1 = *(uint32_t*)&h23;
    }
}

// ---------------------------------------------------------------------------
// Launch
// ---------------------------------------------------------------------------
extern "C" void kernel_launch(void* const* d_in, const int* in_sizes, int n_in,
                              void* d_out, int out_size) {
    (void)in_sizes; (void)n_in; (void)out_size;
    const float* x       = (const float*)d_in[0];
    const float* norm1_w = (const float*)d_in[2];
    const float* qkv_w   = (const float*)d_in[3];
    const float* out_w   = (const float*)d_in[4];
    const float* norm2_w = (const float*)d_in[5];
    const float* gate_w  = (const float*)d_in[6];
    const float* up_w    = (const float*)d_in[7];
    const float* down_w  = (const float*)d_in[8];
    float* out = (float*)d_out;

    float *x2, *gate;
    __half *qkv16, *h16, *attn16, *act16, *w16;
    cudaGetSymbolAddress((void**)&x2, g_x2);
    cudaGetSymbolAddress((void**)&gate, g_gate);
    cudaGetSymbolAddress((void**)&qkv16, g_qkv16);
    cudaGetSymbolAddress((void**)&h16, g_h16);
    cudaGetSymbolAddress((void**)&attn16, g_attn16);
    cudaGetSymbolAddress((void**)&act16, g_act16);
    cudaGetSymbolAddress((void**)&w16, g_w16);

    cudaFuncSetAttribute((const void*)attn_kernel,
                         cudaFuncAttributeMaxDynamicSharedMemorySize, ATTN_SMEM);
    cudaFuncSetAttribute((const void*)gemm_h<0, true>,
                         cudaFuncAttributeMaxDynamicSharedMemorySize, GEMM_SMEM);
    cudaFuncSetAttribute((const void*)gemm_h<1, false>,
                         cudaFuncAttributeMaxDynamicSharedMemorySize, GEMM_SMEM);
    cudaFuncSetAttribute((const void*)gemm_h<2, false>,
                         cudaFuncAttributeMaxDynamicSharedMemorySize, GEMM_SMEM);
    cudaFuncSetAttribute((const void*)gemm_h<3, true>,
                         cudaFuncAttributeMaxDynamicSharedMemorySize, GEMM_SMEM);

    // 0) Convert weights to fp16
    cvt_f16_kernel<<<(int)((W_OUT - W_QKV) / 4 + 255) / 256, 256>>>(
        (const float4*)qkv_w, (uint2*)(w16 + W_QKV), (int)((W_OUT - W_QKV) / 4));
    cvt_f16_kernel<<<(int)((W_GATE - W_OUT) / 4 + 255) / 256, 256>>>(
        (const float4*)out_w, (uint2*)(w16 + W_OUT), (int)((W_GATE - W_OUT) / 4));
    cvt_f16_kernel<<<(int)((W_UP - W_GATE) / 4 + 255) / 256, 256>>>(
        (const float4*)gate_w, (uint2*)(w16 + W_GATE), (int)((W_UP - W_GATE) / 4));
    cvt_f16_kernel<<<(int)((W_DOWN - W_UP) / 4 + 255) / 256, 256>>>(
        (const float4*)up_w, (uint2*)(w16 + W_UP), (int)((W_DOWN - W_UP) / 4));
    cvt_f16_kernel<<<(int)((W_TOTAL - W_DOWN) / 4 + 255) / 256, 256>>>(
        (const float4*)down_w, (uint2*)(w16 + W_DOWN), (int)((W_TOTAL - W_DOWN) / 4));

    // 1) h16 = rmsnorm(x, norm1_w)
    rmsnorm_kernel<<<kM, 256>>>(x, norm1_w, h16);
    // 2) qkv16 = h16 @ qkv_w16^T
    gemm_h<0, true><<<dim3(3 * kD / BN, kM / BM), 256, GEMM_SMEM>>>(
        h16, w16 + W_QKV, qkv16, nullptr, 3 * kD, kD);
    // 3) tensor-core attention
    attn_kernel<<<dim3(kL / 64, kH, kB), 256, ATTN_SMEM>>>(qkv16, attn16);
    // 4) x2 = attn16 @ out_w16^T + x
    gemm_h<1, false><<<dim3(kD / BN, kM / BM), 256, GEMM_SMEM>>>(
        attn16, w16 + W_OUT, x2, x, kD, kD);
    // 5) h16 = rmsnorm(x2, norm2_w)
    rmsnorm_kernel<<<kM, 256>>>(x2, norm2_w, h16);
    // 6) gate = silu(h16 @ gate_w16^T)
    gemm_h<2, false><<<dim3(kFF / BN, kM / BM), 256, GEMM_SMEM>>>(
        h16, w16 + W_GATE, gate, nullptr, kFF, kD);
    // 7) act16 = (h16 @ up_w16^T) * gate
    gemm_h<3, true><<<dim3(kFF / BN, kM / BM), 256, GEMM_SMEM>>>(
        h16, w16 + W_UP, act16, gate, kFF, kD);
    // 8) out = act16 @ down_w16^T + x2
    gemm_h<1, false><<<dim3(kD / BN, kM / BM), 256, GEMM_SMEM>>>(
        act16, w16 + W_DOWN, out, x2, kD, kFF);
}

// round 10
// speedup vs baseline: 7.6963x; 1.0371x over previous
#include <cuda_runtime.h>
#include <cuda_fp16.h>
#include <math.h>
#include <stdint.h>

// Problem constants
constexpr int kB  = 2;
constexpr int kL  = 2048;
constexpr int kD  = 2048;
constexpr int kH  = 16;
constexpr int kHD = 128;
constexpr int kFF = 8192;
constexpr int kM  = kB * kL;  // 4096 rows

// ---------------------------------------------------------------------------
// Scratch buffers (device globals — no allocation allowed)
// ---------------------------------------------------------------------------
__device__ float  g_x2[(size_t)kM * kD];
__device__ __half g_qkv16[(size_t)kM * 3 * kD];
__device__ __half g_h16[(size_t)kM * kD];
__device__ __half g_attn16[(size_t)kM * kD];
__device__ __half g_gate16[(size_t)kM * kFF];
__device__ __half g_act16[(size_t)kM * kFF];
constexpr size_t W_QKV  = 0;
constexpr size_t W_OUT  = (size_t)3 * kD * kD;
constexpr size_t W_GATE = W_OUT + (size_t)kD * kD;
constexpr size_t W_UP   = W_GATE + (size_t)kFF * kD;
constexpr size_t W_DOWN = W_UP + (size_t)kFF * kD;
constexpr size_t W_TOTAL = W_DOWN + (size_t)kD * kFF;
__device__ __half g_w16[W_TOTAL];

extern __shared__ char dynsmem[];

// ---------------------------------------------------------------------------
// PTX helpers
// ---------------------------------------------------------------------------
__device__ __forceinline__ void mma_f16(float* c, const uint32_t* a, const uint32_t* b) {
    asm volatile(
        "mma.sync.aligned.m16n8k16.row.col.f32.f16.f16.f32 "
        "{%0,%1,%2,%3}, {%4,%5,%6,%7}, {%8,%9}, {%0,%1,%2,%3};"
        : "+f"(c[0]), "+f"(c[1]), "+f"(c[2]), "+f"(c[3])
        : "r"(a[0]), "r"(a[1]), "r"(a[2]), "r"(a[3]), "r"(b[0]), "r"(b[1]));
}
__device__ __forceinline__ void ldsm_x4(uint32_t& r0, uint32_t& r1, uint32_t& r2,
                                        uint32_t& r3, uint32_t addr) {
    asm volatile("ldmatrix.sync.aligned.m8n8.x4.shared.b16 {%0,%1,%2,%3}, [%4];"
                 : "=r"(r0), "=r"(r1), "=r"(r2), "=r"(r3) : "r"(addr));
}
__device__ __forceinline__ void ldsm_x4_t(uint32_t& r0, uint32_t& r1, uint32_t& r2,
                                          uint32_t& r3, uint32_t addr) {
    asm volatile("ldmatrix.sync.aligned.m8n8.x4.trans.shared.b16 {%0,%1,%2,%3}, [%4];"
                 : "=r"(r0), "=r"(r1), "=r"(r2), "=r"(r3) : "r"(addr));
}
__device__ __forceinline__ void cp_async16(uint32_t smem_addr, const void* gmem) {
    asm volatile("cp.async.cg.shared.global [%0], [%1], 16;\n"
                 :: "r"(smem_addr), "l"(gmem));
}
__device__ __forceinline__ void cp_commit() {
    asm volatile("cp.async.commit_group;\n" ::: "memory");
}
__device__ __forceinline__ void cp_wait1() {
    asm volatile("cp.async.wait_group 1;\n" ::: "memory");
}
__device__ __forceinline__ uint32_t smem_u32(const void* p) {
    uint32_t a;
    asm("{ .reg .u64 t; cvta.to.shared.u64 t, %1; cvt.u32.u64 %0, t; }"
        : "=r"(a) : "l"(p));
    return a;
}

// ---------------------------------------------------------------------------
// Fused weight convert: fp32 -> fp16 for all 5 weight matrices in one launch
// ---------------------------------------------------------------------------
constexpr size_t F4_QKV  = W_OUT / 4;       // 3145728
constexpr size_t F4_OUT  = W_GATE / 4;      // 4194304
constexpr size_t F4_GATE = W_UP / 4;        // 8388608
constexpr size_t F4_UP   = W_DOWN / 4;      // 12582912
constexpr size_t F4_ALL  = W_TOTAL / 4;     // 16777216

__global__ __launch_bounds__(256) void cvt_all_kernel(const float4* __restrict__ qkv_w,
                                                      const float4* __restrict__ out_w,
                                                      const float4* __restrict__ gate_w,
                                                      const float4* __restrict__ up_w,
                                                      const float4* __restrict__ down_w,
                                                      uint2* __restrict__ out) {
    size_t i = (size_t)blockIdx.x * 256 + threadIdx.x;
    const float4* src;
    size_t base;
    if (i < F4_QKV)       { src = qkv_w;  base = 0; }
    else if (i < F4_OUT)  { src = out_w;  base = F4_QKV; }
    else if (i < F4_GATE) { src = gate_w; base = F4_OUT; }
    else if (i < F4_UP)   { src = up_w;   base = F4_GATE; }
    else                  { src = down_w; base = F4_UP; }
    float4 v = src[i - base];
    __half2 h0 = __floats2half2_rn(v.x, v.y);
    __half2 h1 = __floats2half2_rn(v.z, v.w);
    out[i] = make_uint2(*(uint32_t*)&h0, *(uint32_t*)&h1);
}

// ---------------------------------------------------------------------------
// FP16 mma.sync GEMM, 2 CTAs/SM: C[M,N] = A[M,K] @ B[N,K]^T.
// Block 128x128, BK=64, 8 warps each 64x32, 3-stage cp.async pipeline.
// EPI: 0 none, 1 +Aux(fp32), 2 silu, 3 *Aux(fp32), 4 *Aux(fp16).
// OUT16: __half out else float.
// ---------------------------------------------------------------------------
constexpr int BM = 128, BN = 128, BK = 64;
constexpr int ROW_W = 36;
constexpr int A_WORDS = BM * ROW_W;
constexpr int B_WORDS = BN * ROW_W;
constexpr int STAGE_WORDS = A_WORDS + B_WORDS;
constexpr int GEMM_SMEM = 3 * STAGE_WORDS * 4;     // 110592 bytes -> 2 CTAs/SM

__device__ __forceinline__ void issue_stage(uint32_t sA, uint32_t sB,
                                            const __half* __restrict__ Ab,
                                            const __half* __restrict__ Bb,
                                            int kt, int Kdim, int tid) {
    const size_t ko = (size_t)kt * BK;
#pragma unroll
    for (int i = 0; i < 4; i++) {
        int idx = tid + 256 * i;
        int row = idx >> 3, ch = idx & 7;
        cp_async16(sA + row * 144 + ch * 16, Ab + (size_t)row * Kdim + ko + ch * 8);
    }
#pragma unroll
    for (int i = 0; i < 4; i++) {
        int idx = tid + 256 * i;
        int row = idx >> 3, ch = idx & 7;
        cp_async16(sB + row * 144 + ch * 16, Bb + (size_t)row * Kdim + ko + ch * 8);
    }
}

template <int EPI, bool OUT16>
__global__ __launch_bounds__(256, 2) void gemm_h(const __half* __restrict__ A,
                                                 const __half* __restrict__ Bm,
                                                 void* __restrict__ Cv,
                                                 const void* __restrict__ AuxV,
                                                 int Ndim, int Kdim) {
    const uint32_t sbase = smem_u32(dynsmem);
    const int tid = threadIdx.x;
    const int wid = tid >> 5, lane = tid & 31;
    const int r = lane >> 2, c = lane & 3;
    const int m0 = blockIdx.y * BM;
    const int n0 = blockIdx.x * BN;
    const int wm = (wid & 1) * 64;
    const int wn = (wid >> 1) * 32;

    const __half* Ab = A + (size_t)m0 * Kdim;
    const __half* Bb = Bm + (size_t)n0 * Kdim;
    const int KT = Kdim / BK;

    const uint32_t a_off = ((wm + (lane & 15)) * ROW_W + (lane >> 4) * 4) * 4;
    const uint32_t b_off = ((wn + ((lane & 16) >> 1) + (lane & 7)) * ROW_W
                            + ((lane >> 3) & 1) * 4) * 4;

    float acc[4][4][4];
#pragma unroll
    for (int mb = 0; mb < 4; mb++)
#pragma unroll
        for (int nb = 0; nb < 4; nb++)
#pragma unroll
            for (int q = 0; q < 4; q++) acc[mb][nb][q] = 0.f;

#pragma unroll
    for (int s = 0; s < 2; s++) {
        uint32_t sA = sbase + s * STAGE_WORDS * 4;
        issue_stage(sA, sA + A_WORDS * 4, Ab, Bb, s, Kdim, tid);
        cp_commit();
    }

    int stage = 0;
    for (int kt = 0; kt < KT; kt++) {
        cp_wait1();
        __syncthreads();
        if (kt + 2 < KT) {
            int fs = stage + 2; if (fs >= 3) fs -= 3;
            uint32_t sA = sbase + fs * STAGE_WORDS * 4;
            issue_stage(sA, sA + A_WORDS * 4, Ab, Bb, kt + 2, Kdim, tid);
        }
        cp_commit();

        const uint32_t sA = sbase + stage * STAGE_WORDS * 4;
        const uint32_t sB = sA + A_WORDS * 4;
#pragma unroll
        for (int ks = 0; ks < 4; ks++) {
            uint32_t af[4][4], bf[4][2];
#pragma unroll
            for (int mb = 0; mb < 4; mb++)
                ldsm_x4(af[mb][0], af[mb][1], af[mb][2], af[mb][3],
                        sA + a_off + mb * (16 * ROW_W * 4) + ks * 32);
#pragma unroll
            for (int nb2 = 0; nb2 < 2; nb2++)
                ldsm_x4(bf[2 * nb2][0], bf[2 * nb2][1], bf[2 * nb2 + 1][0], bf[2 * nb2 + 1][1],
                        sB + b_off + nb2 * (16 * ROW_W * 4) + ks * 32);
#pragma unroll
            for (int mb = 0; mb < 4; mb++)
#pragma unroll
                for (int nb = 0; nb < 4; nb++)
                    mma_f16(acc[mb][nb], af[mb], bf[nb]);
        }
        if (++stage == 3) stage = 0;
    }

    // Epilogue
#pragma unroll
    for (int mb = 0; mb < 4; mb++) {
#pragma unroll
        for (int nb = 0; nb < 4; nb++) {
            int row0 = m0 + wm + mb * 16 + r;
            int col = n0 + wn + nb * 8 + c * 2;
#pragma unroll
            for (int half = 0; half < 2; half++) {
                size_t off = (size_t)(row0 + half * 8) * Ndim + col;
                float v0 = acc[mb][nb][half * 2 + 0];
                float v1 = acc[mb][nb][half * 2 + 1];
                if (EPI == 1 || EPI == 3) {
                    float2 a2 = *(const float2*)((const float*)AuxV + off);
                    if (EPI == 1) { v0 += a2.x; v1 += a2.y; }
                    else          { v0 *= a2.x; v1 *= a2.y; }
                }
                if (EPI == 4) {
                    __half2 ah = *(const __half2*)((const __half*)AuxV + off);
                    float2 a2 = __half22float2(ah);
                    v0 *= a2.x; v1 *= a2.y;
                }
                if (EPI == 2) {
                    v0 = v0 / (1.f + expf(-v0));
                    v1 = v1 / (1.f + expf(-v1));
                }
                if (OUT16) {
                    __half2 hv = __floats2half2_rn(v0, v1);
                    *(uint32_t*)((__half*)Cv + off) = *(uint32_t*)&hv;
                } else {
                    *(float2*)((float*)Cv + off) = make_float2(v0, v1);
                }
            }
        }
    }
}

// ---------------------------------------------------------------------------
// RMSNorm: one block per row, fp16 output
// ---------------------------------------------------------------------------
__global__ __launch_bounds__(256) void rmsnorm_kernel(const float* __restrict__ x,
                                                      const float* __restrict__ w,
                                                      __half* __restrict__ out) {
    int row = blockIdx.x;
    int t = threadIdx.x;
    const float4* xr = (const float4*)(x + (size_t)row * kD);
    float4 v0 = xr[t];
    float4 v1 = xr[t + 256];
    float s = v0.x * v0.x + v0.y * v0.y + v0.z * v0.z + v0.w * v0.w
            + v1.x * v1.x + v1.y * v1.y + v1.z * v1.z + v1.w * v1.w;
#pragma unroll
    for (int o = 16; o > 0; o >>= 1) s += __shfl_xor_sync(0xffffffffu, s, o);

    __shared__ float red[8];
    __shared__ float rtot;
    int wid = t >> 5, lane = t & 31;
    if (lane == 0) red[wid] = s;
    __syncthreads();
    if (t == 0) {
        float tot = 0.f;
#pragma unroll
        for (int i = 0; i < 8; i++) tot += red[i];
        rtot = rsqrtf(tot * (1.0f / kD) + 1e-6f);
    }
    __syncthreads();
    float r = rtot;

    const float4* wv = (const float4*)w;
    float4 w0 = wv[t], w1 = wv[t + 256];
    __half2 h0 = __floats2half2_rn(v0.x * r * w0.x, v0.y * r * w0.y);
    __half2 h1 = __floats2half2_rn(v0.z * r * w0.z, v0.w * r * w0.w);
    __half2 h2 = __floats2half2_rn(v1.x * r * w1.x, v1.y * r * w1.y);
    __half2 h3 = __floats2half2_rn(v1.z * r * w1.z, v1.w * r * w1.w);
    uint2* ov = (uint2*)(out + (size_t)row * kD);
    ov[t] = make_uint2(*(uint32_t*)&h0, *(uint32_t*)&h1);
    ov[t + 256] = make_uint2(*(uint32_t*)&h2, *(uint32_t*)&h3);
}

// ---------------------------------------------------------------------------
// Tensor-core flash attention (fp16 MMA, fp32 softmax/accum, causal).
// Softmax parallelized 4 threads/row.
// ---------------------------------------------------------------------------
constexpr int AQ_W = 68;
constexpr int PS_W = 65;
constexpr int PH_W = 36;
constexpr int OFF_Q  = 0;
constexpr int OFF_K  = OFF_Q + 64 * AQ_W;
constexpr int OFF_V  = OFF_K + 64 * AQ_W;
constexpr int OFF_PS = OFF_V + 64 * AQ_W;
constexpr int OFF_PH = OFF_PS + 64 * PS_W;
constexpr int OFF_M  = OFF_PH + 64 * PH_W;
constexpr int OFF_L  = OFF_M + 64;
constexpr int OFF_C  = OFF_L + 64;
constexpr int ATTN_SMEM = (OFF_C + 64) * 4;

__global__ __launch_bounds__(256, 2) void attn_kernel(const __half* __restrict__ qkv,
                                                      __half* __restrict__ o_out) {
    uint32_t* smw = (uint32_t*)dynsmem;
    const uint32_t sb = smem_u32(smw);
    float* ps = (float*)smw + OFF_PS;
    float* mrow = (float*)smw + OFF_M;
    float* lrow = (float*)smw + OFF_L;
    float* crow = (float*)smw + OFF_C;

    const int t = threadIdx.x, wid = t >> 5, lane = t & 31;
    const int q0 = blockIdx.x * 64, h = blockIdx.y, b = blockIdx.z;
    const float scale = 0.08838834764831845f;

    const __half* base = qkv + ((size_t)b * kL) * (3 * kD) + h * kHD;

#pragma unroll
    for (int i = 0; i < 4; i++) {
        int idx = t + 256 * i;
        int row = idx >> 4, ch = idx & 15;
        *(uint4*)(smw + OFF_Q + row * AQ_W + ch * 4) =
            *(const uint4*)(base + (size_t)(q0 + row) * (3 * kD) + ch * 8);
    }
    if (t < 64) { mrow[t] = -1e30f; lrow[t] = 0.f; }

    const int wr  = (wid & 3) * 16;
    const int wcs = (wid >> 2) * 32;
    const int wco = (wid >> 2) * 64;
    const int l15 = lane & 15, l7 = lane & 7;

    const uint32_t qa = sb + (OFF_Q + (wr + l15) * AQ_W + (lane >> 4) * 4) * 4;
    const uint32_t ka = sb + (OFF_K + (wcs + ((lane & 16) >> 1) + l7) * AQ_W
                              + ((lane >> 3) & 1) * 4) * 4;
    const uint32_t pa = sb + (OFF_PH + (wr + l15) * PH_W + (lane >> 4) * 4) * 4;
    const uint32_t va = sb + (OFF_V + ((lane & 8) + l7) * AQ_W) * 4
                        + (wco + ((lane & 16) >> 1)) * 2;

    float oacc[8][4];
#pragma unroll
    for (int nb = 0; nb < 8; nb++)
#pragma unroll
        for (int q = 0; q < 4; q++) oacc[nb][q] = 0.f;

    const int rS = wr + (lane >> 2);
    const int cS = wcs + (lane & 3) * 2;
    const int nkb = blockIdx.x + 1;

    // Softmax assignment: 4 threads per row
    const int smRow = t >> 2;          // 0..63
    const int smPart = (t & 3) * 16;   // col start

    for (int kb = 0; kb < nkb; kb++) {
        const int k0 = kb * 64;
        __syncthreads();
#pragma unroll
        for (int i = 0; i < 4; i++) {
            int idx = t + 256 * i;
            int row = idx >> 4, ch = idx & 15;
            const __half* kr = base + (size_t)(k0 + row) * (3 * kD) + kD + ch * 8;
            *(uint4*)(smw + OFF_K + row * AQ_W + ch * 4) = *(const uint4*)(kr);
            *(uint4*)(smw + OFF_V + row * AQ_W + ch * 4) = *(const uint4*)(kr + kD);
        }
        __syncthreads();

        float sacc[4][4];
#pragma unroll
        for (int nb = 0; nb < 4; nb++)
#pragma unroll
            for (int q = 0; q < 4; q++) sacc[nb][q] = 0.f;
#pragma unroll
        for (int ks = 0; ks < 8; ks++) {
            uint32_t af[4], bf[4][2];
            ldsm_x4(af[0], af[1], af[2], af[3], qa + ks * 32);
            ldsm_x4(bf[0][0], bf[0][1], bf[1][0], bf[1][1], ka + ks * 32);
            ldsm_x4(bf[2][0], bf[2][1], bf[3][0], bf[3][1],
                    ka + 16 * AQ_W * 4 + ks * 32);
#pragma unroll
            for (int nb = 0; nb < 4; nb++) mma_f16(sacc[nb], af, bf[nb]);
        }

        const bool diag = (kb == nkb - 1);
#pragma unroll
        for (int nb = 0; nb < 4; nb++) {
            int col = cS + nb * 8;
            float v0 = sacc[nb][0] * scale, v1 = sacc[nb][1] * scale;
            float v2 = sacc[nb][2] * scale, v3 = sacc[nb][3] * scale;
            if (diag) {
                if (k0 + col > q0 + rS) v0 = -1e30f;
                if (k0 + col + 1 > q0 + rS) v1 = -1e30f;
                if (k0 + col > q0 + rS + 8) v2 = -1e30f;
                if (k0 + col + 1 > q0 + rS + 8) v3 = -1e30f;
            }
            ps[rS * PS_W + col] = v0; ps[rS * PS_W + col + 1] = v1;
            ps[(rS + 8) * PS_W + col] = v2; ps[(rS + 8) * PS_W + col + 1] = v3;
        }
        __syncthreads();

        // Parallel online softmax: 4 threads per row, 16 cols each
        {
            const float* pr = ps + smRow * PS_W + smPart;
            float mx = -1e30f;
#pragma unroll
            for (int j = 0; j < 16; j++) mx = fmaxf(mx, pr[j]);
            mx = fmaxf(mx, __shfl_xor_sync(0xffffffffu, mx, 1));
            mx = fmaxf(mx, __shfl_xor_sync(0xffffffffu, mx, 2));
            float mo = mrow[smRow];
            mx = fmaxf(mx, mo);
            float sum = 0.f;
            uint32_t* phr = smw + OFF_PH + smRow * PH_W + (smPart >> 1);
#pragma unroll
            for (int j = 0; j < 16; j += 2) {
                float p0 = expf(pr[j] - mx);
                float p1 = expf(pr[j + 1] - mx);
                sum += p0 + p1;
                __half2 hp = __floats2half2_rn(p0, p1);
                phr[j >> 1] = *(uint32_t*)&hp;
            }
            sum += __shfl_xor_sync(0xffffffffu, sum, 1);
            sum += __shfl_xor_sync(0xffffffffu, sum, 2);
            if ((t & 3) == 0) {
                float corr = expf(mo - mx);
                lrow[smRow] = lrow[smRow] * corr + sum;
                mrow[smRow] = mx;
                crow[smRow] = corr;
            }
        }
        __syncthreads();

        float corr0 = crow[rS], corr1 = crow[rS + 8];
#pragma unroll
        for (int nb = 0; nb < 8; nb++) {
            oacc[nb][0] *= corr0; oacc[nb][1] *= corr0;
            oacc[nb][2] *= corr1; oacc[nb][3] *= corr1;
        }

#pragma unroll
        for (int ks = 0; ks < 4; ks++) {
            uint32_t af[4], bv[8][2];
            ldsm_x4(af[0], af[1], af[2], af[3], pa + ks * 32);
#pragma unroll
            for (int nb2 = 0; nb2 < 4; nb2++)
                ldsm_x4_t(bv[2 * nb2][0], bv[2 * nb2][1],
                          bv[2 * nb2 + 1][0], bv[2 * nb2 + 1][1],
                          va + ks * (16 * AQ_W * 4) + nb2 * 32);
#pragma unroll
            for (int nb = 0; nb < 8; nb++) mma_f16(oacc[nb], af, bv[nb]);
        }
    }

    float inv0 = 1.f / lrow[rS];
    float inv1 = 1.f / lrow[rS + 8];
#pragma unroll
    for (int nb = 0; nb < 8; nb++) {
        int col = wco + nb * 8 + (lane & 3) * 2;
        __half* d0 = o_out + ((size_t)(b * kL + q0 + rS)) * kD + h * kHD + col;
        __half* d1 = d0 + (size_t)8 * kD;
        __half2 h01 = __floats2half2_rn(oacc[nb][0] * inv0, oacc[nb][1] * inv0);
        __half2 h23 = __floats2half2_rn(oacc[nb][2] * inv1, oacc[nb][3] * inv1);
        *(uint32_t*)d0 = *(uint32_t*)&h01;
        *(uint32_t*)d1 = *(uint32_t*)&h23;
    }
}

// ---------------------------------------------------------------------------
// Launch
// ---------------------------------------------------------------------------
extern "C" void kernel_launch(void* const* d_in, const int* in_sizes, int n_in,
                              void* d_out, int out_size) {
    (void)in_sizes; (void)n_in; (void)out_size;
    const float* x       = (const float*)d_in[0];
    const float* norm1_w = (const float*)d_in[2];
    const float* qkv_w   = (const float*)d_in[3];
    const float* out_w   = (const float*)d_in[4];
    const float* norm2_w = (const float*)d_in[5];
    const float* gate_w  = (const float*)d_in[6];
    const float* up_w    = (const float*)d_in[7];
    const float* down_w  = (const float*)d_in[8];
    float* out = (float*)d_out;

    float* x2;
    __half *qkv16, *h16, *attn16, *gate16, *act16, *w16;
    cudaGetSymbolAddress((void**)&x2, g_x2);
    cudaGetSymbolAddress((void**)&qkv16, g_qkv16);
    cudaGetSymbolAddress((void**)&h16, g_h16);
    cudaGetSymbolAddress((void**)&attn16, g_attn16);
    cudaGetSymbolAddress((void**)&gate16, g_gate16);
    cudaGetSymbolAddress((void**)&act16, g_act16);
    cudaGetSymbolAddress((void**)&w16, g_w16);

    cudaFuncSetAttribute((const void*)attn_kernel,
                         cudaFuncAttributeMaxDynamicSharedMemorySize, ATTN_SMEM);
    cudaFuncSetAttribute((const void*)gemm_h<0, true>,
                         cudaFuncAttributeMaxDynamicSharedMemorySize, GEMM_SMEM);
    cudaFuncSetAttribute((const void*)gemm_h<1, false>,
                         cudaFuncAttributeMaxDynamicSharedMemorySize, GEMM_SMEM);
    cudaFuncSetAttribute((const void*)gemm_h<2, true>,
                         cudaFuncAttributeMaxDynamicSharedMemorySize, GEMM_SMEM);
    cudaFuncSetAttribute((const void*)gemm_h<4, true>,
                         cudaFuncAttributeMaxDynamicSharedMemorySize, GEMM_SMEM);

    // 0) Convert all weights to fp16 (one launch)
    cvt_all_kernel<<<(int)(F4_ALL / 256), 256>>>(
        (const float4*)qkv_w, (const float4*)out_w, (const float4*)gate_w,
        (const float4*)up_w, (const float4*)down_w, (uint2*)w16);

    // 1) h16 = rmsnorm(x, norm1_w)
    rmsnorm_kernel<<<kM, 256>>>(x, norm1_w, h16);
    // 2) qkv16 = h16 @ qkv_w16^T
    gemm_h<0, true><<<dim3(3 * kD / BN, kM / BM), 256, GEMM_SMEM>>>(
        h16, w16 + W_QKV, qkv16, nullptr, 3 * kD, kD);
    // 3) tensor-core attention
    attn_kernel<<<dim3(kL / 64, kH, kB), 256, ATTN_SMEM>>>(qkv16, attn16);
    // 4) x2 = attn16 @ out_w16^T + x
    gemm_h<1, false><<<dim3(kD / BN, kM / BM), 256, GEMM_SMEM>>>(
        attn16, w16 + W_OUT, x2, x, kD, kD);
    // 5) h16 = rmsnorm(x2, norm2_w)
    rmsnorm_kernel<<<kM, 256>>>(x2, norm2_w, h16);
    // 6) gate16 = silu(h16 @ gate_w16^T)  (fp16)
    gemm_h<2, true><<<dim3(kFF / BN, kM / BM), 256, GEMM_SMEM>>>(
        h16, w16 + W_GATE, gate16, nullptr, kFF, kD);
    // 7) act16 = (h16 @ up_w16^T) * gate16  (fp16 aux)
    gemm_h<4, true><<<dim3(kFF / BN, kM / BM), 256, GEMM_SMEM>>>(
        h16, w16 + W_UP, act16, gate16, kFF, kD);
    // 8) out = act16 @ down_w16^T + x2
    gemm_h<1, false><<<dim3(kD / BN, kM / BM), 256, GEMM_SMEM>>>(
        act16, w16 + W_DOWN, out, x2, kD, kFF);
}

// round 11
// speedup vs baseline: 8.2087x; 1.0666x over previous
#include <cuda_runtime.h>
#include <cuda_fp16.h>
#include <math.h>
#include <stdint.h>

// Problem constants
constexpr int kB  = 2;
constexpr int kL  = 2048;
constexpr int kD  = 2048;
constexpr int kH  = 16;
constexpr int kHD = 128;
constexpr int kFF = 8192;
constexpr int kM  = kB * kL;  // 4096 rows

// ---------------------------------------------------------------------------
// Scratch buffers (device globals — no allocation allowed)
// ---------------------------------------------------------------------------
__device__ float  g_x2[(size_t)kM * kD];
__device__ __half g_qkv16[(size_t)kM * 3 * kD];
__device__ __half g_h16[(size_t)kM * kD];
__device__ __half g_attn16[(size_t)kM * kD];
__device__ __half g_gate16[(size_t)kM * kFF];
__device__ __half g_act16[(size_t)kM * kFF];
constexpr size_t W_QKV  = 0;
constexpr size_t W_OUT  = (size_t)3 * kD * kD;
constexpr size_t W_GATE = W_OUT + (size_t)kD * kD;
constexpr size_t W_UP   = W_GATE + (size_t)kFF * kD;
constexpr size_t W_DOWN = W_UP + (size_t)kFF * kD;
constexpr size_t W_TOTAL = W_DOWN + (size_t)kD * kFF;
__device__ __half g_w16[W_TOTAL];

extern __shared__ char dynsmem[];

// ---------------------------------------------------------------------------
// PTX helpers
// ---------------------------------------------------------------------------
__device__ __forceinline__ void mma_f16(float* c, const uint32_t* a, const uint32_t* b) {
    asm volatile(
        "mma.sync.aligned.m16n8k16.row.col.f32.f16.f16.f32 "
        "{%0,%1,%2,%3}, {%4,%5,%6,%7}, {%8,%9}, {%0,%1,%2,%3};"
        : "+f"(c[0]), "+f"(c[1]), "+f"(c[2]), "+f"(c[3])
        : "r"(a[0]), "r"(a[1]), "r"(a[2]), "r"(a[3]), "r"(b[0]), "r"(b[1]));
}
__device__ __forceinline__ void ldsm_x4(uint32_t& r0, uint32_t& r1, uint32_t& r2,
                                        uint32_t& r3, uint32_t addr) {
    asm volatile("ldmatrix.sync.aligned.m8n8.x4.shared.b16 {%0,%1,%2,%3}, [%4];"
                 : "=r"(r0), "=r"(r1), "=r"(r2), "=r"(r3) : "r"(addr));
}
__device__ __forceinline__ void ldsm_x4_t(uint32_t& r0, uint32_t& r1, uint32_t& r2,
                                          uint32_t& r3, uint32_t addr) {
    asm volatile("ldmatrix.sync.aligned.m8n8.x4.trans.shared.b16 {%0,%1,%2,%3}, [%4];"
                 : "=r"(r0), "=r"(r1), "=r"(r2), "=r"(r3) : "r"(addr));
}
__device__ __forceinline__ void cp_async16(uint32_t smem_addr, const void* gmem) {
    asm volatile("cp.async.cg.shared.global [%0], [%1], 16;\n"
                 :: "r"(smem_addr), "l"(gmem));
}
__device__ __forceinline__ void cp_commit() {
    asm volatile("cp.async.commit_group;\n" ::: "memory");
}
__device__ __forceinline__ void cp_wait1() {
    asm volatile("cp.async.wait_group 1;\n" ::: "memory");
}
__device__ __forceinline__ uint32_t smem_u32(const void* p) {
    uint32_t a;
    asm("{ .reg .u64 t; cvta.to.shared.u64 t, %1; cvt.u32.u64 %0, t; }"
        : "=r"(a) : "l"(p));
    return a;
}

// ---------------------------------------------------------------------------
// Fused weight convert: fp32 -> fp16 for all 5 weight matrices in one launch
// ---------------------------------------------------------------------------
constexpr size_t F4_QKV  = W_OUT / 4;
constexpr size_t F4_OUT  = W_GATE / 4;
constexpr size_t F4_GATE = W_UP / 4;
constexpr size_t F4_UP   = W_DOWN / 4;
constexpr size_t F4_ALL  = W_TOTAL / 4;

__global__ __launch_bounds__(256) void cvt_all_kernel(const float4* __restrict__ qkv_w,
                                                      const float4* __restrict__ out_w,
                                                      const float4* __restrict__ gate_w,
                                                      const float4* __restrict__ up_w,
                                                      const float4* __restrict__ down_w,
                                                      uint2* __restrict__ out) {
    size_t i = (size_t)blockIdx.x * 256 + threadIdx.x;
    const float4* src;
    size_t base;
    if (i < F4_QKV)       { src = qkv_w;  base = 0; }
    else if (i < F4_OUT)  { src = out_w;  base = F4_QKV; }
    else if (i < F4_GATE) { src = gate_w; base = F4_OUT; }
    else if (i < F4_UP)   { src = up_w;   base = F4_GATE; }
    else                  { src = down_w; base = F4_UP; }
    float4 v = src[i - base];
    __half2 h0 = __floats2half2_rn(v.x, v.y);
    __half2 h1 = __floats2half2_rn(v.z, v.w);
    out[i] = make_uint2(*(uint32_t*)&h0, *(uint32_t*)&h1);
}

// ---------------------------------------------------------------------------
// FP16 mma.sync GEMM, 2 CTAs/SM (unchanged from round 10, silu uses __expf)
// ---------------------------------------------------------------------------
constexpr int BM = 128, BN = 128, BK = 64;
constexpr int ROW_W = 36;
constexpr int A_WORDS = BM * ROW_W;
constexpr int B_WORDS = BN * ROW_W;
constexpr int STAGE_WORDS = A_WORDS + B_WORDS;
constexpr int GEMM_SMEM = 3 * STAGE_WORDS * 4;

__device__ __forceinline__ void issue_stage(uint32_t sA, uint32_t sB,
                                            const __half* __restrict__ Ab,
                                            const __half* __restrict__ Bb,
                                            int kt, int Kdim, int tid) {
    const size_t ko = (size_t)kt * BK;
#pragma unroll
    for (int i = 0; i < 4; i++) {
        int idx = tid + 256 * i;
        int row = idx >> 3, ch = idx & 7;
        cp_async16(sA + row * 144 + ch * 16, Ab + (size_t)row * Kdim + ko + ch * 8);
    }
#pragma unroll
    for (int i = 0; i < 4; i++) {
        int idx = tid + 256 * i;
        int row = idx >> 3, ch = idx & 7;
        cp_async16(sB + row * 144 + ch * 16, Bb + (size_t)row * Kdim + ko + ch * 8);
    }
}

template <int EPI, bool OUT16>
__global__ __launch_bounds__(256, 2) void gemm_h(const __half* __restrict__ A,
                                                 const __half* __restrict__ Bm,
                                                 void* __restrict__ Cv,
                                                 const void* __restrict__ AuxV,
                                                 int Ndim, int Kdim) {
    const uint32_t sbase = smem_u32(dynsmem);
    const int tid = threadIdx.x;
    const int wid = tid >> 5, lane = tid & 31;
    const int r = lane >> 2, c = lane & 3;
    const int m0 = blockIdx.y * BM;
    const int n0 = blockIdx.x * BN;
    const int wm = (wid & 1) * 64;
    const int wn = (wid >> 1) * 32;

    const __half* Ab = A + (size_t)m0 * Kdim;
    const __half* Bb = Bm + (size_t)n0 * Kdim;
    const int KT = Kdim / BK;

    const uint32_t a_off = ((wm + (lane & 15)) * ROW_W + (lane >> 4) * 4) * 4;
    const uint32_t b_off = ((wn + ((lane & 16) >> 1) + (lane & 7)) * ROW_W
                            + ((lane >> 3) & 1) * 4) * 4;

    float acc[4][4][4];
#pragma unroll
    for (int mb = 0; mb < 4; mb++)
#pragma unroll
        for (int nb = 0; nb < 4; nb++)
#pragma unroll
            for (int q = 0; q < 4; q++) acc[mb][nb][q] = 0.f;

#pragma unroll
    for (int s = 0; s < 2; s++) {
        uint32_t sA = sbase + s * STAGE_WORDS * 4;
        issue_stage(sA, sA + A_WORDS * 4, Ab, Bb, s, Kdim, tid);
        cp_commit();
    }

    int stage = 0;
    for (int kt = 0; kt < KT; kt++) {
        cp_wait1();
        __syncthreads();
        if (kt + 2 < KT) {
            int fs = stage + 2; if (fs >= 3) fs -= 3;
            uint32_t sA = sbase + fs * STAGE_WORDS * 4;
            issue_stage(sA, sA + A_WORDS * 4, Ab, Bb, kt + 2, Kdim, tid);
        }
        cp_commit();

        const uint32_t sA = sbase + stage * STAGE_WORDS * 4;
        const uint32_t sB = sA + A_WORDS * 4;
#pragma unroll
        for (int ks = 0; ks < 4; ks++) {
            uint32_t af[4][4], bf[4][2];
#pragma unroll
            for (int mb = 0; mb < 4; mb++)
                ldsm_x4(af[mb][0], af[mb][1], af[mb][2], af[mb][3],
                        sA + a_off + mb * (16 * ROW_W * 4) + ks * 32);
#pragma unroll
            for (int nb2 = 0; nb2 < 2; nb2++)
                ldsm_x4(bf[2 * nb2][0], bf[2 * nb2][1], bf[2 * nb2 + 1][0], bf[2 * nb2 + 1][1],
                        sB + b_off + nb2 * (16 * ROW_W * 4) + ks * 32);
#pragma unroll
            for (int mb = 0; mb < 4; mb++)
#pragma unroll
                for (int nb = 0; nb < 4; nb++)
                    mma_f16(acc[mb][nb], af[mb], bf[nb]);
        }
        if (++stage == 3) stage = 0;
    }

    // Epilogue
#pragma unroll
    for (int mb = 0; mb < 4; mb++) {
#pragma unroll
        for (int nb = 0; nb < 4; nb++) {
            int row0 = m0 + wm + mb * 16 + r;
            int col = n0 + wn + nb * 8 + c * 2;
#pragma unroll
            for (int half = 0; half < 2; half++) {
                size_t off = (size_t)(row0 + half * 8) * Ndim + col;
                float v0 = acc[mb][nb][half * 2 + 0];
                float v1 = acc[mb][nb][half * 2 + 1];
                if (EPI == 1 || EPI == 3) {
                    float2 a2 = *(const float2*)((const float*)AuxV + off);
                    if (EPI == 1) { v0 += a2.x; v1 += a2.y; }
                    else          { v0 *= a2.x; v1 *= a2.y; }
                }
                if (EPI == 4) {
                    __half2 ah = *(const __half2*)((const __half*)AuxV + off);
                    float2 a2 = __half22float2(ah);
                    v0 *= a2.x; v1 *= a2.y;
                }
                if (EPI == 2) {
                    v0 = v0 / (1.f + __expf(-v0));
                    v1 = v1 / (1.f + __expf(-v1));
                }
                if (OUT16) {
                    __half2 hv = __floats2half2_rn(v0, v1);
                    *(uint32_t*)((__half*)Cv + off) = *(uint32_t*)&hv;
                } else {
                    *(float2*)((float*)Cv + off) = make_float2(v0, v1);
                }
            }
        }
    }
}

// ---------------------------------------------------------------------------
// RMSNorm: one block per row, fp16 output
// ---------------------------------------------------------------------------
__global__ __launch_bounds__(256) void rmsnorm_kernel(const float* __restrict__ x,
                                                      const float* __restrict__ w,
                                                      __half* __restrict__ out) {
    int row = blockIdx.x;
    int t = threadIdx.x;
    const float4* xr = (const float4*)(x + (size_t)row * kD);
    float4 v0 = xr[t];
    float4 v1 = xr[t + 256];
    float s = v0.x * v0.x + v0.y * v0.y + v0.z * v0.z + v0.w * v0.w
            + v1.x * v1.x + v1.y * v1.y + v1.z * v1.z + v1.w * v1.w;
#pragma unroll
    for (int o = 16; o > 0; o >>= 1) s += __shfl_xor_sync(0xffffffffu, s, o);

    __shared__ float red[8];
    __shared__ float rtot;
    int wid = t >> 5, lane = t & 31;
    if (lane == 0) red[wid] = s;
    __syncthreads();
    if (t == 0) {
        float tot = 0.f;
#pragma unroll
        for (int i = 0; i < 8; i++) tot += red[i];
        rtot = rsqrtf(tot * (1.0f / kD) + 1e-6f);
    }
    __syncthreads();
    float r = rtot;

    const float4* wv = (const float4*)w;
    float4 w0 = wv[t], w1 = wv[t + 256];
    __half2 h0 = __floats2half2_rn(v0.x * r * w0.x, v0.y * r * w0.y);
    __half2 h1 = __floats2half2_rn(v0.z * r * w0.z, v0.w * r * w0.w);
    __half2 h2 = __floats2half2_rn(v1.x * r * w1.x, v1.y * r * w1.y);
    __half2 h3 = __floats2half2_rn(v1.z * r * w1.z, v1.w * r * w1.w);
    uint2* ov = (uint2*)(out + (size_t)row * kD);
    ov[t] = make_uint2(*(uint32_t*)&h0, *(uint32_t*)&h1);
    ov[t + 256] = make_uint2(*(uint32_t*)&h2, *(uint32_t*)&h3);
}

// ---------------------------------------------------------------------------
// FA2 tensor-core flash attention: register-resident softmax, no S/P SMEM.
// 128 threads / 4 warps; warp w owns q-rows w*16..w*16+15 across ALL kv/o cols.
// SMEM: Q/K/V tiles only. 3 CTAs/SM.
// ---------------------------------------------------------------------------
constexpr int AQ_W = 68;                       // words per row (272B)
constexpr int OFF_Q = 0;
constexpr int OFF_K = OFF_Q + 64 * AQ_W;
constexpr int OFF_V = OFF_K + 64 * AQ_W;
constexpr int ATTN_SMEM = (OFF_V + 64 * AQ_W) * 4;   // 52224 bytes

__global__ __launch_bounds__(128, 3) void attn_kernel(const __half* __restrict__ qkv,
                                                      __half* __restrict__ o_out) {
    uint32_t* smw = (uint32_t*)dynsmem;
    const uint32_t sb = smem_u32(smw);
    const int t = threadIdx.x, wid = t >> 5, lane = t & 31;
    const int q0 = blockIdx.x * 64, h = blockIdx.y, b = blockIdx.z;
    const float scale = 0.08838834764831845f;

    const __half* base = qkv + ((size_t)b * kL) * (3 * kD) + h * kHD;

    // Load Q tile [64][128]
#pragma unroll
    for (int i = 0; i < 8; i++) {
        int idx = t + 128 * i;
        int row = idx >> 4, ch = idx & 15;
        *(uint4*)(smw + OFF_Q + row * AQ_W + ch * 4) =
            *(const uint4*)(base + (size_t)(q0 + row) * (3 * kD) + ch * 8);
    }

    const int wr = wid * 16;
    const int l15 = lane & 15, l7 = lane & 7;
    const uint32_t qa = sb + (OFF_Q + (wr + l15) * AQ_W + (lane >> 4) * 4) * 4;
    const uint32_t ka = sb + (OFF_K + (((lane & 16) >> 1) + l7) * AQ_W
                              + ((lane >> 3) & 1) * 4) * 4;
    const uint32_t va = sb + (OFF_V + ((lane & 8) + l7) * AQ_W) * 4
                        + ((lane & 16) >> 1) * 2;

    float oacc[16][4];
#pragma unroll
    for (int nb = 0; nb < 16; nb++)
#pragma unroll
        for (int q = 0; q < 4; q++) oacc[nb][q] = 0.f;

    float m0 = -1e30f, m1 = -1e30f, l0 = 0.f, l1 = 0.f;
    const int rS = wr + (lane >> 2);
    const int c2 = (lane & 3) * 2;
    const int nkb = blockIdx.x + 1;

    for (int kb = 0; kb < nkb; kb++) {
        const int k0 = kb * 64;
        __syncthreads();  // prior tile's readers done (also covers Q store on kb=0)
#pragma unroll
        for (int i = 0; i < 8; i++) {
            int idx = t + 128 * i;
            int row = idx >> 4, ch = idx & 15;
            const __half* kr = base + (size_t)(k0 + row) * (3 * kD) + kD + ch * 8;
            *(uint4*)(smw + OFF_K + row * AQ_W + ch * 4) = *(const uint4*)(kr);
            *(uint4*)(smw + OFF_V + row * AQ_W + ch * 4) = *(const uint4*)(kr + kD);
        }
        __syncthreads();

        // S = Q @ K^T : 8 n8-blocks over kv 64, 8 k16-steps over HD 128
        float s[8][4];
#pragma unroll
        for (int j = 0; j < 8; j++)
#pragma unroll
            for (int q = 0; q < 4; q++) s[j][q] = 0.f;
#pragma unroll
        for (int ks = 0; ks < 8; ks++) {
            uint32_t af[4], bf[8][2];
            ldsm_x4(af[0], af[1], af[2], af[3], qa + ks * 32);
#pragma unroll
            for (int nq = 0; nq < 4; nq++)
                ldsm_x4(bf[2 * nq][0], bf[2 * nq][1], bf[2 * nq + 1][0], bf[2 * nq + 1][1],
                        ka + nq * (16 * AQ_W * 4) + ks * 32);
#pragma unroll
            for (int j = 0; j < 8; j++) mma_f16(s[j], af, bf[j]);
        }

        // Scale + causal mask + register softmax (quad shuffles)
        const bool diag = (kb == nkb - 1);
        float mx0 = -1e30f, mx1 = -1e30f;
#pragma unroll
        for (int j = 0; j < 8; j++) {
            int col = k0 + j * 8 + c2;
            s[j][0] *= scale; s[j][1] *= scale;
            s[j][2] *= scale; s[j][3] *= scale;
            if (diag) {
                if (col > q0 + rS) s[j][0] = -1e30f;
                if (col + 1 > q0 + rS) s[j][1] = -1e30f;
                if (col > q0 + rS + 8) s[j][2] = -1e30f;
                if (col + 1 > q0 + rS + 8) s[j][3] = -1e30f;
            }
            mx0 = fmaxf(mx0, fmaxf(s[j][0], s[j][1]));
            mx1 = fmaxf(mx1, fmaxf(s[j][2], s[j][3]));
        }
        mx0 = fmaxf(mx0, __shfl_xor_sync(0xffffffffu, mx0, 1));
        mx0 = fmaxf(mx0, __shfl_xor_sync(0xffffffffu, mx0, 2));
        mx1 = fmaxf(mx1, __shfl_xor_sync(0xffffffffu, mx1, 1));
        mx1 = fmaxf(mx1, __shfl_xor_sync(0xffffffffu, mx1, 2));
        float mn0 = fmaxf(m0, mx0), mn1 = fmaxf(m1, mx1);
        float corr0 = __expf(m0 - mn0), corr1 = __expf(m1 - mn1);

        float sum0 = 0.f, sum1 = 0.f;
        uint32_t pl[8], pu[8];
#pragma unroll
        for (int j = 0; j < 8; j++) {
            float p0 = __expf(s[j][0] - mn0);
            float p1 = __expf(s[j][1] - mn0);
            float p2 = __expf(s[j][2] - mn1);
            float p3 = __expf(s[j][3] - mn1);
            sum0 += p0 + p1; sum1 += p2 + p3;
            __half2 hl = __floats2half2_rn(p0, p1);
            __half2 hu = __floats2half2_rn(p2, p3);
            pl[j] = *(uint32_t*)&hl; pu[j] = *(uint32_t*)&hu;
        }
        sum0 += __shfl_xor_sync(0xffffffffu, sum0, 1);
        sum0 += __shfl_xor_sync(0xffffffffu, sum0, 2);
        sum1 += __shfl_xor_sync(0xffffffffu, sum1, 1);
        sum1 += __shfl_xor_sync(0xffffffffu, sum1, 2);
        l0 = l0 * corr0 + sum0; l1 = l1 * corr1 + sum1;
        m0 = mn0; m1 = mn1;

        // Rescale O
#pragma unroll
        for (int nb = 0; nb < 16; nb++) {
            oacc[nb][0] *= corr0; oacc[nb][1] *= corr0;
            oacc[nb][2] *= corr1; oacc[nb][3] *= corr1;
        }

        // O += P @ V : P from registers (accumulator->A-fragment repack)
#pragma unroll
        for (int kc = 0; kc < 4; kc++) {
            uint32_t af2[4] = { pl[2 * kc], pu[2 * kc], pl[2 * kc + 1], pu[2 * kc + 1] };
            uint32_t bv[16][2];
#pragma unroll
            for (int nb2 = 0; nb2 < 8; nb2++)
                ldsm_x4_t(bv[2 * nb2][0], bv[2 * nb2][1],
                          bv[2 * nb2 + 1][0], bv[2 * nb2 + 1][1],
                          va + kc * (16 * AQ_W * 4) + nb2 * 32);
#pragma unroll
            for (int nb = 0; nb < 16; nb++) mma_f16(oacc[nb], af2, bv[nb]);
        }
    }

    // Epilogue
    float inv0 = 1.f / l0, inv1 = 1.f / l1;
#pragma unroll
    for (int nb = 0; nb < 16; nb++) {
        int col = nb * 8 + c2;
        __half* d0 = o_out + ((size_t)(b * kL + q0 + rS)) * kD + h * kHD + col;
        __half* d1 = d0 + (size_t)8 * kD;
        __half2 h01 = __floats2half2_rn(oacc[nb][0] * inv0, oacc[nb][1] * inv0);
        __half2 h23 = __floats2half2_rn(oacc[nb][2] * inv1, oacc[nb][3] * inv1);
        *(uint32_t*)d0 = *(uint32_t*)&h01;
        *(uint32_t*)d1 = *(uint32_t*)&h23;
    }
}

// ---------------------------------------------------------------------------
// Launch
// ---------------------------------------------------------------------------
extern "C" void kernel_launch(void* const* d_in, const int* in_sizes, int n_in,
                              void* d_out, int out_size) {
    (void)in_sizes; (void)n_in; (void)out_size;
    const float* x       = (const float*)d_in[0];
    const float* norm1_w = (const float*)d_in[2];
    const float* qkv_w   = (const float*)d_in[3];
    const float* out_w   = (const float*)d_in[4];
    const float* norm2_w = (const float*)d_in[5];
    const float* gate_w  = (const float*)d_in[6];
    const float* up_w    = (const float*)d_in[7];
    const float* down_w  = (const float*)d_in[8];
    float* out = (float*)d_out;

    float* x2;
    __half *qkv16, *h16, *attn16, *gate16, *act16, *w16;
    cudaGetSymbolAddress((void**)&x2, g_x2);
    cudaGetSymbolAddress((void**)&qkv16, g_qkv16);
    cudaGetSymbolAddress((void**)&h16, g_h16);
    cudaGetSymbolAddress((void**)&attn16, g_attn16);
    cudaGetSymbolAddress((void**)&gate16, g_gate16);
    cudaGetSymbolAddress((void**)&act16, g_act16);
    cudaGetSymbolAddress((void**)&w16, g_w16);

    cudaFuncSetAttribute((const void*)attn_kernel,
                         cudaFuncAttributeMaxDynamicSharedMemorySize, ATTN_SMEM);
    cudaFuncSetAttribute((const void*)gemm_h<0, true>,
                         cudaFuncAttributeMaxDynamicSharedMemorySize, GEMM_SMEM);
    cudaFuncSetAttribute((const void*)gemm_h<1, false>,
                         cudaFuncAttributeMaxDynamicSharedMemorySize, GEMM_SMEM);
    cudaFuncSetAttribute((const void*)gemm_h<2, true>,
                         cudaFuncAttributeMaxDynamicSharedMemorySize, GEMM_SMEM);
    cudaFuncSetAttribute((const void*)gemm_h<4, true>,
                         cudaFuncAttributeMaxDynamicSharedMemorySize, GEMM_SMEM);

    // 0) Convert all weights to fp16 (one launch)
    cvt_all_kernel<<<(int)(F4_ALL / 256), 256>>>(
        (const float4*)qkv_w, (const float4*)out_w, (const float4*)gate_w,
        (const float4*)up_w, (const float4*)down_w, (uint2*)w16);

    // 1) h16 = rmsnorm(x, norm1_w)
    rmsnorm_kernel<<<kM, 256>>>(x, norm1_w, h16);
    // 2) qkv16 = h16 @ qkv_w16^T
    gemm_h<0, true><<<dim3(3 * kD / BN, kM / BM), 256, GEMM_SMEM>>>(
        h16, w16 + W_QKV, qkv16, nullptr, 3 * kD, kD);
    // 3) FA2 tensor-core attention
    attn_kernel<<<dim3(kL / 64, kH, kB), 128, ATTN_SMEM>>>(qkv16, attn16);
    // 4) x2 = attn16 @ out_w16^T + x
    gemm_h<1, false><<<dim3(kD / BN, kM / BM), 256, GEMM_SMEM>>>(
        attn16, w16 + W_OUT, x2, x, kD, kD);
    // 5) h16 = rmsnorm(x2, norm2_w)
    rmsnorm_kernel<<<kM, 256>>>(x2, norm2_w, h16);
    // 6) gate16 = silu(h16 @ gate_w16^T)
    gemm_h<2, true><<<dim3(kFF / BN, kM / BM), 256, GEMM_SMEM>>>(
        h16, w16 + W_GATE, gate16, nullptr, kFF, kD);
    // 7) act16 = (h16 @ up_w16^T) * gate16
    gemm_h<4, true><<<dim3(kFF / BN, kM / BM), 256, GEMM_SMEM>>>(
        h16, w16 + W_UP, act16, gate16, kFF, kD);
    // 8) out = act16 @ down_w16^T + x2
    gemm_h<1, false><<<dim3(kD / BN, kM / BM), 256, GEMM_SMEM>>>(
        act16, w16 + W_DOWN, out, x2, kD, kFF);
}

// round 12
// speedup vs baseline: 8.4756x; 1.0325x over previous
#include <cuda_runtime.h>
#include <cuda_fp16.h>
#include <math.h>
#include <stdint.h>

// Problem constants
constexpr int kB  = 2;
constexpr int kL  = 2048;
constexpr int kD  = 2048;
constexpr int kH  = 16;
constexpr int kHD = 128;
constexpr int kFF = 8192;
constexpr int kM  = kB * kL;  // 4096 rows

// ---------------------------------------------------------------------------
// Scratch buffers (device globals — no allocation allowed)
// ---------------------------------------------------------------------------
__device__ float  g_x2[(size_t)kM * kD];
__device__ __half g_qkv16[(size_t)kM * 3 * kD];
__device__ __half g_h16[(size_t)kM * kD];
__device__ __half g_attn16[(size_t)kM * kD];
__device__ __half g_act16[(size_t)kM * kFF];
// fp16 weights: [qkv][out][glu (gate/up row-interleaved)][down]
constexpr size_t W_QKV  = 0;
constexpr size_t W_OUT  = (size_t)3 * kD * kD;
constexpr size_t W_GLU  = W_OUT + (size_t)kD * kD;            // 2*FF rows interleaved
constexpr size_t W_DOWN = W_GLU + (size_t)2 * kFF * kD;
constexpr size_t W_TOTAL = W_DOWN + (size_t)kD * kFF;
__device__ __half g_w16[W_TOTAL];

extern __shared__ char dynsmem[];

// ---------------------------------------------------------------------------
// PTX helpers
// ---------------------------------------------------------------------------
__device__ __forceinline__ void mma_f16(float* c, const uint32_t* a, const uint32_t* b) {
    asm volatile(
        "mma.sync.aligned.m16n8k16.row.col.f32.f16.f16.f32 "
        "{%0,%1,%2,%3}, {%4,%5,%6,%7}, {%8,%9}, {%0,%1,%2,%3};"
        : "+f"(c[0]), "+f"(c[1]), "+f"(c[2]), "+f"(c[3])
        : "r"(a[0]), "r"(a[1]), "r"(a[2]), "r"(a[3]), "r"(b[0]), "r"(b[1]));
}
__device__ __forceinline__ void ldsm_x4(uint32_t& r0, uint32_t& r1, uint32_t& r2,
                                        uint32_t& r3, uint32_t addr) {
    asm volatile("ldmatrix.sync.aligned.m8n8.x4.shared.b16 {%0,%1,%2,%3}, [%4];"
                 : "=r"(r0), "=r"(r1), "=r"(r2), "=r"(r3) : "r"(addr));
}
__device__ __forceinline__ void ldsm_x4_t(uint32_t& r0, uint32_t& r1, uint32_t& r2,
                                          uint32_t& r3, uint32_t addr) {
    asm volatile("ldmatrix.sync.aligned.m8n8.x4.trans.shared.b16 {%0,%1,%2,%3}, [%4];"
                 : "=r"(r0), "=r"(r1), "=r"(r2), "=r"(r3) : "r"(addr));
}
__device__ __forceinline__ void cp_async16(uint32_t smem_addr, const void* gmem) {
    asm volatile("cp.async.cg.shared.global [%0], [%1], 16;\n"
                 :: "r"(smem_addr), "l"(gmem));
}
__device__ __forceinline__ void cp_commit() {
    asm volatile("cp.async.commit_group;\n" ::: "memory");
}
__device__ __forceinline__ void cp_wait1() {
    asm volatile("cp.async.wait_group 1;\n" ::: "memory");
}
__device__ __forceinline__ uint32_t smem_u32(const void* p) {
    uint32_t a;
    asm("{ .reg .u64 t; cvta.to.shared.u64 t, %1; cvt.u32.u64 %0, t; }"
        : "=r"(a) : "l"(p));
    return a;
}

// ---------------------------------------------------------------------------
// Fused weight convert. gate/up are interleaved row-wise into the GLU region:
// GLU row 2j = gate row j, GLU row 2j+1 = up row j.
// ---------------------------------------------------------------------------
constexpr size_t F4R = kD / 4;                 // 512 float4 per row
constexpr size_t F4_QKV  = W_OUT / 4;
constexpr size_t F4_OUT  = W_GLU / 4;
constexpr size_t F4_GATE = F4_OUT + (size_t)kFF * F4R;   // virtual gate segment end
constexpr size_t F4_UP   = F4_GATE + (size_t)kFF * F4R;  // virtual up segment end
constexpr size_t F4_ALL  = W_TOTAL / 4;

__global__ __launch_bounds__(256) void cvt_all_kernel(const float4* __restrict__ qkv_w,
                                                      const float4* __restrict__ out_w,
                                                      const float4* __restrict__ gate_w,
                                                      const float4* __restrict__ up_w,
                                                      const float4* __restrict__ down_w,
                                                      uint2* __restrict__ out) {
    size_t i = (size_t)blockIdx.x * 256 + threadIdx.x;
    const float4* src;
    size_t j, dst;
    if (i < F4_QKV) {
        src = qkv_w; j = i; dst = i;
    } else if (i < F4_OUT) {
        src = out_w; j = i - F4_QKV; dst = i;
    } else if (i < F4_GATE) {
        src = gate_w; j = i - F4_OUT;
        size_t row = j / F4R, col = j % F4R;
        dst = F4_OUT + (2 * row) * F4R + col;
    } else if (i < F4_UP) {
        src = up_w; j = i - F4_GATE;
        size_t row = j / F4R, col = j % F4R;
        dst = F4_OUT + (2 * row + 1) * F4R + col;
    } else {
        src = down_w; j = i - F4_UP; dst = i;
    }
    float4 v = src[j];
    __half2 h0 = __floats2half2_rn(v.x, v.y);
    __half2 h1 = __floats2half2_rn(v.z, v.w);
    out[dst] = make_uint2(*(uint32_t*)&h0, *(uint32_t*)&h1);
}

// ---------------------------------------------------------------------------
// FP16 mma.sync GEMM, 2 CTAs/SM: C[M,N] = A[M,K] @ B[N,K]^T.
// Block 128x128, BK=64, 8 warps each 64x32, 3-stage cp.async pipeline.
// EPI: 0 none, 1 +Aux(fp32), 5 GLU (even col=gate, odd col=up ->
//      silu(gate)*up written as __half at col/2, stride Ndim/2).
// OUT16: __half out else float.
// ---------------------------------------------------------------------------
constexpr int BM = 128, BN = 128, BK = 64;
constexpr int ROW_W = 36;
constexpr int A_WORDS = BM * ROW_W;
constexpr int B_WORDS = BN * ROW_W;
constexpr int STAGE_WORDS = A_WORDS + B_WORDS;
constexpr int GEMM_SMEM = 3 * STAGE_WORDS * 4;

__device__ __forceinline__ void issue_stage(uint32_t sA, uint32_t sB,
                                            const __half* __restrict__ Ab,
                                            const __half* __restrict__ Bb,
                                            int kt, int Kdim, int tid) {
    const size_t ko = (size_t)kt * BK;
#pragma unroll
    for (int i = 0; i < 4; i++) {
        int idx = tid + 256 * i;
        int row = idx >> 3, ch = idx & 7;
        cp_async16(sA + row * 144 + ch * 16, Ab + (size_t)row * Kdim + ko + ch * 8);
    }
#pragma unroll
    for (int i = 0; i < 4; i++) {
        int idx = tid + 256 * i;
        int row = idx >> 3, ch = idx & 7;
        cp_async16(sB + row * 144 + ch * 16, Bb + (size_t)row * Kdim + ko + ch * 8);
    }
}

template <int EPI, bool OUT16>
__global__ __launch_bounds__(256, 2) void gemm_h(const __half* __restrict__ A,
                                                 const __half* __restrict__ Bm,
                                                 void* __restrict__ Cv,
                                                 const void* __restrict__ AuxV,
                                                 int Ndim, int Kdim) {
    const uint32_t sbase = smem_u32(dynsmem);
    const int tid = threadIdx.x;
    const int wid = tid >> 5, lane = tid & 31;
    const int r = lane >> 2, c = lane & 3;
    const int m0 = blockIdx.y * BM;
    const int n0 = blockIdx.x * BN;
    const int wm = (wid & 1) * 64;
    const int wn = (wid >> 1) * 32;

    const __half* Ab = A + (size_t)m0 * Kdim;
    const __half* Bb = Bm + (size_t)n0 * Kdim;
    const int KT = Kdim / BK;

    const uint32_t a_off = ((wm + (lane & 15)) * ROW_W + (lane >> 4) * 4) * 4;
    const uint32_t b_off = ((wn + ((lane & 16) >> 1) + (lane & 7)) * ROW_W
                            + ((lane >> 3) & 1) * 4) * 4;

    float acc[4][4][4];
#pragma unroll
    for (int mb = 0; mb < 4; mb++)
#pragma unroll
        for (int nb = 0; nb < 4; nb++)
#pragma unroll
            for (int q = 0; q < 4; q++) acc[mb][nb][q] = 0.f;

#pragma unroll
    for (int s = 0; s < 2; s++) {
        uint32_t sA = sbase + s * STAGE_WORDS * 4;
        issue_stage(sA, sA + A_WORDS * 4, Ab, Bb, s, Kdim, tid);
        cp_commit();
    }

    int stage = 0;
    for (int kt = 0; kt < KT; kt++) {
        cp_wait1();
        __syncthreads();
        if (kt + 2 < KT) {
            int fs = stage + 2; if (fs >= 3) fs -= 3;
            uint32_t sA = sbase + fs * STAGE_WORDS * 4;
            issue_stage(sA, sA + A_WORDS * 4, Ab, Bb, kt + 2, Kdim, tid);
        }
        cp_commit();

        const uint32_t sA = sbase + stage * STAGE_WORDS * 4;
        const uint32_t sB = sA + A_WORDS * 4;
#pragma unroll
        for (int ks = 0; ks < 4; ks++) {
            uint32_t af[4][4], bf[4][2];
#pragma unroll
            for (int mb = 0; mb < 4; mb++)
                ldsm_x4(af[mb][0], af[mb][1], af[mb][2], af[mb][3],
                        sA + a_off + mb * (16 * ROW_W * 4) + ks * 32);
#pragma unroll
            for (int nb2 = 0; nb2 < 2; nb2++)
                ldsm_x4(bf[2 * nb2][0], bf[2 * nb2][1], bf[2 * nb2 + 1][0], bf[2 * nb2 + 1][1],
                        sB + b_off + nb2 * (16 * ROW_W * 4) + ks * 32);
#pragma unroll
            for (int mb = 0; mb < 4; mb++)
#pragma unroll
                for (int nb = 0; nb < 4; nb++)
                    mma_f16(acc[mb][nb], af[mb], bf[nb]);
        }
        if (++stage == 3) stage = 0;
    }

    // Epilogue
#pragma unroll
    for (int mb = 0; mb < 4; mb++) {
#pragma unroll
        for (int nb = 0; nb < 4; nb++) {
            int row0 = m0 + wm + mb * 16 + r;
            int col = n0 + wn + nb * 8 + c * 2;
#pragma unroll
            for (int half = 0; half < 2; half++) {
                int row = row0 + half * 8;
                float v0 = acc[mb][nb][half * 2 + 0];
                float v1 = acc[mb][nb][half * 2 + 1];
                if (EPI == 5) {
                    // GLU: v0 = gate (even col), v1 = up (odd col)
                    float g = v0 / (1.f + __expf(-v0));
                    __half* dst = (__half*)Cv + (size_t)row * (Ndim / 2) + (col >> 1);
                    *dst = __float2half(g * v1);
                    continue;
                }
                size_t off = (size_t)row * Ndim + col;
                if (EPI == 1) {
                    float2 a2 = *(const float2*)((const float*)AuxV + off);
                    v0 += a2.x; v1 += a2.y;
                }
                if (OUT16) {
                    __half2 hv = __floats2half2_rn(v0, v1);
                    *(uint32_t*)((__half*)Cv + off) = *(uint32_t*)&hv;
                } else {
                    *(float2*)((float*)Cv + off) = make_float2(v0, v1);
                }
            }
        }
    }
}

// ---------------------------------------------------------------------------
// RMSNorm: one block per row, fp16 output
// ---------------------------------------------------------------------------
__global__ __launch_bounds__(256) void rmsnorm_kernel(const float* __restrict__ x,
                                                      const float* __restrict__ w,
                                                      __half* __restrict__ out) {
    int row = blockIdx.x;
    int t = threadIdx.x;
    const float4* xr = (const float4*)(x + (size_t)row * kD);
    float4 v0 = xr[t];
    float4 v1 = xr[t + 256];
    float s = v0.x * v0.x + v0.y * v0.y + v0.z * v0.z + v0.w * v0.w
            + v1.x * v1.x + v1.y * v1.y + v1.z * v1.z + v1.w * v1.w;
#pragma unroll
    for (int o = 16; o > 0; o >>= 1) s += __shfl_xor_sync(0xffffffffu, s, o);

    __shared__ float red[8];
    __shared__ float rtot;
    int wid = t >> 5, lane = t & 31;
    if (lane == 0) red[wid] = s;
    __syncthreads();
    if (t == 0) {
        float tot = 0.f;
#pragma unroll
        for (int i = 0; i < 8; i++) tot += red[i];
        rtot = rsqrtf(tot * (1.0f / kD) + 1e-6f);
    }
    __syncthreads();
    float r = rtot;

    const float4* wv = (const float4*)w;
    float4 w0 = wv[t], w1 = wv[t + 256];
    __half2 h0 = __floats2half2_rn(v0.x * r * w0.x, v0.y * r * w0.y);
    __half2 h1 = __floats2half2_rn(v0.z * r * w0.z, v0.w * r * w0.w);
    __half2 h2 = __floats2half2_rn(v1.x * r * w1.x, v1.y * r * w1.y);
    __half2 h3 = __floats2half2_rn(v1.z * r * w1.z, v1.w * r * w1.w);
    uint2* ov = (uint2*)(out + (size_t)row * kD);
    ov[t] = make_uint2(*(uint32_t*)&h0, *(uint32_t*)&h1);
    ov[t + 256] = make_uint2(*(uint32_t*)&h2, *(uint32_t*)&h3);
}

// ---------------------------------------------------------------------------
// FA2 tensor-core flash attention (unchanged from round 11).
// ---------------------------------------------------------------------------
constexpr int AQ_W = 68;
constexpr int OFF_Q = 0;
constexpr int OFF_K = OFF_Q + 64 * AQ_W;
constexpr int OFF_V = OFF_K + 64 * AQ_W;
constexpr int ATTN_SMEM = (OFF_V + 64 * AQ_W) * 4;   // 52224 bytes

__global__ __launch_bounds__(128, 3) void attn_kernel(const __half* __restrict__ qkv,
                                                      __half* __restrict__ o_out) {
    uint32_t* smw = (uint32_t*)dynsmem;
    const uint32_t sb = smem_u32(smw);
    const int t = threadIdx.x, wid = t >> 5, lane = t & 31;
    const int q0 = blockIdx.x * 64, h = blockIdx.y, b = blockIdx.z;
    const float scale = 0.08838834764831845f;

    const __half* base = qkv + ((size_t)b * kL) * (3 * kD) + h * kHD;

#pragma unroll
    for (int i = 0; i < 8; i++) {
        int idx = t + 128 * i;
        int row = idx >> 4, ch = idx & 15;
        *(uint4*)(smw + OFF_Q + row * AQ_W + ch * 4) =
            *(const uint4*)(base + (size_t)(q0 + row) * (3 * kD) + ch * 8);
    }

    const int wr = wid * 16;
    const int l15 = lane & 15, l7 = lane & 7;
    const uint32_t qa = sb + (OFF_Q + (wr + l15) * AQ_W + (lane >> 4) * 4) * 4;
    const uint32_t ka = sb + (OFF_K + (((lane & 16) >> 1) + l7) * AQ_W
                              + ((lane >> 3) & 1) * 4) * 4;
    const uint32_t va = sb + (OFF_V + ((lane & 8) + l7) * AQ_W) * 4
                        + ((lane & 16) >> 1) * 2;

    float oacc[16][4];
#pragma unroll
    for (int nb = 0; nb < 16; nb++)
#pragma unroll
        for (int q = 0; q < 4; q++) oacc[nb][q] = 0.f;

    float m0 = -1e30f, m1 = -1e30f, l0 = 0.f, l1 = 0.f;
    const int rS = wr + (lane >> 2);
    const int c2 = (lane & 3) * 2;
    const int nkb = blockIdx.x + 1;

    for (int kb = 0; kb < nkb; kb++) {
        const int k0 = kb * 64;
        __syncthreads();
#pragma unroll
        for (int i = 0; i < 8; i++) {
            int idx = t + 128 * i;
            int row = idx >> 4, ch = idx & 15;
            const __half* kr = base + (size_t)(k0 + row) * (3 * kD) + kD + ch * 8;
            *(uint4*)(smw + OFF_K + row * AQ_W + ch * 4) = *(const uint4*)(kr);
            *(uint4*)(smw + OFF_V + row * AQ_W + ch * 4) = *(const uint4*)(kr + kD);
        }
        __syncthreads();

        float s[8][4];
#pragma unroll
        for (int j = 0; j < 8; j++)
#pragma unroll
            for (int q = 0; q < 4; q++) s[j][q] = 0.f;
#pragma unroll
        for (int ks = 0; ks < 8; ks++) {
            uint32_t af[4], bf[8][2];
            ldsm_x4(af[0], af[1], af[2], af[3], qa + ks * 32);
#pragma unroll
            for (int nq = 0; nq < 4; nq++)
                ldsm_x4(bf[2 * nq][0], bf[2 * nq][1], bf[2 * nq + 1][0], bf[2 * nq + 1][1],
                        ka + nq * (16 * AQ_W * 4) + ks * 32);
#pragma unroll
            for (int j = 0; j < 8; j++) mma_f16(s[j], af, bf[j]);
        }

        const bool diag = (kb == nkb - 1);
        float mx0 = -1e30f, mx1 = -1e30f;
#pragma unroll
        for (int j = 0; j < 8; j++) {
            int col = k0 + j * 8 + c2;
            s[j][0] *= scale; s[j][1] *= scale;
            s[j][2] *= scale; s[j][3] *= scale;
            if (diag) {
                if (col > q0 + rS) s[j][0] = -1e30f;
                if (col + 1 > q0 + rS) s[j][1] = -1e30f;
                if (col > q0 + rS + 8) s[j][2] = -1e30f;
                if (col + 1 > q0 + rS + 8) s[j][3] = -1e30f;
            }
            mx0 = fmaxf(mx0, fmaxf(s[j][0], s[j][1]));
            mx1 = fmaxf(mx1, fmaxf(s[j][2], s[j][3]));
        }
        mx0 = fmaxf(mx0, __shfl_xor_sync(0xffffffffu, mx0, 1));
        mx0 = fmaxf(mx0, __shfl_xor_sync(0xffffffffu, mx0, 2));
        mx1 = fmaxf(mx1, __shfl_xor_sync(0xffffffffu, mx1, 1));
        mx1 = fmaxf(mx1, __shfl_xor_sync(0xffffffffu, mx1, 2));
        float mn0 = fmaxf(m0, mx0), mn1 = fmaxf(m1, mx1);
        float corr0 = __expf(m0 - mn0), corr1 = __expf(m1 - mn1);

        float sum0 = 0.f, sum1 = 0.f;
        uint32_t pl[8], pu[8];
#pragma unroll
        for (int j = 0; j < 8; j++) {
            float p0 = __expf(s[j][0] - mn0);
            float p1 = __expf(s[j][1] - mn0);
            float p2 = __expf(s[j][2] - mn1);
            float p3 = __expf(s[j][3] - mn1);
            sum0 += p0 + p1; sum1 += p2 + p3;
            __half2 hl = __floats2half2_rn(p0, p1);
            __half2 hu = __floats2half2_rn(p2, p3);
            pl[j] = *(uint32_t*)&hl; pu[j] = *(uint32_t*)&hu;
        }
        sum0 += __shfl_xor_sync(0xffffffffu, sum0, 1);
        sum0 += __shfl_xor_sync(0xffffffffu, sum0, 2);
        sum1 += __shfl_xor_sync(0xffffffffu, sum1, 1);
        sum1 += __shfl_xor_sync(0xffffffffu, sum1, 2);
        l0 = l0 * corr0 + sum0; l1 = l1 * corr1 + sum1;
        m0 = mn0; m1 = mn1;

#pragma unroll
        for (int nb = 0; nb < 16; nb++) {
            oacc[nb][0] *= corr0; oacc[nb][1] *= corr0;
            oacc[nb][2] *= corr1; oacc[nb][3] *= corr1;
        }

#pragma unroll
        for (int kc = 0; kc < 4; kc++) {
            uint32_t af2[4] = { pl[2 * kc], pu[2 * kc], pl[2 * kc + 1], pu[2 * kc + 1] };
            uint32_t bv[16][2];
#pragma unroll
            for (int nb2 = 0; nb2 < 8; nb2++)
                ldsm_x4_t(bv[2 * nb2][0], bv[2 * nb2][1],
                          bv[2 * nb2 + 1][0], bv[2 * nb2 + 1][1],
                          va + kc * (16 * AQ_W * 4) + nb2 * 32);
#pragma unroll
            for (int nb = 0; nb < 16; nb++) mma_f16(oacc[nb], af2, bv[nb]);
        }
    }

    float inv0 = 1.f / l0, inv1 = 1.f / l1;
#pragma unroll
    for (int nb = 0; nb < 16; nb++) {
        int col = nb * 8 + c2;
        __half* d0 = o_out + ((size_t)(b * kL + q0 + rS)) * kD + h * kHD + col;
        __half* d1 = d0 + (size_t)8 * kD;
        __half2 h01 = __floats2half2_rn(oacc[nb][0] * inv0, oacc[nb][1] * inv0);
        __half2 h23 = __floats2half2_rn(oacc[nb][2] * inv1, oacc[nb][3] * inv1);
        *(uint32_t*)d0 = *(uint32_t*)&h01;
        *(uint32_t*)d1 = *(uint32_t*)&h23;
    }
}

// ---------------------------------------------------------------------------
// Launch
// ---------------------------------------------------------------------------
extern "C" void kernel_launch(void* const* d_in, const int* in_sizes, int n_in,
                              void* d_out, int out_size) {
    (void)in_sizes; (void)n_in; (void)out_size;
    const float* x       = (const float*)d_in[0];
    const float* norm1_w = (const float*)d_in[2];
    const float* qkv_w   = (const float*)d_in[3];
    const float* out_w   = (const float*)d_in[4];
    const float* norm2_w = (const float*)d_in[5];
    const float* gate_w  = (const float*)d_in[6];
    const float* up_w    = (const float*)d_in[7];
    const float* down_w  = (const float*)d_in[8];
    float* out = (float*)d_out;

    float* x2;
    __half *qkv16, *h16, *attn16, *act16, *w16;
    cudaGetSymbolAddress((void**)&x2, g_x2);
    cudaGetSymbolAddress((void**)&qkv16, g_qkv16);
    cudaGetSymbolAddress((void**)&h16, g_h16);
    cudaGetSymbolAddress((void**)&attn16, g_attn16);
    cudaGetSymbolAddress((void**)&act16, g_act16);
    cudaGetSymbolAddress((void**)&w16, g_w16);

    cudaFuncSetAttribute((const void*)attn_kernel,
                         cudaFuncAttributeMaxDynamicSharedMemorySize, ATTN_SMEM);
    cudaFuncSetAttribute((const void*)gemm_h<0, true>,
                         cudaFuncAttributeMaxDynamicSharedMemorySize, GEMM_SMEM);
    cudaFuncSetAttribute((const void*)gemm_h<1, false>,
                         cudaFuncAttributeMaxDynamicSharedMemorySize, GEMM_SMEM);
    cudaFuncSetAttribute((const void*)gemm_h<5, true>,
                         cudaFuncAttributeMaxDynamicSharedMemorySize, GEMM_SMEM);

    // 0) Convert all weights to fp16 (gate/up interleaved into GLU region)
    cvt_all_kernel<<<(int)(F4_ALL / 256), 256>>>(
        (const float4*)qkv_w, (const float4*)out_w, (const float4*)gate_w,
        (const float4*)up_w, (const float4*)down_w, (uint2*)w16);

    // 1) h16 = rmsnorm(x, norm1_w)
    rmsnorm_kernel<<<kM, 256>>>(x, norm1_w, h16);
    // 2) qkv16 = h16 @ qkv_w16^T
    gemm_h<0, true><<<dim3(3 * kD / BN, kM / BM), 256, GEMM_SMEM>>>(
        h16, w16 + W_QKV, qkv16, nullptr, 3 * kD, kD);
    // 3) FA2 tensor-core attention
    attn_kernel<<<dim3(kL / 64, kH, kB), 128, ATTN_SMEM>>>(qkv16, attn16);
    // 4) x2 = attn16 @ out_w16^T + x
    gemm_h<1, false><<<dim3(kD / BN, kM / BM), 256, GEMM_SMEM>>>(
        attn16, w16 + W_OUT, x2, x, kD, kD);
    // 5) h16 = rmsnorm(x2, norm2_w)
    rmsnorm_kernel<<<kM, 256>>>(x2, norm2_w, h16);
    // 6) act16 = silu(h16 @ gate^T) * (h16 @ up^T)  — single fused GLU GEMM
    gemm_h<5, true><<<dim3(2 * kFF / BN, kM / BM), 256, GEMM_SMEM>>>(
        h16, w16 + W_GLU, act16, nullptr, 2 * kFF, kD);
    // 7) out = act16 @ down_w16^T + x2
    gemm_h<1, false><<<dim3(kD / BN, kM / BM), 256, GEMM_SMEM>>>(
        act16, w16 + W_DOWN, out, x2, kD, kFF);
}